// round 2
// baseline (speedup 1.0000x reference)
#include <cuda_runtime.h>
#include <cuda_bf16.h>
#include <cstdint>

// Problem constants
#define BB    8
#define NN    2048
#define DIMM  512
#define HH    8
#define DD    64
#define INNERR 512
#define NSCALE 0.044194173824159216f   // 512^-0.5

// Scratch (allocation-free rule: __device__ globals).
// NOTE: referenced ONLY from device code — host code must never take their address.
__device__ float g_q[(size_t)BB * HH * NN * DD];   // [b,h,n,d]
__device__ float g_k[(size_t)BB * HH * NN * DD];   // [b,h,n,d]
__device__ float g_v[(size_t)BB * HH * NN * DD];   // [b,h,n,d]
__device__ float g_o[(size_t)BB * NN * INNERR];    // [b,n,(h d)]

// ---------------------------------------------------------------------------
// GEMM: C[16384,512] = A[16384,512] @ W[512,512]
// BM=BN=128, BK=8, 256 threads, 8x8 micro-tile per thread.
// DST 0/1/2 -> A from arg, write head-split into g_q/g_k/g_v.
// DST 3     -> A = g_o (device global), write flat + bias to Cout.
// ---------------------------------------------------------------------------
#define AS_LD 132

template<int DST>
__global__ __launch_bounds__(256)
void gemm128(const float* __restrict__ Ain, const float* __restrict__ W,
             const float* __restrict__ bias, float* __restrict__ Cout)
{
    // Resolve A in device code (legal place to reference __device__ globals)
    const float* __restrict__ A = (DST == 3) ? (const float*)g_o : Ain;

    __shared__ float As[8 * AS_LD];   // transposed: As[k][m]
    __shared__ float Bs[8 * 128];     // Bs[k][n]

    const int tid = threadIdx.x;
    const int tx  = tid & 15;         // 16 col-groups
    const int ty  = tid >> 4;         // 16 row-groups
    const int rowBase = blockIdx.y * 128;
    const int colBase = blockIdx.x * 128;

    const int arow = tid >> 1;        // 0..127
    const int akv  = (tid & 1) * 4;   // 0 or 4
    const int brow = tid >> 5;        // 0..7
    const int bcol = (tid & 31) * 4;  // 0..124

    float acc[8][8];
#pragma unroll
    for (int i = 0; i < 8; ++i)
#pragma unroll
        for (int j = 0; j < 8; ++j) acc[i][j] = 0.f;

    for (int kt = 0; kt < 64; ++kt) {
        const int k0 = kt * 8;
        float4 av = *(const float4*)&A[(size_t)(rowBase + arow) * 512 + k0 + akv];
        float4 bv = *(const float4*)&W[(size_t)(k0 + brow) * 512 + colBase + bcol];
        __syncthreads();
        As[(akv + 0) * AS_LD + arow] = av.x;
        As[(akv + 1) * AS_LD + arow] = av.y;
        As[(akv + 2) * AS_LD + arow] = av.z;
        As[(akv + 3) * AS_LD + arow] = av.w;
        *(float4*)&Bs[brow * 128 + bcol] = bv;
        __syncthreads();

#pragma unroll
        for (int k = 0; k < 8; ++k) {
            float a[8], b[8];
            *(float4*)&a[0] = *(const float4*)&As[k * AS_LD + ty * 8];
            *(float4*)&a[4] = *(const float4*)&As[k * AS_LD + ty * 8 + 4];
            *(float4*)&b[0] = *(const float4*)&Bs[k * 128 + tx * 8];
            *(float4*)&b[4] = *(const float4*)&Bs[k * 128 + tx * 8 + 4];
#pragma unroll
            for (int i = 0; i < 8; ++i)
#pragma unroll
                for (int j = 0; j < 8; ++j)
                    acc[i][j] = fmaf(a[i], b[j], acc[i][j]);
        }
    }

    const int col0 = colBase + tx * 8;

    if (DST < 3) {
        float* C = (DST == 0) ? g_q : (DST == 1) ? g_k : g_v;
        const int h  = col0 >> 6;
        const int d0 = col0 & 63;
#pragma unroll
        for (int i = 0; i < 8; ++i) {
            const int row = rowBase + ty * 8 + i;
            const int b   = row >> 11;       // / 2048
            const int n   = row & 2047;
            float* dst = C + (((size_t)(b * HH + h) * NN + n) * DD + d0);
            *(float4*)(dst)     = make_float4(acc[i][0], acc[i][1], acc[i][2], acc[i][3]);
            *(float4*)(dst + 4) = make_float4(acc[i][4], acc[i][5], acc[i][6], acc[i][7]);
        }
    } else {
        float4 b0 = *(const float4*)&bias[col0];
        float4 b1 = *(const float4*)&bias[col0 + 4];
#pragma unroll
        for (int i = 0; i < 8; ++i) {
            const int row = rowBase + ty * 8 + i;
            float* dst = Cout + (size_t)row * 512 + col0;
            *(float4*)(dst)     = make_float4(acc[i][0] + b0.x, acc[i][1] + b0.y,
                                              acc[i][2] + b0.z, acc[i][3] + b0.w);
            *(float4*)(dst + 4) = make_float4(acc[i][4] + b1.x, acc[i][5] + b1.y,
                                              acc[i][6] + b1.z, acc[i][7] + b1.w);
        }
    }
}

// ---------------------------------------------------------------------------
// Flash attention: one query row per thread, BM=128 rows/block, KV tiles BN=64.
// grid = (N/128, B*H), block = 128 threads. Reads g_q/g_k/g_v, writes g_o.
// smem: qs[128][65], kts[64(d)][68(j)], vs[64(j)][68(d)]  -> 68096 B dynamic.
// ---------------------------------------------------------------------------
#define QS_LD 65
#define KT_LD 68
#define VS_LD 68
#define ATTN_SMEM ((128 * QS_LD + 64 * KT_LD + 64 * VS_LD) * 4)

__global__ __launch_bounds__(128)
void attn_kernel()
{
    const float* __restrict__ q = g_q;
    const float* __restrict__ k = g_k;
    const float* __restrict__ v = g_v;
    float* __restrict__ o = g_o;

    extern __shared__ float sm[];
    float* qs  = sm;                       // 128*65
    float* kts = qs + 128 * QS_LD;         // 64*68 (d-major, j contiguous)
    float* vs  = kts + 64 * KT_LD;         // 64*68 (j-major, d contiguous)

    const int t     = threadIdx.x;
    const int bh    = blockIdx.y;
    const int qtile = blockIdx.x;

    // load Q tile (128 rows x 64) into smem
    const float* qbase = q + ((size_t)bh * NN + qtile * 128) * DD;
    {
#pragma unroll
        for (int it = 0; it < 16; ++it) {
            int f   = it * 128 + t;        // 2048 float4 total
            int row = f >> 4, dv = f & 15;
            float4 val = ((const float4*)qbase)[row * 16 + dv];
            float* dst = &qs[row * QS_LD + dv * 4];
            dst[0] = val.x; dst[1] = val.y; dst[2] = val.z; dst[3] = val.w;
        }
    }

    float mrun = -1e30f, lrun = 0.f;
    float4 acc[16];
#pragma unroll
    for (int i = 0; i < 16; ++i) acc[i] = make_float4(0.f, 0.f, 0.f, 0.f);

    for (int jt = 0; jt < NN / 64; ++jt) {
        __syncthreads();   // protect smem from previous iter readers
        const float* kb = k + ((size_t)bh * NN + jt * 64) * DD;
        const float* vb = v + ((size_t)bh * NN + jt * 64) * DD;
#pragma unroll
        for (int it = 0; it < 8; ++it) {
            int f   = it * 128 + t;        // 1024 float4
            int row = f >> 4, dv = f & 15;
            float4 val = ((const float4*)kb)[row * 16 + dv];
            kts[(dv * 4 + 0) * KT_LD + row] = val.x;
            kts[(dv * 4 + 1) * KT_LD + row] = val.y;
            kts[(dv * 4 + 2) * KT_LD + row] = val.z;
            kts[(dv * 4 + 3) * KT_LD + row] = val.w;
        }
#pragma unroll
        for (int it = 0; it < 8; ++it) {
            int f   = it * 128 + t;
            int row = f >> 4, dv = f & 15;
            ((float4*)&vs[row * VS_LD])[dv] = ((const float4*)vb)[row * 16 + dv];
        }
        __syncthreads();

        // --- scores: s[j] = q_row . k_j  (K reads are warp-uniform -> broadcast)
        float s[64];
#pragma unroll
        for (int j = 0; j < 64; ++j) s[j] = 0.f;
        const float* myq = &qs[t * QS_LD];
#pragma unroll 4
        for (int d = 0; d < 64; ++d) {
            float qd = myq[d];
            const float4* kr = (const float4*)&kts[d * KT_LD];
#pragma unroll
            for (int j4 = 0; j4 < 16; ++j4) {
                float4 kv4 = kr[j4];
                s[4 * j4 + 0] = fmaf(qd, kv4.x, s[4 * j4 + 0]);
                s[4 * j4 + 1] = fmaf(qd, kv4.y, s[4 * j4 + 1]);
                s[4 * j4 + 2] = fmaf(qd, kv4.z, s[4 * j4 + 2]);
                s[4 * j4 + 3] = fmaf(qd, kv4.w, s[4 * j4 + 3]);
            }
        }

        // --- online softmax update
        float tmax = -1e30f;
#pragma unroll
        for (int j = 0; j < 64; ++j) tmax = fmaxf(tmax, s[j]);
        float newm = fmaxf(mrun, tmax * NSCALE);
        float corr = __expf(mrun - newm);
        lrun *= corr;
#pragma unroll
        for (int i = 0; i < 16; ++i) {
            acc[i].x *= corr; acc[i].y *= corr; acc[i].z *= corr; acc[i].w *= corr;
        }
        mrun = newm;

#pragma unroll 2
        for (int j = 0; j < 64; ++j) {
            float p = __expf(fmaf(s[j], NSCALE, -newm));
            lrun += p;
            const float4* vr = (const float4*)&vs[j * VS_LD];
#pragma unroll
            for (int d4 = 0; d4 < 16; ++d4) {
                float4 vv = vr[d4];
                acc[d4].x = fmaf(p, vv.x, acc[d4].x);
                acc[d4].y = fmaf(p, vv.y, acc[d4].y);
                acc[d4].z = fmaf(p, vv.z, acc[d4].z);
                acc[d4].w = fmaf(p, vv.w, acc[d4].w);
            }
        }
    }

    // epilogue: o[b, n, h*64 + d]
    const float inv = 1.f / lrun;
    const int b = bh >> 3, h = bh & 7;
    const int n = qtile * 128 + t;
    float* ob = o + ((size_t)(b * NN + n) * INNERR) + h * DD;
#pragma unroll
    for (int d4 = 0; d4 < 16; ++d4) {
        float4 r = acc[d4];
        r.x *= inv; r.y *= inv; r.z *= inv; r.w *= inv;
        ((float4*)ob)[d4] = r;
    }
}

// ---------------------------------------------------------------------------
extern "C" void kernel_launch(void* const* d_in, const int* in_sizes, int n_in,
                              void* d_out, int out_size)
{
    const float* x  = (const float*)d_in[0];
    const float* m  = (const float*)d_in[1];
    const float* Wq = (const float*)d_in[2];
    const float* Wk = (const float*)d_in[3];
    const float* Wv = (const float*)d_in[4];
    const float* Wo = (const float*)d_in[5];
    const float* bo = (const float*)d_in[6];
    float* out = (float*)d_out;

    // allow >48KB dynamic smem for attention (non-stream call; capture-safe)
    static bool attr_done = false;
    if (!attr_done) {
        cudaFuncSetAttribute(attn_kernel,
                             cudaFuncAttributeMaxDynamicSharedMemorySize, ATTN_SMEM);
        attr_done = true;
    }

    dim3 gg(4, 128);   // cols 512/128, rows 16384/128
    gemm128<0><<<gg, 256>>>(x, Wq, bo, nullptr);
    gemm128<1><<<gg, 256>>>(m, Wk, bo, nullptr);
    gemm128<2><<<gg, 256>>>(m, Wv, bo, nullptr);

    attn_kernel<<<dim3(NN / 128, BB * HH), 128, ATTN_SMEM>>>();

    gemm128<3><<<gg, 256>>>(nullptr, Wo, bo, out);
}

// round 3
// speedup vs baseline: 1.0969x; 1.0969x over previous
#include <cuda_runtime.h>
#include <cuda_bf16.h>
#include <cstdint>

// Problem constants
#define BB    8
#define NN    2048
#define DIMM  512
#define HH    8
#define DD    64
#define INNERR 512
#define NSCALE 0.044194173824159216f   // 512^-0.5

typedef unsigned long long u64t;

// ---- packed f32x2 helpers (Blackwell FFMA2 path; ptxas never auto-emits) ----
__device__ __forceinline__ u64t pk2(float lo, float hi) {
    u64t r; asm("mov.b64 %0,{%1,%2};" : "=l"(r) : "f"(lo), "f"(hi)); return r;
}
__device__ __forceinline__ float2 upk2(u64t v) {
    float2 f; asm("mov.b64 {%0,%1},%2;" : "=f"(f.x), "=f"(f.y) : "l"(v)); return f;
}
__device__ __forceinline__ u64t fma2(u64t a, u64t b, u64t c) {
    u64t d; asm("fma.rn.f32x2 %0,%1,%2,%3;" : "=l"(d) : "l"(a), "l"(b), "l"(c)); return d;
}
__device__ __forceinline__ u64t mul2(u64t a, u64t b) {
    u64t d; asm("mul.rn.f32x2 %0,%1,%2;" : "=l"(d) : "l"(a), "l"(b)); return d;
}

// Scratch (allocation-free rule: __device__ globals).
// Referenced ONLY from device code — host never takes their address.
__device__ float g_q[(size_t)BB * HH * NN * DD];   // [b,h,n,d]
__device__ float g_k[(size_t)BB * HH * NN * DD];   // [b,h,n,d]
__device__ float g_v[(size_t)BB * HH * NN * DD];   // [b,h,n,d]
__device__ float g_o[(size_t)BB * NN * INNERR];    // [b,n,(h d)]

// ---------------------------------------------------------------------------
// GEMM: C[16384,512] = A[16384,512] @ W[512,512]
// BM=BN=128, BK=8, 256 threads, 8x8 micro-tile per thread (packed over n).
// DST 0/1/2 -> A from arg, write head-split into g_q/g_k/g_v.
// DST 3     -> A = g_o (device global), write flat + bias to Cout.
// ---------------------------------------------------------------------------
#define AS_LD 132

template<int DST>
__global__ __launch_bounds__(256)
void gemm128(const float* __restrict__ Ain, const float* __restrict__ W,
             const float* __restrict__ bias, float* __restrict__ Cout)
{
    const float* __restrict__ A = (DST == 3) ? (const float*)g_o : Ain;

    __shared__ float As[8 * AS_LD];   // transposed: As[k][m]
    __shared__ float Bs[8 * 128];     // Bs[k][n]

    const int tid = threadIdx.x;
    const int tx  = tid & 15;         // 16 col-groups
    const int ty  = tid >> 4;         // 16 row-groups
    const int rowBase = blockIdx.y * 128;
    const int colBase = blockIdx.x * 128;

    const int arow = tid >> 1;        // 0..127
    const int akv  = (tid & 1) * 4;   // 0 or 4
    const int brow = tid >> 5;        // 0..7
    const int bcol = (tid & 31) * 4;  // 0..124

    u64t acc2[8][4];
#pragma unroll
    for (int i = 0; i < 8; ++i)
#pragma unroll
        for (int j = 0; j < 4; ++j) acc2[i][j] = 0ull;

    for (int kt = 0; kt < 64; ++kt) {
        const int k0 = kt * 8;
        float4 av = *(const float4*)&A[(size_t)(rowBase + arow) * 512 + k0 + akv];
        float4 bv = *(const float4*)&W[(size_t)(k0 + brow) * 512 + colBase + bcol];
        __syncthreads();
        As[(akv + 0) * AS_LD + arow] = av.x;
        As[(akv + 1) * AS_LD + arow] = av.y;
        As[(akv + 2) * AS_LD + arow] = av.z;
        As[(akv + 3) * AS_LD + arow] = av.w;
        *(float4*)&Bs[brow * 128 + bcol] = bv;
        __syncthreads();

#pragma unroll
        for (int k = 0; k < 8; ++k) {
            float a[8];
            *(float4*)&a[0] = *(const float4*)&As[k * AS_LD + ty * 8];
            *(float4*)&a[4] = *(const float4*)&As[k * AS_LD + ty * 8 + 4];
            ulonglong2 b01 = *(const ulonglong2*)&Bs[k * 128 + tx * 8];
            ulonglong2 b23 = *(const ulonglong2*)&Bs[k * 128 + tx * 8 + 4];
#pragma unroll
            for (int i = 0; i < 8; ++i) {
                u64t ai = pk2(a[i], a[i]);
                acc2[i][0] = fma2(ai, b01.x, acc2[i][0]);
                acc2[i][1] = fma2(ai, b01.y, acc2[i][1]);
                acc2[i][2] = fma2(ai, b23.x, acc2[i][2]);
                acc2[i][3] = fma2(ai, b23.y, acc2[i][3]);
            }
        }
    }

    const int col0 = colBase + tx * 8;

    if (DST < 3) {
        float* C = (DST == 0) ? g_q : (DST == 1) ? g_k : g_v;
        const int h  = col0 >> 6;
        const int d0 = col0 & 63;
#pragma unroll
        for (int i = 0; i < 8; ++i) {
            const int row = rowBase + ty * 8 + i;
            const int b   = row >> 11;       // / 2048
            const int n   = row & 2047;
            float* dst = C + (((size_t)(b * HH + h) * NN + n) * DD + d0);
            float2 c0 = upk2(acc2[i][0]), c1 = upk2(acc2[i][1]);
            float2 c2 = upk2(acc2[i][2]), c3 = upk2(acc2[i][3]);
            *(float4*)(dst)     = make_float4(c0.x, c0.y, c1.x, c1.y);
            *(float4*)(dst + 4) = make_float4(c2.x, c2.y, c3.x, c3.y);
        }
    } else {
        float4 b0 = *(const float4*)&bias[col0];
        float4 b1 = *(const float4*)&bias[col0 + 4];
#pragma unroll
        for (int i = 0; i < 8; ++i) {
            const int row = rowBase + ty * 8 + i;
            float* dst = Cout + (size_t)row * 512 + col0;
            float2 c0 = upk2(acc2[i][0]), c1 = upk2(acc2[i][1]);
            float2 c2 = upk2(acc2[i][2]), c3 = upk2(acc2[i][3]);
            *(float4*)(dst)     = make_float4(c0.x + b0.x, c0.y + b0.y,
                                              c1.x + b0.z, c1.y + b0.w);
            *(float4*)(dst + 4) = make_float4(c2.x + b1.x, c2.y + b1.y,
                                              c3.x + b1.z, c3.y + b1.w);
        }
    }
}

// ---------------------------------------------------------------------------
// Flash attention: one query row per thread, BM=128 rows/block, KV tiles BN=64.
// grid = (N/128, B*H), block = 128 threads. Reads g_q/g_k/g_v, writes g_o.
// Inner math fully packed f32x2 (FFMA2).
// smem: qs[128][65], kts[64(d)][68(j)], vs[64(j)][68(d)]  -> 68096 B dynamic.
// ---------------------------------------------------------------------------
#define QS_LD 65
#define KT_LD 68
#define VS_LD 68
#define ATTN_SMEM ((128 * QS_LD + 64 * KT_LD + 64 * VS_LD) * 4)

__global__ __launch_bounds__(128)
void attn_kernel()
{
    const float* __restrict__ q = g_q;
    const float* __restrict__ k = g_k;
    const float* __restrict__ v = g_v;
    float* __restrict__ o = g_o;

    extern __shared__ float sm[];
    float* qs  = sm;                       // 128*65
    float* kts = qs + 128 * QS_LD;         // 64*68 (d-major, j contiguous), 16B-aligned rows
    float* vs  = kts + 64 * KT_LD;         // 64*68 (j-major, d contiguous), 16B-aligned rows

    const int t     = threadIdx.x;
    const int bh    = blockIdx.y;
    const int qtile = blockIdx.x;

    // load Q tile (128 rows x 64) into smem
    const float* qbase = q + ((size_t)bh * NN + qtile * 128) * DD;
    {
#pragma unroll
        for (int it = 0; it < 16; ++it) {
            int f   = it * 128 + t;        // 2048 float4 total
            int row = f >> 4, dv = f & 15;
            float4 val = ((const float4*)qbase)[row * 16 + dv];
            float* dst = &qs[row * QS_LD + dv * 4];
            dst[0] = val.x; dst[1] = val.y; dst[2] = val.z; dst[3] = val.w;
        }
    }

    float mrun = -1e30f, lrun = 0.f;
    u64t acc2[32];                        // packed output accumulator, d pairs
#pragma unroll
    for (int i = 0; i < 32; ++i) acc2[i] = 0ull;

    for (int jt = 0; jt < NN / 64; ++jt) {
        __syncthreads();   // protect smem from previous iter readers
        const float* kb = k + ((size_t)bh * NN + jt * 64) * DD;
        const float* vb = v + ((size_t)bh * NN + jt * 64) * DD;
#pragma unroll
        for (int it = 0; it < 8; ++it) {
            int f   = it * 128 + t;        // 1024 float4
            int row = f >> 4, dv = f & 15;
            float4 val = ((const float4*)kb)[row * 16 + dv];
            kts[(dv * 4 + 0) * KT_LD + row] = val.x;
            kts[(dv * 4 + 1) * KT_LD + row] = val.y;
            kts[(dv * 4 + 2) * KT_LD + row] = val.z;
            kts[(dv * 4 + 3) * KT_LD + row] = val.w;
        }
#pragma unroll
        for (int it = 0; it < 8; ++it) {
            int f   = it * 128 + t;
            int row = f >> 4, dv = f & 15;
            ((float4*)&vs[row * VS_LD])[dv] = ((const float4*)vb)[row * 16 + dv];
        }
        __syncthreads();

        // --- scores: s[j] = q_row . k_j  (K reads warp-uniform -> broadcast)
        u64t s2[32];
#pragma unroll
        for (int j = 0; j < 32; ++j) s2[j] = 0ull;
        const float* myq = &qs[t * QS_LD];
#pragma unroll 4
        for (int d = 0; d < 64; ++d) {
            float qd = myq[d];
            u64t q2 = pk2(qd, qd);
            const ulonglong2* kr = (const ulonglong2*)&kts[d * KT_LD];
#pragma unroll
            for (int j4 = 0; j4 < 16; ++j4) {
                ulonglong2 kv = kr[j4];
                s2[2 * j4 + 0] = fma2(q2, kv.x, s2[2 * j4 + 0]);
                s2[2 * j4 + 1] = fma2(q2, kv.y, s2[2 * j4 + 1]);
            }
        }

        // --- online softmax update
        float tmax = -1e30f;
#pragma unroll
        for (int j = 0; j < 32; ++j) {
            float2 f = upk2(s2[j]);
            tmax = fmaxf(tmax, fmaxf(f.x, f.y));
        }
        float newm = fmaxf(mrun, tmax * NSCALE);
        float corr = __expf(mrun - newm);
        lrun *= corr;
        u64t corr2 = pk2(corr, corr);
#pragma unroll
        for (int i = 0; i < 32; ++i) acc2[i] = mul2(corr2, acc2[i]);
        mrun = newm;

#pragma unroll 2
        for (int j2 = 0; j2 < 32; ++j2) {
            float2 sv = upk2(s2[j2]);
            float p0 = __expf(fmaf(sv.x, NSCALE, -newm));
            float p1 = __expf(fmaf(sv.y, NSCALE, -newm));
            lrun += p0 + p1;
            u64t pp0 = pk2(p0, p0);
            u64t pp1 = pk2(p1, p1);
            const ulonglong2* v0 = (const ulonglong2*)&vs[(2 * j2 + 0) * VS_LD];
            const ulonglong2* v1 = (const ulonglong2*)&vs[(2 * j2 + 1) * VS_LD];
#pragma unroll
            for (int k4 = 0; k4 < 16; ++k4) {
                ulonglong2 vv = v0[k4];
                acc2[2 * k4 + 0] = fma2(pp0, vv.x, acc2[2 * k4 + 0]);
                acc2[2 * k4 + 1] = fma2(pp0, vv.y, acc2[2 * k4 + 1]);
            }
#pragma unroll
            for (int k4 = 0; k4 < 16; ++k4) {
                ulonglong2 vv = v1[k4];
                acc2[2 * k4 + 0] = fma2(pp1, vv.x, acc2[2 * k4 + 0]);
                acc2[2 * k4 + 1] = fma2(pp1, vv.y, acc2[2 * k4 + 1]);
            }
        }
    }

    // epilogue: o[b, n, h*64 + d]
    const float inv = 1.f / lrun;
    const int b = bh >> 3, h = bh & 7;
    const int n = qtile * 128 + t;
    float* ob = o + ((size_t)(b * NN + n) * INNERR) + h * DD;
#pragma unroll
    for (int d4 = 0; d4 < 16; ++d4) {
        float2 c0 = upk2(acc2[2 * d4 + 0]);
        float2 c1 = upk2(acc2[2 * d4 + 1]);
        ((float4*)ob)[d4] = make_float4(c0.x * inv, c0.y * inv, c1.x * inv, c1.y * inv);
    }
}

// ---------------------------------------------------------------------------
extern "C" void kernel_launch(void* const* d_in, const int* in_sizes, int n_in,
                              void* d_out, int out_size)
{
    const float* x  = (const float*)d_in[0];
    const float* m  = (const float*)d_in[1];
    const float* Wq = (const float*)d_in[2];
    const float* Wk = (const float*)d_in[3];
    const float* Wv = (const float*)d_in[4];
    const float* Wo = (const float*)d_in[5];
    const float* bo = (const float*)d_in[6];
    float* out = (float*)d_out;

    // allow >48KB dynamic smem for attention (non-stream call; capture-safe)
    cudaFuncSetAttribute(attn_kernel,
                         cudaFuncAttributeMaxDynamicSharedMemorySize, ATTN_SMEM);

    dim3 gg(4, 128);   // cols 512/128, rows 16384/128
    gemm128<0><<<gg, 256>>>(x, Wq, bo, nullptr);
    gemm128<1><<<gg, 256>>>(m, Wk, bo, nullptr);
    gemm128<2><<<gg, 256>>>(m, Wv, bo, nullptr);

    attn_kernel<<<dim3(NN / 128, BB * HH), 128, ATTN_SMEM>>>();

    gemm128<3><<<gg, 256>>>(nullptr, Wo, bo, out);
}

// round 4
// speedup vs baseline: 1.6101x; 1.4678x over previous
#include <cuda_runtime.h>
#include <cuda_bf16.h>
#include <cstdint>

// Problem constants
#define BB    8
#define NN    2048
#define DIMM  512
#define HH    8
#define DD    64
#define INNERR 512
#define NSCALE 0.044194173824159216f   // 512^-0.5

typedef unsigned long long u64t;

// ---- packed f32x2 helpers (Blackwell FFMA2 path; ptxas never auto-emits) ----
__device__ __forceinline__ u64t pk2(float lo, float hi) {
    u64t r; asm("mov.b64 %0,{%1,%2};" : "=l"(r) : "f"(lo), "f"(hi)); return r;
}
__device__ __forceinline__ float2 upk2(u64t v) {
    float2 f; asm("mov.b64 {%0,%1},%2;" : "=f"(f.x), "=f"(f.y) : "l"(v)); return f;
}
__device__ __forceinline__ u64t fma2(u64t a, u64t b, u64t c) {
    u64t d; asm("fma.rn.f32x2 %0,%1,%2,%3;" : "=l"(d) : "l"(a), "l"(b), "l"(c)); return d;
}
__device__ __forceinline__ u64t mul2(u64t a, u64t b) {
    u64t d; asm("mul.rn.f32x2 %0,%1,%2;" : "=l"(d) : "l"(a), "l"(b)); return d;
}

// Scratch (allocation-free rule: __device__ globals).
// Referenced ONLY from device code — host never takes their address.
__device__ float g_q[(size_t)BB * HH * NN * DD];   // [b,h,n,d]
__device__ float g_k[(size_t)BB * HH * NN * DD];   // [b,h,n,d]
__device__ float g_v[(size_t)BB * HH * NN * DD];   // [b,h,n,d]
__device__ float g_o[(size_t)BB * NN * INNERR];    // [b,n,(h d)]

// ---------------------------------------------------------------------------
// GEMM: C[16384,512] = A[16384,512] @ W[512,512]
// BM=BN=128, BK=8, 256 threads, 8x8 micro-tile per thread (packed over n).
// ---------------------------------------------------------------------------
#define AS_LD 132

template<int DST>
__global__ __launch_bounds__(256)
void gemm128(const float* __restrict__ Ain, const float* __restrict__ W,
             const float* __restrict__ bias, float* __restrict__ Cout)
{
    const float* __restrict__ A = (DST == 3) ? (const float*)g_o : Ain;

    __shared__ float As[8 * AS_LD];   // transposed: As[k][m]
    __shared__ float Bs[8 * 128];     // Bs[k][n]

    const int tid = threadIdx.x;
    const int tx  = tid & 15;
    const int ty  = tid >> 4;
    const int rowBase = blockIdx.y * 128;
    const int colBase = blockIdx.x * 128;

    const int arow = tid >> 1;
    const int akv  = (tid & 1) * 4;
    const int brow = tid >> 5;
    const int bcol = (tid & 31) * 4;

    u64t acc2[8][4];
#pragma unroll
    for (int i = 0; i < 8; ++i)
#pragma unroll
        for (int j = 0; j < 4; ++j) acc2[i][j] = 0ull;

    for (int kt = 0; kt < 64; ++kt) {
        const int k0 = kt * 8;
        float4 av = *(const float4*)&A[(size_t)(rowBase + arow) * 512 + k0 + akv];
        float4 bv = *(const float4*)&W[(size_t)(k0 + brow) * 512 + colBase + bcol];
        __syncthreads();
        As[(akv + 0) * AS_LD + arow] = av.x;
        As[(akv + 1) * AS_LD + arow] = av.y;
        As[(akv + 2) * AS_LD + arow] = av.z;
        As[(akv + 3) * AS_LD + arow] = av.w;
        *(float4*)&Bs[brow * 128 + bcol] = bv;
        __syncthreads();

#pragma unroll
        for (int k = 0; k < 8; ++k) {
            float a[8];
            *(float4*)&a[0] = *(const float4*)&As[k * AS_LD + ty * 8];
            *(float4*)&a[4] = *(const float4*)&As[k * AS_LD + ty * 8 + 4];
            ulonglong2 b01 = *(const ulonglong2*)&Bs[k * 128 + tx * 8];
            ulonglong2 b23 = *(const ulonglong2*)&Bs[k * 128 + tx * 8 + 4];
#pragma unroll
            for (int i = 0; i < 8; ++i) {
                u64t ai = pk2(a[i], a[i]);
                acc2[i][0] = fma2(ai, b01.x, acc2[i][0]);
                acc2[i][1] = fma2(ai, b01.y, acc2[i][1]);
                acc2[i][2] = fma2(ai, b23.x, acc2[i][2]);
                acc2[i][3] = fma2(ai, b23.y, acc2[i][3]);
            }
        }
    }

    const int col0 = colBase + tx * 8;

    if (DST < 3) {
        float* C = (DST == 0) ? g_q : (DST == 1) ? g_k : g_v;
        const int h  = col0 >> 6;
        const int d0 = col0 & 63;
#pragma unroll
        for (int i = 0; i < 8; ++i) {
            const int row = rowBase + ty * 8 + i;
            const int b   = row >> 11;
            const int n   = row & 2047;
            float* dst = C + (((size_t)(b * HH + h) * NN + n) * DD + d0);
            float2 c0 = upk2(acc2[i][0]), c1 = upk2(acc2[i][1]);
            float2 c2 = upk2(acc2[i][2]), c3 = upk2(acc2[i][3]);
            *(float4*)(dst)     = make_float4(c0.x, c0.y, c1.x, c1.y);
            *(float4*)(dst + 4) = make_float4(c2.x, c2.y, c3.x, c3.y);
        }
    } else {
        float4 b0 = *(const float4*)&bias[col0];
        float4 b1 = *(const float4*)&bias[col0 + 4];
#pragma unroll
        for (int i = 0; i < 8; ++i) {
            const int row = rowBase + ty * 8 + i;
            float* dst = Cout + (size_t)row * 512 + col0;
            float2 c0 = upk2(acc2[i][0]), c1 = upk2(acc2[i][1]);
            float2 c2 = upk2(acc2[i][2]), c3 = upk2(acc2[i][3]);
            *(float4*)(dst)     = make_float4(c0.x + b0.x, c0.y + b0.y,
                                              c1.x + b0.z, c1.y + b0.w);
            *(float4*)(dst + 4) = make_float4(c2.x + b1.x, c2.y + b1.y,
                                              c3.x + b1.z, c3.y + b1.w);
        }
    }
}

// ---------------------------------------------------------------------------
// Flash attention, 2 query rows per thread (rows t and t+128).
// BM=256 q rows / block (128 threads), KV tiles BN=32.
// grid = (N/256, B*H). All inner math packed f32x2.
// smem: qs[256][65] + kts[64][36] + vs[32][68]  = 84480 B dynamic.
// ---------------------------------------------------------------------------
#define QS_LD 65
#define KT_LD 36
#define VS_LD 68
#define ATTN_SMEM ((256 * QS_LD + 64 * KT_LD + 32 * VS_LD) * 4)

__global__ __launch_bounds__(128)
void attn_kernel()
{
    const float* __restrict__ q = g_q;
    const float* __restrict__ k = g_k;
    const float* __restrict__ v = g_v;
    float* __restrict__ o = g_o;

    extern __shared__ float sm[];
    float* qs  = sm;                       // 256*65
    float* kts = qs + 256 * QS_LD;         // 64(d) x 36 (j contiguous)
    float* vs  = kts + 64 * KT_LD;         // 32(j) x 68 (d contiguous)

    const int t     = threadIdx.x;
    const int bh    = blockIdx.y;
    const int qtile = blockIdx.x;

    // load Q tile (256 rows x 64) into smem
    const float* qbase = q + ((size_t)bh * NN + qtile * 256) * DD;
#pragma unroll
    for (int it = 0; it < 32; ++it) {
        int f   = it * 128 + t;            // 4096 float4 total
        int row = f >> 4, dv = f & 15;
        float4 val = ((const float4*)qbase)[row * 16 + dv];
        float* dst = &qs[row * QS_LD + dv * 4];
        dst[0] = val.x; dst[1] = val.y; dst[2] = val.z; dst[3] = val.w;
    }

    float m0 = -1e30f, m1 = -1e30f, l0 = 0.f, l1 = 0.f;
    u64t a0[32], a1[32];                  // packed over d: 2 rows x 64 d
#pragma unroll
    for (int i = 0; i < 32; ++i) { a0[i] = 0ull; a1[i] = 0ull; }

    const float* q0p = &qs[t * QS_LD];
    const float* q1p = &qs[(t + 128) * QS_LD];

    for (int jt = 0; jt < NN / 32; ++jt) {
        __syncthreads();                   // protect smem from previous readers
        const float* kb = k + ((size_t)bh * NN + jt * 32) * DD;
        const float* vb = v + ((size_t)bh * NN + jt * 32) * DD;
        // K tile 32x64 -> transposed kts[d][j]
#pragma unroll
        for (int it = 0; it < 4; ++it) {
            int f   = it * 128 + t;        // 512 float4
            int row = f >> 4, dv = f & 15;
            float4 val = ((const float4*)kb)[row * 16 + dv];
            kts[(dv * 4 + 0) * KT_LD + row] = val.x;
            kts[(dv * 4 + 1) * KT_LD + row] = val.y;
            kts[(dv * 4 + 2) * KT_LD + row] = val.z;
            kts[(dv * 4 + 3) * KT_LD + row] = val.w;
        }
        // V tile 32x64 j-major
#pragma unroll
        for (int it = 0; it < 4; ++it) {
            int f   = it * 128 + t;
            int row = f >> 4, dv = f & 15;
            ((float4*)&vs[row * VS_LD])[dv] = ((const float4*)vb)[row * 16 + dv];
        }
        __syncthreads();

        // --- scores for both rows: packed over j (16 u64 = 32 j each)
        u64t s0[16], s1[16];
#pragma unroll
        for (int j = 0; j < 16; ++j) { s0[j] = 0ull; s1[j] = 0ull; }
#pragma unroll 4
        for (int d = 0; d < 64; ++d) {
            float qa = q0p[d], qb = q1p[d];
            u64t qa2 = pk2(qa, qa);
            u64t qb2 = pk2(qb, qb);
            const ulonglong2* kr = (const ulonglong2*)&kts[d * KT_LD];
#pragma unroll
            for (int j4 = 0; j4 < 8; ++j4) {
                ulonglong2 kv = kr[j4];
                s0[2 * j4 + 0] = fma2(qa2, kv.x, s0[2 * j4 + 0]);
                s0[2 * j4 + 1] = fma2(qa2, kv.y, s0[2 * j4 + 1]);
                s1[2 * j4 + 0] = fma2(qb2, kv.x, s1[2 * j4 + 0]);
                s1[2 * j4 + 1] = fma2(qb2, kv.y, s1[2 * j4 + 1]);
            }
        }

        // --- online softmax update (per row)
        float t0 = -1e30f, t1 = -1e30f;
#pragma unroll
        for (int j = 0; j < 16; ++j) {
            float2 f0 = upk2(s0[j]); t0 = fmaxf(t0, fmaxf(f0.x, f0.y));
            float2 f1 = upk2(s1[j]); t1 = fmaxf(t1, fmaxf(f1.x, f1.y));
        }
        float nm0 = fmaxf(m0, t0 * NSCALE);
        float nm1 = fmaxf(m1, t1 * NSCALE);
        float c0 = __expf(m0 - nm0);
        float c1 = __expf(m1 - nm1);
        l0 *= c0; l1 *= c1;
        u64t c02 = pk2(c0, c0), c12 = pk2(c1, c1);
#pragma unroll
        for (int i = 0; i < 32; ++i) { a0[i] = mul2(c02, a0[i]); a1[i] = mul2(c12, a1[i]); }
        m0 = nm0; m1 = nm1;

        // --- PV: 16 pairs of j
#pragma unroll 2
        for (int j2 = 0; j2 < 16; ++j2) {
            float2 sv0 = upk2(s0[j2]);
            float2 sv1 = upk2(s1[j2]);
            float p00 = __expf(fmaf(sv0.x, NSCALE, -nm0));
            float p01 = __expf(fmaf(sv0.y, NSCALE, -nm0));
            float p10 = __expf(fmaf(sv1.x, NSCALE, -nm1));
            float p11 = __expf(fmaf(sv1.y, NSCALE, -nm1));
            l0 += p00 + p01;
            l1 += p10 + p11;
            u64t q00 = pk2(p00, p00), q01 = pk2(p01, p01);
            u64t q10 = pk2(p10, p10), q11 = pk2(p11, p11);
            const ulonglong2* vr0 = (const ulonglong2*)&vs[(2 * j2 + 0) * VS_LD];
            const ulonglong2* vr1 = (const ulonglong2*)&vs[(2 * j2 + 1) * VS_LD];
#pragma unroll
            for (int k4 = 0; k4 < 16; ++k4) {
                ulonglong2 vv = vr0[k4];
                a0[2 * k4 + 0] = fma2(q00, vv.x, a0[2 * k4 + 0]);
                a0[2 * k4 + 1] = fma2(q00, vv.y, a0[2 * k4 + 1]);
                a1[2 * k4 + 0] = fma2(q10, vv.x, a1[2 * k4 + 0]);
                a1[2 * k4 + 1] = fma2(q10, vv.y, a1[2 * k4 + 1]);
            }
#pragma unroll
            for (int k4 = 0; k4 < 16; ++k4) {
                ulonglong2 vv = vr1[k4];
                a0[2 * k4 + 0] = fma2(q01, vv.x, a0[2 * k4 + 0]);
                a0[2 * k4 + 1] = fma2(q01, vv.y, a0[2 * k4 + 1]);
                a1[2 * k4 + 0] = fma2(q11, vv.x, a1[2 * k4 + 0]);
                a1[2 * k4 + 1] = fma2(q11, vv.y, a1[2 * k4 + 1]);
            }
        }
    }

    // epilogue: o[b, n, h*64 + d] for rows t and t+128
    const int b = bh >> 3, h = bh & 7;
    {
        const float inv = 1.f / l0;
        const int n = qtile * 256 + t;
        float* ob = o + ((size_t)(b * NN + n) * INNERR) + h * DD;
#pragma unroll
        for (int d4 = 0; d4 < 16; ++d4) {
            float2 x0 = upk2(a0[2 * d4 + 0]);
            float2 x1 = upk2(a0[2 * d4 + 1]);
            ((float4*)ob)[d4] = make_float4(x0.x * inv, x0.y * inv, x1.x * inv, x1.y * inv);
        }
    }
    {
        const float inv = 1.f / l1;
        const int n = qtile * 256 + t + 128;
        float* ob = o + ((size_t)(b * NN + n) * INNERR) + h * DD;
#pragma unroll
        for (int d4 = 0; d4 < 16; ++d4) {
            float2 x0 = upk2(a1[2 * d4 + 0]);
            float2 x1 = upk2(a1[2 * d4 + 1]);
            ((float4*)ob)[d4] = make_float4(x0.x * inv, x0.y * inv, x1.x * inv, x1.y * inv);
        }
    }
}

// ---------------------------------------------------------------------------
extern "C" void kernel_launch(void* const* d_in, const int* in_sizes, int n_in,
                              void* d_out, int out_size)
{
    const float* x  = (const float*)d_in[0];
    const float* m  = (const float*)d_in[1];
    const float* Wq = (const float*)d_in[2];
    const float* Wk = (const float*)d_in[3];
    const float* Wv = (const float*)d_in[4];
    const float* Wo = (const float*)d_in[5];
    const float* bo = (const float*)d_in[6];
    float* out = (float*)d_out;

    cudaFuncSetAttribute(attn_kernel,
                         cudaFuncAttributeMaxDynamicSharedMemorySize, ATTN_SMEM);

    dim3 gg(4, 128);   // cols 512/128, rows 16384/128
    gemm128<0><<<gg, 256>>>(x, Wq, bo, nullptr);
    gemm128<1><<<gg, 256>>>(m, Wk, bo, nullptr);
    gemm128<2><<<gg, 256>>>(m, Wv, bo, nullptr);

    attn_kernel<<<dim3(NN / 256, BB * HH), 128, ATTN_SMEM>>>();

    gemm128<3><<<gg, 256>>>(nullptr, Wo, bo, out);
}

// round 6
// speedup vs baseline: 1.7434x; 1.0828x over previous
#include <cuda_runtime.h>
#include <cuda_bf16.h>
#include <cstdint>

// Problem constants
#define BB    8
#define NN    2048
#define DIMM  512
#define HH    8
#define DD    64
#define INNERR 512
#define NSCALE 0.044194173824159216f   // 512^-0.5

typedef unsigned long long u64t;

// ---- packed f32x2 helpers (attention path) ----
__device__ __forceinline__ u64t pk2(float lo, float hi) {
    u64t r; asm("mov.b64 %0,{%1,%2};" : "=l"(r) : "f"(lo), "f"(hi)); return r;
}
__device__ __forceinline__ float2 upk2(u64t v) {
    float2 f; asm("mov.b64 {%0,%1},%2;" : "=f"(f.x), "=f"(f.y) : "l"(v)); return f;
}
__device__ __forceinline__ u64t fma2(u64t a, u64t b, u64t c) {
    u64t d; asm("fma.rn.f32x2 %0,%1,%2,%3;" : "=l"(d) : "l"(a), "l"(b), "l"(c)); return d;
}
__device__ __forceinline__ u64t mul2(u64t a, u64t b) {
    u64t d; asm("mul.rn.f32x2 %0,%1,%2;" : "=l"(d) : "l"(a), "l"(b)); return d;
}

// ---- warp MMA helpers (sm_80+ baseline; no arch-'a' gating) ----
__device__ __forceinline__ void ldsm4(uint32_t* r, uint32_t addr) {
    asm volatile("ldmatrix.sync.aligned.m8n8.x4.shared.b16 {%0,%1,%2,%3}, [%4];"
                 : "=r"(r[0]), "=r"(r[1]), "=r"(r[2]), "=r"(r[3]) : "r"(addr));
}
__device__ __forceinline__ void mma16816(float* c, const uint32_t* a, const uint32_t* b) {
    asm volatile("mma.sync.aligned.m16n8k16.row.col.f32.bf16.bf16.f32 "
                 "{%0,%1,%2,%3}, {%4,%5,%6,%7}, {%8,%9}, {%0,%1,%2,%3};"
                 : "+f"(c[0]), "+f"(c[1]), "+f"(c[2]), "+f"(c[3])
                 : "r"(a[0]), "r"(a[1]), "r"(a[2]), "r"(a[3]), "r"(b[0]), "r"(b[1]));
}
__device__ __forceinline__ uint32_t smem_to_u32(const void* p) {
    uint32_t a;
    asm("{ .reg .u64 t; cvta.to.shared.u64 t, %1; cvt.u32.u64 %0, t; }"
        : "=r"(a) : "l"(p));
    return a;
}
#define SWZ(off) ((off) ^ (((off) >> 3) & 0x70))

// =========================== scratch (device globals only) =================
__device__ float g_q[(size_t)BB * HH * NN * DD];
__device__ float g_k[(size_t)BB * HH * NN * DD];
__device__ float g_v[(size_t)BB * HH * NN * DD];
__device__ float g_o[(size_t)BB * NN * INNERR];

#define ACNT ((size_t)16384 * 512)
__device__ unsigned short g_xh[ACNT], g_xl[ACNT];
__device__ unsigned short g_mh[ACNT], g_ml[ACNT];
__device__ unsigned short g_oh[ACNT], g_ol[ACNT];
#define WCNT ((size_t)512 * 512)
__device__ unsigned short g_wqh[WCNT], g_wql[WCNT];
__device__ unsigned short g_wkh[WCNT], g_wkl[WCNT];
__device__ unsigned short g_wvh[WCNT], g_wvl[WCNT];
__device__ unsigned short g_woh[WCNT], g_wol[WCNT];

__device__ __forceinline__ void bf16split(float v, unsigned short& h, unsigned short& l) {
    __nv_bfloat16 bh = __float2bfloat16(v);
    float r = v - __bfloat162float(bh);
    __nv_bfloat16 bl = __float2bfloat16(r);
    h = __bfloat16_as_ushort(bh);
    l = __bfloat16_as_ushort(bl);
}

// ---------------------------------------------------------------------------
// cvtA<SEL>: row-major fp32 [16384,512] -> bf16 hi/lo (same layout).
// ---------------------------------------------------------------------------
template<int SEL>
__global__ __launch_bounds__(256)
void cvtA(const float* __restrict__ srcArg)
{
    const float* src = (SEL == 2) ? (const float*)g_o : srcArg;
    unsigned short* h = (SEL == 0) ? g_xh : (SEL == 1) ? g_mh : g_oh;
    unsigned short* l = (SEL == 0) ? g_xl : (SEL == 1) ? g_ml : g_ol;
    size_t i4 = (size_t)blockIdx.x * 256 + threadIdx.x;
    float4 v = ((const float4*)src)[i4];
    ushort4 hv, lv;
    bf16split(v.x, hv.x, lv.x);
    bf16split(v.y, hv.y, lv.y);
    bf16split(v.z, hv.z, lv.z);
    bf16split(v.w, hv.w, lv.w);
    ((ushort4*)h)[i4] = hv;
    ((ushort4*)l)[i4] = lv;
}

// ---------------------------------------------------------------------------
// cvtW<SEL>: W[512 k,512 n] fp32 -> transposed bf16 hi/lo Wt[n][k].
// ---------------------------------------------------------------------------
template<int SEL>
__global__ __launch_bounds__(1024)
void cvtW(const float* __restrict__ W)
{
    unsigned short* h = (SEL == 0) ? g_wqh : (SEL == 1) ? g_wkh : (SEL == 2) ? g_wvh : g_woh;
    unsigned short* l = (SEL == 0) ? g_wql : (SEL == 1) ? g_wkl : (SEL == 2) ? g_wvl : g_wol;
    __shared__ float tile[32][33];
    int k = blockIdx.y * 32 + threadIdx.y;
    int n = blockIdx.x * 32 + threadIdx.x;
    tile[threadIdx.y][threadIdx.x] = W[(size_t)k * 512 + n];
    __syncthreads();
    int nn = blockIdx.x * 32 + threadIdx.y;
    int kk = blockIdx.y * 32 + threadIdx.x;
    float v = tile[threadIdx.x][threadIdx.y];
    unsigned short hv, lv;
    bf16split(v, hv, lv);
    h[(size_t)nn * 512 + kk] = hv;
    l[(size_t)nn * 512 + kk] = lv;
}

// ---------------------------------------------------------------------------
// HMMA GEMM: C[16384,512] = A[16384,512] @ W[512,512], bf16 3-split.
// Block 128x128, 8 warps (2m x 4n), warp tile 64x32, k-chunks of 64.
// smem: 4 tiles of 128x64 bf16 (SW128-swizzled) = 64 KB dynamic.
// ---------------------------------------------------------------------------
#define SA_H 0
#define SA_L 16384
#define SB_H 32768
#define SB_L 49152
#define GM_SMEM 65536

template<int DST>
__global__ __launch_bounds__(256)
void gemm_mma(const float* __restrict__ bias, float* __restrict__ Cout)
{
    const unsigned short* Ah = (DST == 0) ? g_xh : (DST == 3) ? g_oh : g_mh;
    const unsigned short* Al = (DST == 0) ? g_xl : (DST == 3) ? g_ol : g_ml;
    const unsigned short* Bhp = (DST == 0) ? g_wqh : (DST == 1) ? g_wkh
                               : (DST == 2) ? g_wvh : g_woh;
    const unsigned short* Blp = (DST == 0) ? g_wql : (DST == 1) ? g_wkl
                               : (DST == 2) ? g_wvl : g_wol;

    extern __shared__ char smem[];
    const uint32_t sb = smem_to_u32(smem);

    const int tid  = threadIdx.x;
    const int wid  = tid >> 5;
    const int lane = tid & 31;
    const int warp_m = wid >> 2;        // 0..1
    const int warp_n = wid & 3;         // 0..3
    const int rowBase = blockIdx.y * 128;
    const int colBase = blockIdx.x * 128;

    float c[4][4][4];
#pragma unroll
    for (int i = 0; i < 4; ++i)
#pragma unroll
        for (int j = 0; j < 4; ++j)
#pragma unroll
            for (int e = 0; e < 4; ++e) c[i][j][e] = 0.f;

    // ldmatrix lane-address bases (byte offsets within a 128x64 tile)
    // A (x4 over m16k16): lane -> row (lane&15), k-half (lane>>4)
    uint32_t aAddr[4], maskA[4];
    {
        int r = lane & 15, hf = lane >> 4;
#pragma unroll
        for (int mt = 0; mt < 4; ++mt) {
            uint32_t rb = (uint32_t)((warp_m * 64 + mt * 16 + r) * 128 + hf * 16);
            maskA[mt] = (rb >> 3) & 0x70;
            aAddr[mt] = rb;
        }
    }
    // B (x4 over two n8k16 tiles): lane -> n row, k-half
    uint32_t bAddr[2], maskB[2];
    {
        int rn = ((lane >> 4) << 3) + (lane & 7);
        int hf = (lane >> 3) & 1;
#pragma unroll
        for (int nt2 = 0; nt2 < 2; ++nt2) {
            uint32_t rb = (uint32_t)((warp_n * 32 + nt2 * 16 + rn) * 128 + hf * 16);
            maskB[nt2] = (rb >> 3) & 0x70;
            bAddr[nt2] = rb;
        }
    }

    for (int kc = 0; kc < 8; ++kc) {
        // load 4 tiles of 128x64 bf16 into swizzled smem (1024x16B each)
        __syncthreads();
#pragma unroll
        for (int it = 0; it < 4; ++it) {
            int unit = it * 256 + tid;
            int row = unit >> 3, seg = unit & 7;
            uint32_t off = SWZ((uint32_t)(row * 128 + seg * 16));
            size_t ga = (size_t)(rowBase + row) * 512 + kc * 64 + seg * 8;
            size_t gb = (size_t)(colBase + row) * 512 + kc * 64 + seg * 8;
            *(uint4*)(smem + SA_H + off) = *(const uint4*)(Ah + ga);
            *(uint4*)(smem + SA_L + off) = *(const uint4*)(Al + ga);
            *(uint4*)(smem + SB_H + off) = *(const uint4*)(Bhp + gb);
            *(uint4*)(smem + SB_L + off) = *(const uint4*)(Blp + gb);
        }
        __syncthreads();

#pragma unroll
        for (int ks = 0; ks < 4; ++ks) {
            uint32_t ah[4][4], al[4][4], bh[4][2], bl[4][2];
#pragma unroll
            for (int mt = 0; mt < 4; ++mt) {
                uint32_t o = ((aAddr[mt] + ks * 32) ^ maskA[mt]);
                ldsm4(ah[mt], sb + SA_H + o);
                ldsm4(al[mt], sb + SA_L + o);
            }
#pragma unroll
            for (int nt2 = 0; nt2 < 2; ++nt2) {
                uint32_t o = ((bAddr[nt2] + ks * 32) ^ maskB[nt2]);
                uint32_t t4[4];
                ldsm4(t4, sb + SB_H + o);
                bh[2 * nt2][0] = t4[0]; bh[2 * nt2][1] = t4[1];
                bh[2 * nt2 + 1][0] = t4[2]; bh[2 * nt2 + 1][1] = t4[3];
                ldsm4(t4, sb + SB_L + o);
                bl[2 * nt2][0] = t4[0]; bl[2 * nt2][1] = t4[1];
                bl[2 * nt2 + 1][0] = t4[2]; bl[2 * nt2 + 1][1] = t4[3];
            }
#pragma unroll
            for (int mt = 0; mt < 4; ++mt)
#pragma unroll
                for (int nt = 0; nt < 4; ++nt) {
                    mma16816(c[mt][nt], ah[mt], bh[nt]);
                    mma16816(c[mt][nt], ah[mt], bl[nt]);
                    mma16816(c[mt][nt], al[mt], bh[nt]);
                }
        }
    }

    // epilogue: thread holds (row t/4 [+8], col 2*(t%4)+{0,1}) per 16x8 tile
    const int r0 = (lane >> 2);
    const int c2 = 2 * (lane & 3);
#pragma unroll
    for (int mt = 0; mt < 4; ++mt) {
#pragma unroll
        for (int nt = 0; nt < 4; ++nt) {
            int row = rowBase + warp_m * 64 + mt * 16 + r0;
            int col = colBase + warp_n * 32 + nt * 8 + c2;
            if (DST < 3) {
                float* C = (DST == 0) ? g_q : (DST == 1) ? g_k : g_v;
                const int h = col >> 6, d0 = col & 63;
                {
                    const int b = row >> 11, n = row & 2047;
                    float* p = C + (((size_t)(b * HH + h) * NN + n) * DD + d0);
                    *(float2*)p = make_float2(c[mt][nt][0], c[mt][nt][1]);
                }
                {
                    const int rw = row + 8;
                    const int b = rw >> 11, n = rw & 2047;
                    float* p = C + (((size_t)(b * HH + h) * NN + n) * DD + d0);
                    *(float2*)p = make_float2(c[mt][nt][2], c[mt][nt][3]);
                }
            } else {
                float2 bv = *(const float2*)&bias[col];
                float* p0 = Cout + (size_t)row * 512 + col;
                *(float2*)p0 = make_float2(c[mt][nt][0] + bv.x, c[mt][nt][1] + bv.y);
                float* p1 = Cout + (size_t)(row + 8) * 512 + col;
                *(float2*)p1 = make_float2(c[mt][nt][2] + bv.x, c[mt][nt][3] + bv.y);
            }
        }
    }
}

// ---------------------------------------------------------------------------
// Flash attention (FFMA2, verified): 2 q rows/thread, BM=256, BN=32.
// grid = (N/256, B*H), 128 threads.
// ---------------------------------------------------------------------------
#define QS_LD 65
#define KT_LD 36
#define VS_LD 68
#define ATTN_SMEM ((256 * QS_LD + 64 * KT_LD + 32 * VS_LD) * 4)

__global__ __launch_bounds__(128)
void attn_kernel()
{
    const float* __restrict__ q = g_q;
    const float* __restrict__ k = g_k;
    const float* __restrict__ v = g_v;
    float* __restrict__ o = g_o;

    extern __shared__ float sm[];
    float* qs  = sm;
    float* kts = qs + 256 * QS_LD;
    float* vs  = kts + 64 * KT_LD;

    const int t     = threadIdx.x;
    const int bh    = blockIdx.y;
    const int qtile = blockIdx.x;

    const float* qbase = q + ((size_t)bh * NN + qtile * 256) * DD;
#pragma unroll
    for (int it = 0; it < 32; ++it) {
        int f   = it * 128 + t;
        int row = f >> 4, dv = f & 15;
        float4 val = ((const float4*)qbase)[row * 16 + dv];
        float* dst = &qs[row * QS_LD + dv * 4];
        dst[0] = val.x; dst[1] = val.y; dst[2] = val.z; dst[3] = val.w;
    }

    float m0 = -1e30f, m1 = -1e30f, l0 = 0.f, l1 = 0.f;
    u64t a0[32], a1[32];
#pragma unroll
    for (int i = 0; i < 32; ++i) { a0[i] = 0ull; a1[i] = 0ull; }

    const float* q0p = &qs[t * QS_LD];
    const float* q1p = &qs[(t + 128) * QS_LD];

    for (int jt = 0; jt < NN / 32; ++jt) {
        __syncthreads();
        const float* kb = k + ((size_t)bh * NN + jt * 32) * DD;
        const float* vb = v + ((size_t)bh * NN + jt * 32) * DD;
#pragma unroll
        for (int it = 0; it < 4; ++it) {
            int f   = it * 128 + t;
            int row = f >> 4, dv = f & 15;
            float4 val = ((const float4*)kb)[row * 16 + dv];
            kts[(dv * 4 + 0) * KT_LD + row] = val.x;
            kts[(dv * 4 + 1) * KT_LD + row] = val.y;
            kts[(dv * 4 + 2) * KT_LD + row] = val.z;
            kts[(dv * 4 + 3) * KT_LD + row] = val.w;
        }
#pragma unroll
        for (int it = 0; it < 4; ++it) {
            int f   = it * 128 + t;
            int row = f >> 4, dv = f & 15;
            ((float4*)&vs[row * VS_LD])[dv] = ((const float4*)vb)[row * 16 + dv];
        }
        __syncthreads();

        u64t s0[16], s1[16];
#pragma unroll
        for (int j = 0; j < 16; ++j) { s0[j] = 0ull; s1[j] = 0ull; }
#pragma unroll 4
        for (int d = 0; d < 64; ++d) {
            float qa = q0p[d], qb = q1p[d];
            u64t qa2 = pk2(qa, qa);
            u64t qb2 = pk2(qb, qb);
            const ulonglong2* kr = (const ulonglong2*)&kts[d * KT_LD];
#pragma unroll
            for (int j4 = 0; j4 < 8; ++j4) {
                ulonglong2 kv = kr[j4];
                s0[2 * j4 + 0] = fma2(qa2, kv.x, s0[2 * j4 + 0]);
                s0[2 * j4 + 1] = fma2(qa2, kv.y, s0[2 * j4 + 1]);
                s1[2 * j4 + 0] = fma2(qb2, kv.x, s1[2 * j4 + 0]);
                s1[2 * j4 + 1] = fma2(qb2, kv.y, s1[2 * j4 + 1]);
            }
        }

        float t0 = -1e30f, t1 = -1e30f;
#pragma unroll
        for (int j = 0; j < 16; ++j) {
            float2 f0 = upk2(s0[j]); t0 = fmaxf(t0, fmaxf(f0.x, f0.y));
            float2 f1 = upk2(s1[j]); t1 = fmaxf(t1, fmaxf(f1.x, f1.y));
        }
        float nm0 = fmaxf(m0, t0 * NSCALE);
        float nm1 = fmaxf(m1, t1 * NSCALE);
        float c0 = __expf(m0 - nm0);
        float c1 = __expf(m1 - nm1);
        l0 *= c0; l1 *= c1;
        u64t c02 = pk2(c0, c0), c12 = pk2(c1, c1);
#pragma unroll
        for (int i = 0; i < 32; ++i) { a0[i] = mul2(c02, a0[i]); a1[i] = mul2(c12, a1[i]); }
        m0 = nm0; m1 = nm1;

#pragma unroll 2
        for (int j2 = 0; j2 < 16; ++j2) {
            float2 sv0 = upk2(s0[j2]);
            float2 sv1 = upk2(s1[j2]);
            float p00 = __expf(fmaf(sv0.x, NSCALE, -nm0));
            float p01 = __expf(fmaf(sv0.y, NSCALE, -nm0));
            float p10 = __expf(fmaf(sv1.x, NSCALE, -nm1));
            float p11 = __expf(fmaf(sv1.y, NSCALE, -nm1));
            l0 += p00 + p01;
            l1 += p10 + p11;
            u64t q00 = pk2(p00, p00), q01 = pk2(p01, p01);
            u64t q10 = pk2(p10, p10), q11 = pk2(p11, p11);
            const ulonglong2* vr0 = (const ulonglong2*)&vs[(2 * j2 + 0) * VS_LD];
            const ulonglong2* vr1 = (const ulonglong2*)&vs[(2 * j2 + 1) * VS_LD];
#pragma unroll
            for (int k4 = 0; k4 < 16; ++k4) {
                ulonglong2 vv = vr0[k4];
                a0[2 * k4 + 0] = fma2(q00, vv.x, a0[2 * k4 + 0]);
                a0[2 * k4 + 1] = fma2(q00, vv.y, a0[2 * k4 + 1]);
                a1[2 * k4 + 0] = fma2(q10, vv.x, a1[2 * k4 + 0]);
                a1[2 * k4 + 1] = fma2(q10, vv.y, a1[2 * k4 + 1]);
            }
#pragma unroll
            for (int k4 = 0; k4 < 16; ++k4) {
                ulonglong2 vv = vr1[k4];
                a0[2 * k4 + 0] = fma2(q01, vv.x, a0[2 * k4 + 0]);
                a0[2 * k4 + 1] = fma2(q01, vv.y, a0[2 * k4 + 1]);
                a1[2 * k4 + 0] = fma2(q11, vv.x, a1[2 * k4 + 0]);
                a1[2 * k4 + 1] = fma2(q11, vv.y, a1[2 * k4 + 1]);
            }
        }
    }

    const int b = bh >> 3, h = bh & 7;
    {
        const float inv = 1.f / l0;
        const int n = qtile * 256 + t;
        float* ob = o + ((size_t)(b * NN + n) * INNERR) + h * DD;
#pragma unroll
        for (int d4 = 0; d4 < 16; ++d4) {
            float2 x0 = upk2(a0[2 * d4 + 0]);
            float2 x1 = upk2(a0[2 * d4 + 1]);
            ((float4*)ob)[d4] = make_float4(x0.x * inv, x0.y * inv, x1.x * inv, x1.y * inv);
        }
    }
    {
        const float inv = 1.f / l1;
        const int n = qtile * 256 + t + 128;
        float* ob = o + ((size_t)(b * NN + n) * INNERR) + h * DD;
#pragma unroll
        for (int d4 = 0; d4 < 16; ++d4) {
            float2 x0 = upk2(a1[2 * d4 + 0]);
            float2 x1 = upk2(a1[2 * d4 + 1]);
            ((float4*)ob)[d4] = make_float4(x0.x * inv, x0.y * inv, x1.x * inv, x1.y * inv);
        }
    }
}

// ---------------------------------------------------------------------------
extern "C" void kernel_launch(void* const* d_in, const int* in_sizes, int n_in,
                              void* d_out, int out_size)
{
    const float* x  = (const float*)d_in[0];
    const float* m  = (const float*)d_in[1];
    const float* Wq = (const float*)d_in[2];
    const float* Wk = (const float*)d_in[3];
    const float* Wv = (const float*)d_in[4];
    const float* Wo = (const float*)d_in[5];
    const float* bo = (const float*)d_in[6];
    float* out = (float*)d_out;

    cudaFuncSetAttribute(attn_kernel,
                         cudaFuncAttributeMaxDynamicSharedMemorySize, ATTN_SMEM);
    cudaFuncSetAttribute(gemm_mma<0>, cudaFuncAttributeMaxDynamicSharedMemorySize, GM_SMEM);
    cudaFuncSetAttribute(gemm_mma<1>, cudaFuncAttributeMaxDynamicSharedMemorySize, GM_SMEM);
    cudaFuncSetAttribute(gemm_mma<2>, cudaFuncAttributeMaxDynamicSharedMemorySize, GM_SMEM);
    cudaFuncSetAttribute(gemm_mma<3>, cudaFuncAttributeMaxDynamicSharedMemorySize, GM_SMEM);

    // bf16 hi/lo splits of activations + transposed weights
    cvtA<0><<<8192, 256>>>(x);
    cvtA<1><<<8192, 256>>>(m);
    dim3 wg(16, 16), wb(32, 32);
    cvtW<0><<<wg, wb>>>(Wq);
    cvtW<1><<<wg, wb>>>(Wk);
    cvtW<2><<<wg, wb>>>(Wv);
    cvtW<3><<<wg, wb>>>(Wo);

    // tensor-core projections (write head-split fp32 Q/K/V)
    dim3 gg(4, 128);
    gemm_mma<0><<<gg, 256, GM_SMEM>>>(bo, nullptr);
    gemm_mma<1><<<gg, 256, GM_SMEM>>>(bo, nullptr);
    gemm_mma<2><<<gg, 256, GM_SMEM>>>(bo, nullptr);

    attn_kernel<<<dim3(NN / 256, BB * HH), 128, ATTN_SMEM>>>();

    // output projection
    cvtA<2><<<8192, 256>>>(nullptr);
    gemm_mma<3><<<gg, 256, GM_SMEM>>>(bo, out);
}

// round 9
// speedup vs baseline: 3.9499x; 2.2657x over previous
#include <cuda_runtime.h>
#include <cuda_bf16.h>
#include <cstdint>

// Problem constants
#define BB    8
#define NN    2048
#define DIMM  512
#define HH    8
#define DD    64
#define INNERR 512
#define NSCALE 0.044194173824159216f   // 512^-0.5

// ---- warp MMA helpers (sm_80+ baseline; no arch-'a' gating) ----
__device__ __forceinline__ void ldsm4(uint32_t* r, uint32_t addr) {
    asm volatile("ldmatrix.sync.aligned.m8n8.x4.shared.b16 {%0,%1,%2,%3}, [%4];"
                 : "=r"(r[0]), "=r"(r[1]), "=r"(r[2]), "=r"(r[3]) : "r"(addr));
}
__device__ __forceinline__ void ldsm4t(uint32_t* r, uint32_t addr) {
    asm volatile("ldmatrix.sync.aligned.m8n8.x4.trans.shared.b16 {%0,%1,%2,%3}, [%4];"
                 : "=r"(r[0]), "=r"(r[1]), "=r"(r[2]), "=r"(r[3]) : "r"(addr));
}
__device__ __forceinline__ void mma16816(float* c, const uint32_t* a, const uint32_t* b) {
    asm volatile("mma.sync.aligned.m16n8k16.row.col.f32.bf16.bf16.f32 "
                 "{%0,%1,%2,%3}, {%4,%5,%6,%7}, {%8,%9}, {%0,%1,%2,%3};"
                 : "+f"(c[0]), "+f"(c[1]), "+f"(c[2]), "+f"(c[3])
                 : "r"(a[0]), "r"(a[1]), "r"(a[2]), "r"(a[3]), "r"(b[0]), "r"(b[1]));
}
__device__ __forceinline__ uint32_t smem_to_u32(const void* p) {
    uint32_t a;
    asm("{ .reg .u64 t; cvta.to.shared.u64 t, %1; cvt.u32.u64 %0, t; }"
        : "=r"(a) : "l"(p));
    return a;
}
#define SWZ(off) ((off) ^ (((off) >> 3) & 0x70))

__device__ __forceinline__ uint32_t bf2pack(float lo, float hi) {
    __nv_bfloat162 t = __floats2bfloat162_rn(lo, hi);   // x=lo (low 16b), y=hi
    return *reinterpret_cast<uint32_t*>(&t);
}

// =========================== scratch (device globals only) =================
#define ACNT ((size_t)16384 * 512)
__device__ unsigned short g_xh[ACNT], g_xl[ACNT];   // x bf16 hi/lo
__device__ unsigned short g_mh[ACNT], g_ml[ACNT];   // m bf16 hi/lo
__device__ unsigned short g_oh[ACNT], g_ol[ACNT];   // attention out hi/lo [b,n,(h d)]
#define QKV ((size_t)BB * HH * NN * DD)
__device__ unsigned short g_qh[QKV], g_ql[QKV];     // Q*scale hi/lo [b,h,n,d]
__device__ unsigned short g_kh[QKV], g_kl[QKV];     // K hi/lo
__device__ unsigned short g_vh[QKV], g_vl[QKV];     // V hi/lo
#define WCNT ((size_t)512 * 512)
__device__ unsigned short g_wqh[WCNT], g_wql[WCNT];
__device__ unsigned short g_wkh[WCNT], g_wkl[WCNT];
__device__ unsigned short g_wvh[WCNT], g_wvl[WCNT];
__device__ unsigned short g_woh[WCNT], g_wol[WCNT];

__device__ __forceinline__ void bf16split(float v, unsigned short& h, unsigned short& l) {
    __nv_bfloat16 bh = __float2bfloat16(v);
    float r = v - __bfloat162float(bh);
    __nv_bfloat16 bl = __float2bfloat16(r);
    h = __bfloat16_as_ushort(bh);
    l = __bfloat16_as_ushort(bl);
}

// ---------------------------------------------------------------------------
// cvtA<SEL>: row-major fp32 [16384,512] -> bf16 hi/lo. 0: x, 1: m.
// ---------------------------------------------------------------------------
template<int SEL>
__global__ __launch_bounds__(256)
void cvtA(const float* __restrict__ src)
{
    unsigned short* h = (SEL == 0) ? g_xh : g_mh;
    unsigned short* l = (SEL == 0) ? g_xl : g_ml;
    size_t i4 = (size_t)blockIdx.x * 256 + threadIdx.x;
    float4 v = ((const float4*)src)[i4];
    ushort4 hv, lv;
    bf16split(v.x, hv.x, lv.x);
    bf16split(v.y, hv.y, lv.y);
    bf16split(v.z, hv.z, lv.z);
    bf16split(v.w, hv.w, lv.w);
    ((ushort4*)h)[i4] = hv;
    ((ushort4*)l)[i4] = lv;
}

// ---------------------------------------------------------------------------
// cvtW<SEL>: W[512 k,512 n] fp32 -> transposed bf16 hi/lo Wt[n][k].
// ---------------------------------------------------------------------------
template<int SEL>
__global__ __launch_bounds__(1024)
void cvtW(const float* __restrict__ W)
{
    unsigned short* h = (SEL == 0) ? g_wqh : (SEL == 1) ? g_wkh : (SEL == 2) ? g_wvh : g_woh;
    unsigned short* l = (SEL == 0) ? g_wql : (SEL == 1) ? g_wkl : (SEL == 2) ? g_wvl : g_wol;
    __shared__ float tile[32][33];
    int k = blockIdx.y * 32 + threadIdx.y;
    int n = blockIdx.x * 32 + threadIdx.x;
    tile[threadIdx.y][threadIdx.x] = W[(size_t)k * 512 + n];
    __syncthreads();
    int nn = blockIdx.x * 32 + threadIdx.y;
    int kk = blockIdx.y * 32 + threadIdx.x;
    float v = tile[threadIdx.x][threadIdx.y];
    unsigned short hv, lv;
    bf16split(v, hv, lv);
    h[(size_t)nn * 512 + kk] = hv;
    l[(size_t)nn * 512 + kk] = lv;
}

// ---------------------------------------------------------------------------
// HMMA GEMM: C[16384,512] = A @ W, bf16 3-split. Block 128x128, 8 warps.
// DST 0: Q (scale baked, hi/lo)  1: K (hi/lo)  2: V (hi/lo)
// DST 3: out = g_oh/g_ol @ Wo + bias (fp32 out)
// ---------------------------------------------------------------------------
#define SA_H 0
#define SA_L 16384
#define SB_H 32768
#define SB_L 49152
#define GM_SMEM 65536

template<int DST>
__global__ __launch_bounds__(256)
void gemm_mma(const float* __restrict__ bias, float* __restrict__ Cout)
{
    const unsigned short* Ah = (DST == 0) ? g_xh : (DST == 3) ? g_oh : g_mh;
    const unsigned short* Al = (DST == 0) ? g_xl : (DST == 3) ? g_ol : g_ml;
    const unsigned short* Bhp = (DST == 0) ? g_wqh : (DST == 1) ? g_wkh
                               : (DST == 2) ? g_wvh : g_woh;
    const unsigned short* Blp = (DST == 0) ? g_wql : (DST == 1) ? g_wkl
                               : (DST == 2) ? g_wvl : g_wol;

    extern __shared__ char smem[];
    const uint32_t sb = smem_to_u32(smem);

    const int tid  = threadIdx.x;
    const int wid  = tid >> 5;
    const int lane = tid & 31;
    const int warp_m = wid >> 2;
    const int warp_n = wid & 3;
    const int rowBase = blockIdx.y * 128;
    const int colBase = blockIdx.x * 128;

    float c[4][4][4];
#pragma unroll
    for (int i = 0; i < 4; ++i)
#pragma unroll
        for (int j = 0; j < 4; ++j)
#pragma unroll
            for (int e = 0; e < 4; ++e) c[i][j][e] = 0.f;

    uint32_t aAddr[4], maskA[4];
    {
        int r = lane & 15, hf = lane >> 4;
#pragma unroll
        for (int mt = 0; mt < 4; ++mt) {
            uint32_t rb = (uint32_t)((warp_m * 64 + mt * 16 + r) * 128 + hf * 16);
            maskA[mt] = (rb >> 3) & 0x70;
            aAddr[mt] = rb;
        }
    }
    uint32_t bAddr[2], maskB[2];
    {
        int rn = ((lane >> 4) << 3) + (lane & 7);
        int hf = (lane >> 3) & 1;
#pragma unroll
        for (int nt2 = 0; nt2 < 2; ++nt2) {
            uint32_t rb = (uint32_t)((warp_n * 32 + nt2 * 16 + rn) * 128 + hf * 16);
            maskB[nt2] = (rb >> 3) & 0x70;
            bAddr[nt2] = rb;
        }
    }

    for (int kc = 0; kc < 8; ++kc) {
        __syncthreads();
#pragma unroll
        for (int it = 0; it < 4; ++it) {
            int unit = it * 256 + tid;
            int row = unit >> 3, seg = unit & 7;
            uint32_t off = SWZ((uint32_t)(row * 128 + seg * 16));
            size_t ga = (size_t)(rowBase + row) * 512 + kc * 64 + seg * 8;
            size_t gb = (size_t)(colBase + row) * 512 + kc * 64 + seg * 8;
            *(uint4*)(smem + SA_H + off) = *(const uint4*)(Ah + ga);
            *(uint4*)(smem + SA_L + off) = *(const uint4*)(Al + ga);
            *(uint4*)(smem + SB_H + off) = *(const uint4*)(Bhp + gb);
            *(uint4*)(smem + SB_L + off) = *(const uint4*)(Blp + gb);
        }
        __syncthreads();

#pragma unroll
        for (int ks = 0; ks < 4; ++ks) {
            uint32_t ah[4][4], al[4][4], bh[4][2], bl[4][2];
#pragma unroll
            for (int mt = 0; mt < 4; ++mt) {
                uint32_t o = ((aAddr[mt] + ks * 32) ^ maskA[mt]);
                ldsm4(ah[mt], sb + SA_H + o);
                ldsm4(al[mt], sb + SA_L + o);
            }
#pragma unroll
            for (int nt2 = 0; nt2 < 2; ++nt2) {
                uint32_t o = ((bAddr[nt2] + ks * 32) ^ maskB[nt2]);
                uint32_t t4[4];
                ldsm4(t4, sb + SB_H + o);
                bh[2 * nt2][0] = t4[0]; bh[2 * nt2][1] = t4[1];
                bh[2 * nt2 + 1][0] = t4[2]; bh[2 * nt2 + 1][1] = t4[3];
                ldsm4(t4, sb + SB_L + o);
                bl[2 * nt2][0] = t4[0]; bl[2 * nt2][1] = t4[1];
                bl[2 * nt2 + 1][0] = t4[2]; bl[2 * nt2 + 1][1] = t4[3];
            }
#pragma unroll
            for (int mt = 0; mt < 4; ++mt)
#pragma unroll
                for (int nt = 0; nt < 4; ++nt) {
                    mma16816(c[mt][nt], ah[mt], bh[nt]);
                    mma16816(c[mt][nt], ah[mt], bl[nt]);
                    mma16816(c[mt][nt], al[mt], bh[nt]);
                }
        }
    }

    const int r0 = (lane >> 2);
    const int c2 = 2 * (lane & 3);
#pragma unroll
    for (int mt = 0; mt < 4; ++mt) {
#pragma unroll
        for (int nt = 0; nt < 4; ++nt) {
            int row = rowBase + warp_m * 64 + mt * 16 + r0;
            int col = colBase + warp_n * 32 + nt * 8 + c2;
            if (DST < 3) {
                const float s = (DST == 0) ? NSCALE : 1.f;
                const int h = col >> 6, d0 = col & 63;
#pragma unroll
                for (int half = 0; half < 2; ++half) {
                    const int rw = row + half * 8;
                    const int b = rw >> 11, n = rw & 2047;
                    float v0 = c[mt][nt][2 * half + 0] * s;
                    float v1 = c[mt][nt][2 * half + 1] * s;
                    uint32_t ph = bf2pack(v0, v1);
                    float h0 = __uint_as_float(ph << 16);
                    float h1 = __uint_as_float(ph & 0xffff0000u);
                    uint32_t pl = bf2pack(v0 - h0, v1 - h1);
                    size_t idx = (((size_t)(b * HH + h) * NN + n) * DD + d0) >> 1;
                    if (DST == 0) {
                        ((uint32_t*)g_qh)[idx] = ph;
                        ((uint32_t*)g_ql)[idx] = pl;
                    } else if (DST == 1) {
                        ((uint32_t*)g_kh)[idx] = ph;
                        ((uint32_t*)g_kl)[idx] = pl;
                    } else {
                        ((uint32_t*)g_vh)[idx] = ph;
                        ((uint32_t*)g_vl)[idx] = pl;
                    }
                }
            } else {
                float2 bv = *(const float2*)&bias[col];
                float* p0 = Cout + (size_t)row * 512 + col;
                *(float2*)p0 = make_float2(c[mt][nt][0] + bv.x, c[mt][nt][1] + bv.y);
                float* p1 = Cout + (size_t)(row + 8) * 512 + col;
                *(float2*)p1 = make_float2(c[mt][nt][2] + bv.x, c[mt][nt][3] + bv.y);
            }
        }
    }
}

// ---------------------------------------------------------------------------
// Flash attention on mma.sync: BM=128 (8 warps x 16 rows), KV tiles of 64.
// S = Qs*K^T via 3-split; P and V ALSO hi/lo split: O += Ph Vh + Pl Vh + Ph Vl.
// grid = (16, B*H), 256 threads. Writes bf16 hi/lo O.
// smem: Qh 16K | Ql 16K | Kh 8K | Kl 8K | Vh 8K | Vl 8K = 65536 B
// ---------------------------------------------------------------------------
#define AT_QH 0
#define AT_QL 16384
#define AT_KH 32768
#define AT_KL 40960
#define AT_VT 49152
#define AT_VL 57344
#define AT_SMEM 65536

__global__ __launch_bounds__(256)
void attn_mma()
{
    extern __shared__ char smem[];
    const uint32_t sb = smem_to_u32(smem);
    const int tid = threadIdx.x, wid = tid >> 5, lane = tid & 31;
    const int bh = blockIdx.y, qtile = blockIdx.x;

    // stage Q hi/lo (128x64 bf16) into swizzled smem
    const size_t qoff = ((size_t)bh * NN + qtile * 128) * DD;
#pragma unroll
    for (int i = 0; i < 4; ++i) {
        int unit = i * 256 + tid;           // 1024 units
        int row = unit >> 3, seg = unit & 7;
        uint32_t off = (uint32_t)(row * 128 + ((seg * 16) ^ ((row & 7) << 4)));
        *(uint4*)(smem + AT_QH + off) = *(const uint4*)(g_qh + qoff + row * 64 + seg * 8);
        *(uint4*)(smem + AT_QL + off) = *(const uint4*)(g_ql + qoff + row * 64 + seg * 8);
    }
    __syncthreads();

    // per-warp Q A-fragments: hi kept in regs; lo re-read per k-step
    uint32_t qh[4][4];
    uint32_t qlOff[4];
    {
        int r = lane & 15, hf = lane >> 4;
        int row = wid * 16 + r;
        uint32_t base = (uint32_t)(row * 128);
        uint32_t msk = (uint32_t)((row & 7) << 4);
#pragma unroll
        for (int ks = 0; ks < 4; ++ks) {
            uint32_t off = base + (uint32_t)((hf * 16 + ks * 32) ^ (int)msk);
            ldsm4(qh[ks], sb + AT_QH + off);
            qlOff[ks] = off;
        }
    }

    // K B-frag lane mapping
    const int rnk = ((lane >> 4) << 3) + (lane & 7);
    const int hfk = (lane >> 3) & 1;
    // V trans-frag lane mapping
    const int jj  = lane & 15;
    const int dd8 = ((lane >> 4) & 1) * 8;

    float m0 = -1e30f, m1 = -1e30f, l0 = 0.f, l1 = 0.f;
    float o[8][4];
#pragma unroll
    for (int t = 0; t < 8; ++t)
#pragma unroll
        for (int e = 0; e < 4; ++e) o[t][e] = 0.f;

    for (int jt = 0; jt < NN / 64; ++jt) {
        __syncthreads();
        const size_t kvoff = ((size_t)bh * NN + jt * 64) * DD;
#pragma unroll
        for (int i = 0; i < 2; ++i) {
            int unit = i * 256 + tid;        // 512 units
            int row = unit >> 3, seg = unit & 7;
            uint32_t off = (uint32_t)(row * 128 + ((seg * 16) ^ ((row & 7) << 4)));
            *(uint4*)(smem + AT_KH + off) = *(const uint4*)(g_kh + kvoff + row * 64 + seg * 8);
            *(uint4*)(smem + AT_KL + off) = *(const uint4*)(g_kl + kvoff + row * 64 + seg * 8);
            *(uint4*)(smem + AT_VT + off) = *(const uint4*)(g_vh + kvoff + row * 64 + seg * 8);
            *(uint4*)(smem + AT_VL + off) = *(const uint4*)(g_vl + kvoff + row * 64 + seg * 8);
        }
        __syncthreads();

        // ---- S = Qs K^T (3-split)
        float c[8][4];
#pragma unroll
        for (int t = 0; t < 8; ++t)
#pragma unroll
            for (int e = 0; e < 4; ++e) c[t][e] = 0.f;

#pragma unroll
        for (int ks = 0; ks < 4; ++ks) {
            uint32_t koff[4];
#pragma unroll
            for (int nt2 = 0; nt2 < 4; ++nt2) {
                int row = nt2 * 16 + rnk;
                koff[nt2] = (uint32_t)(row * 128)
                          + (uint32_t)((hfk * 16 + ks * 32) ^ ((row & 7) << 4));
            }
            uint32_t ql4[4];
            ldsm4(ql4, sb + AT_QL + qlOff[ks]);
            uint32_t kf[4][4];
#pragma unroll
            for (int nt2 = 0; nt2 < 4; ++nt2) ldsm4(kf[nt2], sb + AT_KH + koff[nt2]);
#pragma unroll
            for (int nt2 = 0; nt2 < 4; ++nt2) {
                uint32_t b0[2] = { kf[nt2][0], kf[nt2][1] };
                uint32_t b1[2] = { kf[nt2][2], kf[nt2][3] };
                mma16816(c[2 * nt2 + 0], qh[ks], b0);
                mma16816(c[2 * nt2 + 1], qh[ks], b1);
                mma16816(c[2 * nt2 + 0], ql4, b0);
                mma16816(c[2 * nt2 + 1], ql4, b1);
            }
#pragma unroll
            for (int nt2 = 0; nt2 < 4; ++nt2) ldsm4(kf[nt2], sb + AT_KL + koff[nt2]);
#pragma unroll
            for (int nt2 = 0; nt2 < 4; ++nt2) {
                uint32_t b0[2] = { kf[nt2][0], kf[nt2][1] };
                uint32_t b1[2] = { kf[nt2][2], kf[nt2][3] };
                mma16816(c[2 * nt2 + 0], qh[ks], b0);
                mma16816(c[2 * nt2 + 1], qh[ks], b1);
            }
        }

        // ---- online softmax (rows r0 = lane>>2, r0+8)
        float mx0 = -1e30f, mx1 = -1e30f;
#pragma unroll
        for (int t = 0; t < 8; ++t) {
            mx0 = fmaxf(mx0, fmaxf(c[t][0], c[t][1]));
            mx1 = fmaxf(mx1, fmaxf(c[t][2], c[t][3]));
        }
        mx0 = fmaxf(mx0, __shfl_xor_sync(0xffffffffu, mx0, 1));
        mx0 = fmaxf(mx0, __shfl_xor_sync(0xffffffffu, mx0, 2));
        mx1 = fmaxf(mx1, __shfl_xor_sync(0xffffffffu, mx1, 1));
        mx1 = fmaxf(mx1, __shfl_xor_sync(0xffffffffu, mx1, 2));

        float nm0 = fmaxf(m0, mx0), nm1 = fmaxf(m1, mx1);
        float cr0 = __expf(m0 - nm0), cr1 = __expf(m1 - nm1);
        m0 = nm0; m1 = nm1;
        l0 *= cr0; l1 *= cr1;
#pragma unroll
        for (int t = 0; t < 8; ++t) {
            o[t][0] *= cr0; o[t][1] *= cr0;
            o[t][2] *= cr1; o[t][3] *= cr1;
        }

        // ---- O += P V with P,V hi/lo split (3 terms)
#pragma unroll
        for (int ks = 0; ks < 4; ++ks) {
            uint32_t aPh[4], aPl[4];
#pragma unroll
            for (int half = 0; half < 2; ++half) {
                int t = 2 * ks + half;
                float p0 = __expf(c[t][0] - nm0);
                float p1 = __expf(c[t][1] - nm0);
                float p2 = __expf(c[t][2] - nm1);
                float p3 = __expf(c[t][3] - nm1);
                l0 += p0 + p1;
                l1 += p2 + p3;
                uint32_t h01 = bf2pack(p0, p1);
                uint32_t h23 = bf2pack(p2, p3);
                float hh0 = __uint_as_float(h01 << 16);
                float hh1 = __uint_as_float(h01 & 0xffff0000u);
                float hh2 = __uint_as_float(h23 << 16);
                float hh3 = __uint_as_float(h23 & 0xffff0000u);
                aPh[half ? 2 : 0] = h01;
                aPh[half ? 3 : 1] = h23;
                aPl[half ? 2 : 0] = bf2pack(p0 - hh0, p1 - hh1);
                aPl[half ? 3 : 1] = bf2pack(p2 - hh2, p3 - hh3);
            }
            int row = ks * 16 + jj;
            uint32_t rbase = (uint32_t)(row * 128);
            uint32_t msk = (uint32_t)((row & 7) << 4);
#pragma unroll
            for (int dt2 = 0; dt2 < 4; ++dt2) {
                uint32_t off = rbase + (uint32_t)(((dt2 * 16 + dd8) * 2) ^ (int)msk);
                uint32_t vh4[4], vl4[4];
                ldsm4t(vh4, sb + AT_VT + off);
                ldsm4t(vl4, sb + AT_VL + off);
                uint32_t bh0[2] = { vh4[0], vh4[1] };
                uint32_t bh1[2] = { vh4[2], vh4[3] };
                uint32_t bl0[2] = { vl4[0], vl4[1] };
                uint32_t bl1[2] = { vl4[2], vl4[3] };
                mma16816(o[2 * dt2 + 0], aPh, bh0);
                mma16816(o[2 * dt2 + 1], aPh, bh1);
                mma16816(o[2 * dt2 + 0], aPl, bh0);
                mma16816(o[2 * dt2 + 1], aPl, bh1);
                mma16816(o[2 * dt2 + 0], aPh, bl0);
                mma16816(o[2 * dt2 + 1], aPh, bl1);
            }
        }
    }

    // l is a per-thread partial sum over this thread's 16-of-64 j columns;
    // the o accumulators hold the FULL row sum. Reduce l across the quad.
    l0 += __shfl_xor_sync(0xffffffffu, l0, 1);
    l0 += __shfl_xor_sync(0xffffffffu, l0, 2);
    l1 += __shfl_xor_sync(0xffffffffu, l1, 1);
    l1 += __shfl_xor_sync(0xffffffffu, l1, 2);

    // ---- epilogue: write bf16 hi/lo of O at [b, n, h*64+d]
    const int b = bh >> 3, h = bh & 7;
    const int gr = wid * 16 + (lane >> 2);
    const float inv0 = 1.f / l0, inv1 = 1.f / l1;
    const int n0 = qtile * 128 + gr;
    const int colb = h * 64 + 2 * (lane & 3);
#pragma unroll
    for (int t = 0; t < 8; ++t) {
        const int d = t * 8;
        {
            float v0 = o[t][0] * inv0, v1 = o[t][1] * inv0;
            uint32_t ph = bf2pack(v0, v1);
            float h0 = __uint_as_float(ph << 16);
            float h1 = __uint_as_float(ph & 0xffff0000u);
            size_t idx = (((size_t)(b * NN + n0) * INNERR) + colb + d) >> 1;
            ((uint32_t*)g_oh)[idx] = ph;
            ((uint32_t*)g_ol)[idx] = bf2pack(v0 - h0, v1 - h1);
        }
        {
            float v0 = o[t][2] * inv1, v1 = o[t][3] * inv1;
            uint32_t ph = bf2pack(v0, v1);
            float h0 = __uint_as_float(ph << 16);
            float h1 = __uint_as_float(ph & 0xffff0000u);
            size_t idx = (((size_t)(b * NN + n0 + 8) * INNERR) + colb + d) >> 1;
            ((uint32_t*)g_oh)[idx] = ph;
            ((uint32_t*)g_ol)[idx] = bf2pack(v0 - h0, v1 - h1);
        }
    }
}

// ---------------------------------------------------------------------------
extern "C" void kernel_launch(void* const* d_in, const int* in_sizes, int n_in,
                              void* d_out, int out_size)
{
    const float* x  = (const float*)d_in[0];
    const float* m  = (const float*)d_in[1];
    const float* Wq = (const float*)d_in[2];
    const float* Wk = (const float*)d_in[3];
    const float* Wv = (const float*)d_in[4];
    const float* Wo = (const float*)d_in[5];
    const float* bo = (const float*)d_in[6];
    float* out = (float*)d_out;

    cudaFuncSetAttribute(attn_mma, cudaFuncAttributeMaxDynamicSharedMemorySize, AT_SMEM);
    cudaFuncSetAttribute(gemm_mma<0>, cudaFuncAttributeMaxDynamicSharedMemorySize, GM_SMEM);
    cudaFuncSetAttribute(gemm_mma<1>, cudaFuncAttributeMaxDynamicSharedMemorySize, GM_SMEM);
    cudaFuncSetAttribute(gemm_mma<2>, cudaFuncAttributeMaxDynamicSharedMemorySize, GM_SMEM);
    cudaFuncSetAttribute(gemm_mma<3>, cudaFuncAttributeMaxDynamicSharedMemorySize, GM_SMEM);

    // bf16 hi/lo splits of inputs + transposed weights
    cvtA<0><<<8192, 256>>>(x);
    cvtA<1><<<8192, 256>>>(m);
    dim3 wg(16, 16), wb(32, 32);
    cvtW<0><<<wg, wb>>>(Wq);
    cvtW<1><<<wg, wb>>>(Wk);
    cvtW<2><<<wg, wb>>>(Wv);
    cvtW<3><<<wg, wb>>>(Wo);

    // projections -> bf16 Q (scaled, hi/lo), K (hi/lo), V (hi/lo)
    dim3 gg(4, 128);
    gemm_mma<0><<<gg, 256, GM_SMEM>>>(bo, nullptr);
    gemm_mma<1><<<gg, 256, GM_SMEM>>>(bo, nullptr);
    gemm_mma<2><<<gg, 256, GM_SMEM>>>(bo, nullptr);

    attn_mma<<<dim3(16, BB * HH), 256, AT_SMEM>>>();

    // output projection (reads g_oh/g_ol)
    gemm_mma<3><<<gg, 256, GM_SMEM>>>(bo, out);
}

// round 10
// speedup vs baseline: 5.0948x; 1.2899x over previous
#include <cuda_runtime.h>
#include <cuda_bf16.h>
#include <cstdint>

// Problem constants
#define BB    8
#define NN    2048
#define DIMM  512
#define HH    8
#define DD    64
#define INNERR 512
#define NSCALE 0.044194173824159216f   // 512^-0.5

// ---- warp MMA helpers (sm_80+ baseline; no arch-'a' gating) ----
__device__ __forceinline__ void ldsm4(uint32_t* r, uint32_t addr) {
    asm volatile("ldmatrix.sync.aligned.m8n8.x4.shared.b16 {%0,%1,%2,%3}, [%4];"
                 : "=r"(r[0]), "=r"(r[1]), "=r"(r[2]), "=r"(r[3]) : "r"(addr));
}
__device__ __forceinline__ void ldsm4t(uint32_t* r, uint32_t addr) {
    asm volatile("ldmatrix.sync.aligned.m8n8.x4.trans.shared.b16 {%0,%1,%2,%3}, [%4];"
                 : "=r"(r[0]), "=r"(r[1]), "=r"(r[2]), "=r"(r[3]) : "r"(addr));
}
__device__ __forceinline__ void mma16816(float* c, const uint32_t* a, const uint32_t* b) {
    asm volatile("mma.sync.aligned.m16n8k16.row.col.f32.bf16.bf16.f32 "
                 "{%0,%1,%2,%3}, {%4,%5,%6,%7}, {%8,%9}, {%0,%1,%2,%3};"
                 : "+f"(c[0]), "+f"(c[1]), "+f"(c[2]), "+f"(c[3])
                 : "r"(a[0]), "r"(a[1]), "r"(a[2]), "r"(a[3]), "r"(b[0]), "r"(b[1]));
}
__device__ __forceinline__ uint32_t smem_to_u32(const void* p) {
    uint32_t a;
    asm("{ .reg .u64 t; cvta.to.shared.u64 t, %1; cvt.u32.u64 %0, t; }"
        : "=r"(a) : "l"(p));
    return a;
}
// ---- cp.async (LDGSTS) ----
__device__ __forceinline__ void cpa16(uint32_t dst, const void* src) {
    asm volatile("cp.async.cg.shared.global [%0], [%1], 16;" :: "r"(dst), "l"(src));
}
#define CP_COMMIT() asm volatile("cp.async.commit_group;" ::: "memory")
#define CP_WAIT(N)  asm volatile("cp.async.wait_group %0;" :: "n"(N) : "memory")

#define SWZ(off) ((off) ^ (((off) >> 3) & 0x70))

__device__ __forceinline__ uint32_t bf2pack(float lo, float hi) {
    __nv_bfloat162 t = __floats2bfloat162_rn(lo, hi);   // x=lo (low 16b), y=hi
    return *reinterpret_cast<uint32_t*>(&t);
}

// =========================== scratch (device globals only) =================
#define ACNT ((size_t)16384 * 512)
__device__ unsigned short g_xh[ACNT], g_xl[ACNT];   // x bf16 hi/lo
__device__ unsigned short g_mh[ACNT], g_ml[ACNT];   // m bf16 hi/lo
__device__ unsigned short g_oh[ACNT], g_ol[ACNT];   // attention out hi/lo [b,n,(h d)]
#define QKV ((size_t)BB * HH * NN * DD)
__device__ unsigned short g_qh[QKV], g_ql[QKV];     // Q*scale hi/lo [b,h,n,d]
__device__ unsigned short g_kh[QKV], g_kl[QKV];     // K hi/lo
__device__ unsigned short g_vh[QKV], g_vl[QKV];     // V hi/lo
#define WCNT ((size_t)512 * 512)
__device__ unsigned short g_wqh[WCNT], g_wql[WCNT];
__device__ unsigned short g_wkh[WCNT], g_wkl[WCNT];
__device__ unsigned short g_wvh[WCNT], g_wvl[WCNT];
__device__ unsigned short g_woh[WCNT], g_wol[WCNT];

__device__ __forceinline__ void bf16split(float v, unsigned short& h, unsigned short& l) {
    __nv_bfloat16 bh = __float2bfloat16(v);
    float r = v - __bfloat162float(bh);
    __nv_bfloat16 bl = __float2bfloat16(r);
    h = __bfloat16_as_ushort(bh);
    l = __bfloat16_as_ushort(bl);
}

// ---------------------------------------------------------------------------
// cvtA<SEL>: row-major fp32 [16384,512] -> bf16 hi/lo. 0: x, 1: m.
// ---------------------------------------------------------------------------
template<int SEL>
__global__ __launch_bounds__(256)
void cvtA(const float* __restrict__ src)
{
    unsigned short* h = (SEL == 0) ? g_xh : g_mh;
    unsigned short* l = (SEL == 0) ? g_xl : g_ml;
    size_t i4 = (size_t)blockIdx.x * 256 + threadIdx.x;
    float4 v = ((const float4*)src)[i4];
    ushort4 hv, lv;
    bf16split(v.x, hv.x, lv.x);
    bf16split(v.y, hv.y, lv.y);
    bf16split(v.z, hv.z, lv.z);
    bf16split(v.w, hv.w, lv.w);
    ((ushort4*)h)[i4] = hv;
    ((ushort4*)l)[i4] = lv;
}

// ---------------------------------------------------------------------------
// cvtW<SEL>: W[512 k,512 n] fp32 -> transposed bf16 hi/lo Wt[n][k].
// ---------------------------------------------------------------------------
template<int SEL>
__global__ __launch_bounds__(1024)
void cvtW(const float* __restrict__ W)
{
    unsigned short* h = (SEL == 0) ? g_wqh : (SEL == 1) ? g_wkh : (SEL == 2) ? g_wvh : g_woh;
    unsigned short* l = (SEL == 0) ? g_wql : (SEL == 1) ? g_wkl : (SEL == 2) ? g_wvl : g_wol;
    __shared__ float tile[32][33];
    int k = blockIdx.y * 32 + threadIdx.y;
    int n = blockIdx.x * 32 + threadIdx.x;
    tile[threadIdx.y][threadIdx.x] = W[(size_t)k * 512 + n];
    __syncthreads();
    int nn = blockIdx.x * 32 + threadIdx.y;
    int kk = blockIdx.y * 32 + threadIdx.x;
    float v = tile[threadIdx.x][threadIdx.y];
    unsigned short hv, lv;
    bf16split(v, hv, lv);
    h[(size_t)nn * 512 + kk] = hv;
    l[(size_t)nn * 512 + kk] = lv;
}

// ---------------------------------------------------------------------------
// HMMA GEMM: C[16384,512] = A @ W, bf16 3-split. Block 128x128, 8 warps.
// 2-stage cp.async double buffer over k-chunks of 64 (stage = 64KB).
// DST 0: Q (scale baked, hi/lo)  1: K (hi/lo)  2: V (hi/lo)
// DST 3: out = g_oh/g_ol @ Wo + bias (fp32 out)
// ---------------------------------------------------------------------------
#define SA_H 0
#define SA_L 16384
#define SB_H 32768
#define SB_L 49152
#define GM_STAGE 65536
#define GM_SMEM  (2 * GM_STAGE)

template<int DST>
__global__ __launch_bounds__(256)
void gemm_mma(const float* __restrict__ bias, float* __restrict__ Cout)
{
    const unsigned short* Ah = (DST == 0) ? g_xh : (DST == 3) ? g_oh : g_mh;
    const unsigned short* Al = (DST == 0) ? g_xl : (DST == 3) ? g_ol : g_ml;
    const unsigned short* Bhp = (DST == 0) ? g_wqh : (DST == 1) ? g_wkh
                               : (DST == 2) ? g_wvh : g_woh;
    const unsigned short* Blp = (DST == 0) ? g_wql : (DST == 1) ? g_wkl
                               : (DST == 2) ? g_wvl : g_wol;

    extern __shared__ char smem[];
    const uint32_t sb = smem_to_u32(smem);

    const int tid  = threadIdx.x;
    const int wid  = tid >> 5;
    const int lane = tid & 31;
    const int warp_m = wid >> 2;
    const int warp_n = wid & 3;
    const int rowBase = blockIdx.y * 128;
    const int colBase = blockIdx.x * 128;

    float c[4][4][4];
#pragma unroll
    for (int i = 0; i < 4; ++i)
#pragma unroll
        for (int j = 0; j < 4; ++j)
#pragma unroll
            for (int e = 0; e < 4; ++e) c[i][j][e] = 0.f;

    uint32_t aAddr[4], maskA[4];
    {
        int r = lane & 15, hf = lane >> 4;
#pragma unroll
        for (int mt = 0; mt < 4; ++mt) {
            uint32_t rb = (uint32_t)((warp_m * 64 + mt * 16 + r) * 128 + hf * 16);
            maskA[mt] = (rb >> 3) & 0x70;
            aAddr[mt] = rb;
        }
    }
    uint32_t bAddr[2], maskB[2];
    {
        int rn = ((lane >> 4) << 3) + (lane & 7);
        int hf = (lane >> 3) & 1;
#pragma unroll
        for (int nt2 = 0; nt2 < 2; ++nt2) {
            uint32_t rb = (uint32_t)((warp_n * 32 + nt2 * 16 + rn) * 128 + hf * 16);
            maskB[nt2] = (rb >> 3) & 0x70;
            bAddr[nt2] = rb;
        }
    }

    // stage loader: 4 planes x 128x64 bf16, via cp.async
    auto load_stage = [&](int st, int kc) {
        uint32_t base = sb + st * GM_STAGE;
#pragma unroll
        for (int it = 0; it < 4; ++it) {
            int unit = it * 256 + tid;
            int row = unit >> 3, seg = unit & 7;
            uint32_t off = SWZ((uint32_t)(row * 128 + seg * 16));
            size_t ga = (size_t)(rowBase + row) * 512 + kc * 64 + seg * 8;
            size_t gb = (size_t)(colBase + row) * 512 + kc * 64 + seg * 8;
            cpa16(base + SA_H + off, Ah + ga);
            cpa16(base + SA_L + off, Al + ga);
            cpa16(base + SB_H + off, Bhp + gb);
            cpa16(base + SB_L + off, Blp + gb);
        }
    };

    load_stage(0, 0);
    CP_COMMIT();

    for (int kc = 0; kc < 8; ++kc) {
        if (kc + 1 < 8) {
            load_stage((kc + 1) & 1, kc + 1);
            CP_COMMIT();
            CP_WAIT(1);
        } else {
            CP_WAIT(0);
        }
        __syncthreads();

        const uint32_t stb = sb + (kc & 1) * GM_STAGE;
#pragma unroll
        for (int ks = 0; ks < 4; ++ks) {
            uint32_t ah[4][4], al[4][4], bh[4][2], bl[4][2];
#pragma unroll
            for (int mt = 0; mt < 4; ++mt) {
                uint32_t o = ((aAddr[mt] + ks * 32) ^ maskA[mt]);
                ldsm4(ah[mt], stb + SA_H + o);
                ldsm4(al[mt], stb + SA_L + o);
            }
#pragma unroll
            for (int nt2 = 0; nt2 < 2; ++nt2) {
                uint32_t o = ((bAddr[nt2] + ks * 32) ^ maskB[nt2]);
                uint32_t t4[4];
                ldsm4(t4, stb + SB_H + o);
                bh[2 * nt2][0] = t4[0]; bh[2 * nt2][1] = t4[1];
                bh[2 * nt2 + 1][0] = t4[2]; bh[2 * nt2 + 1][1] = t4[3];
                ldsm4(t4, stb + SB_L + o);
                bl[2 * nt2][0] = t4[0]; bl[2 * nt2][1] = t4[1];
                bl[2 * nt2 + 1][0] = t4[2]; bl[2 * nt2 + 1][1] = t4[3];
            }
#pragma unroll
            for (int mt = 0; mt < 4; ++mt)
#pragma unroll
                for (int nt = 0; nt < 4; ++nt) {
                    mma16816(c[mt][nt], ah[mt], bh[nt]);
                    mma16816(c[mt][nt], ah[mt], bl[nt]);
                    mma16816(c[mt][nt], al[mt], bh[nt]);
                }
        }
        __syncthreads();   // all warps done with this stage before it is re-filled
    }

    const int r0 = (lane >> 2);
    const int c2 = 2 * (lane & 3);
#pragma unroll
    for (int mt = 0; mt < 4; ++mt) {
#pragma unroll
        for (int nt = 0; nt < 4; ++nt) {
            int row = rowBase + warp_m * 64 + mt * 16 + r0;
            int col = colBase + warp_n * 32 + nt * 8 + c2;
            if (DST < 3) {
                const float s = (DST == 0) ? NSCALE : 1.f;
                const int h = col >> 6, d0 = col & 63;
#pragma unroll
                for (int half = 0; half < 2; ++half) {
                    const int rw = row + half * 8;
                    const int b = rw >> 11, n = rw & 2047;
                    float v0 = c[mt][nt][2 * half + 0] * s;
                    float v1 = c[mt][nt][2 * half + 1] * s;
                    uint32_t ph = bf2pack(v0, v1);
                    float h0 = __uint_as_float(ph << 16);
                    float h1 = __uint_as_float(ph & 0xffff0000u);
                    uint32_t pl = bf2pack(v0 - h0, v1 - h1);
                    size_t idx = (((size_t)(b * HH + h) * NN + n) * DD + d0) >> 1;
                    if (DST == 0) {
                        ((uint32_t*)g_qh)[idx] = ph;
                        ((uint32_t*)g_ql)[idx] = pl;
                    } else if (DST == 1) {
                        ((uint32_t*)g_kh)[idx] = ph;
                        ((uint32_t*)g_kl)[idx] = pl;
                    } else {
                        ((uint32_t*)g_vh)[idx] = ph;
                        ((uint32_t*)g_vl)[idx] = pl;
                    }
                }
            } else {
                float2 bv = *(const float2*)&bias[col];
                float* p0 = Cout + (size_t)row * 512 + col;
                *(float2*)p0 = make_float2(c[mt][nt][0] + bv.x, c[mt][nt][1] + bv.y);
                float* p1 = Cout + (size_t)(row + 8) * 512 + col;
                *(float2*)p1 = make_float2(c[mt][nt][2] + bv.x, c[mt][nt][3] + bv.y);
            }
        }
    }
}

// ---------------------------------------------------------------------------
// Flash attention on mma.sync: BM=128 (8 warps x 16 rows), KV tiles of 64.
// 2-stage cp.async double buffer for the KV planes (stage = 32KB).
// S = Qs*K^T 3-split; PV 3-split (Ph Vh + Pl Vh + Ph Vl).
// smem: Qh 16K | Ql 16K | stage0 32K | stage1 32K = 96 KB.
// ---------------------------------------------------------------------------
#define AT_QH 0
#define AT_QL 16384
#define AT_ST0 32768
#define AT_STAGE 32768
#define KV_KH 0
#define KV_KL 8192
#define KV_VH 16384
#define KV_VL 24576
#define AT_SMEM (AT_ST0 + 2 * AT_STAGE)

__global__ __launch_bounds__(256)
void attn_mma()
{
    extern __shared__ char smem[];
    const uint32_t sb = smem_to_u32(smem);
    const int tid = threadIdx.x, wid = tid >> 5, lane = tid & 31;
    const int bh = blockIdx.y, qtile = blockIdx.x;

    const size_t bhoff = (size_t)bh * NN * DD;

    // KV stage loader via cp.async
    auto load_kv = [&](int st, int jt) {
        uint32_t base = sb + AT_ST0 + st * AT_STAGE;
        const size_t kvoff = bhoff + (size_t)jt * 64 * DD;
#pragma unroll
        for (int i = 0; i < 2; ++i) {
            int unit = i * 256 + tid;        // 512 units
            int row = unit >> 3, seg = unit & 7;
            uint32_t off = (uint32_t)(row * 128 + ((seg * 16) ^ ((row & 7) << 4)));
            size_t g = kvoff + row * 64 + seg * 8;
            cpa16(base + KV_KH + off, g_kh + g);
            cpa16(base + KV_KL + off, g_kl + g);
            cpa16(base + KV_VH + off, g_vh + g);
            cpa16(base + KV_VL + off, g_vl + g);
        }
    };

    load_kv(0, 0);
    CP_COMMIT();

    // stage Q hi/lo (128x64 bf16) into swizzled smem (plain loads, once)
    const size_t qoff = bhoff + (size_t)qtile * 128 * DD;
#pragma unroll
    for (int i = 0; i < 4; ++i) {
        int unit = i * 256 + tid;           // 1024 units
        int row = unit >> 3, seg = unit & 7;
        uint32_t off = (uint32_t)(row * 128 + ((seg * 16) ^ ((row & 7) << 4)));
        *(uint4*)(smem + AT_QH + off) = *(const uint4*)(g_qh + qoff + row * 64 + seg * 8);
        *(uint4*)(smem + AT_QL + off) = *(const uint4*)(g_ql + qoff + row * 64 + seg * 8);
    }
    __syncthreads();

    // per-warp Q A-fragments: hi kept in regs; lo re-read per k-step
    uint32_t qh[4][4];
    uint32_t qlOff[4];
    {
        int r = lane & 15, hf = lane >> 4;
        int row = wid * 16 + r;
        uint32_t base = (uint32_t)(row * 128);
        uint32_t msk = (uint32_t)((row & 7) << 4);
#pragma unroll
        for (int ks = 0; ks < 4; ++ks) {
            uint32_t off = base + (uint32_t)((hf * 16 + ks * 32) ^ (int)msk);
            ldsm4(qh[ks], sb + AT_QH + off);
            qlOff[ks] = off;
        }
    }

    // K B-frag lane mapping
    const int rnk = ((lane >> 4) << 3) + (lane & 7);
    const int hfk = (lane >> 3) & 1;
    // V trans-frag lane mapping
    const int jj  = lane & 15;
    const int dd8 = ((lane >> 4) & 1) * 8;

    float m0 = -1e30f, m1 = -1e30f, l0 = 0.f, l1 = 0.f;
    float o[8][4];
#pragma unroll
    for (int t = 0; t < 8; ++t)
#pragma unroll
        for (int e = 0; e < 4; ++e) o[t][e] = 0.f;

    for (int jt = 0; jt < NN / 64; ++jt) {
        if (jt + 1 < NN / 64) {
            load_kv((jt + 1) & 1, jt + 1);
            CP_COMMIT();
            CP_WAIT(1);
        } else {
            CP_WAIT(0);
        }
        __syncthreads();

        const uint32_t stb = sb + AT_ST0 + (jt & 1) * AT_STAGE;

        // ---- S = Qs K^T (3-split)
        float c[8][4];
#pragma unroll
        for (int t = 0; t < 8; ++t)
#pragma unroll
            for (int e = 0; e < 4; ++e) c[t][e] = 0.f;

#pragma unroll
        for (int ks = 0; ks < 4; ++ks) {
            uint32_t koff[4];
#pragma unroll
            for (int nt2 = 0; nt2 < 4; ++nt2) {
                int row = nt2 * 16 + rnk;
                koff[nt2] = (uint32_t)(row * 128)
                          + (uint32_t)((hfk * 16 + ks * 32) ^ ((row & 7) << 4));
            }
            uint32_t ql4[4];
            ldsm4(ql4, sb + AT_QL + qlOff[ks]);
            uint32_t kf[4][4];
#pragma unroll
            for (int nt2 = 0; nt2 < 4; ++nt2) ldsm4(kf[nt2], stb + KV_KH + koff[nt2]);
#pragma unroll
            for (int nt2 = 0; nt2 < 4; ++nt2) {
                uint32_t b0[2] = { kf[nt2][0], kf[nt2][1] };
                uint32_t b1[2] = { kf[nt2][2], kf[nt2][3] };
                mma16816(c[2 * nt2 + 0], qh[ks], b0);
                mma16816(c[2 * nt2 + 1], qh[ks], b1);
                mma16816(c[2 * nt2 + 0], ql4, b0);
                mma16816(c[2 * nt2 + 1], ql4, b1);
            }
#pragma unroll
            for (int nt2 = 0; nt2 < 4; ++nt2) ldsm4(kf[nt2], stb + KV_KL + koff[nt2]);
#pragma unroll
            for (int nt2 = 0; nt2 < 4; ++nt2) {
                uint32_t b0[2] = { kf[nt2][0], kf[nt2][1] };
                uint32_t b1[2] = { kf[nt2][2], kf[nt2][3] };
                mma16816(c[2 * nt2 + 0], qh[ks], b0);
                mma16816(c[2 * nt2 + 1], qh[ks], b1);
            }
        }

        // ---- online softmax (rows r0 = lane>>2, r0+8)
        float mx0 = -1e30f, mx1 = -1e30f;
#pragma unroll
        for (int t = 0; t < 8; ++t) {
            mx0 = fmaxf(mx0, fmaxf(c[t][0], c[t][1]));
            mx1 = fmaxf(mx1, fmaxf(c[t][2], c[t][3]));
        }
        mx0 = fmaxf(mx0, __shfl_xor_sync(0xffffffffu, mx0, 1));
        mx0 = fmaxf(mx0, __shfl_xor_sync(0xffffffffu, mx0, 2));
        mx1 = fmaxf(mx1, __shfl_xor_sync(0xffffffffu, mx1, 1));
        mx1 = fmaxf(mx1, __shfl_xor_sync(0xffffffffu, mx1, 2));

        float nm0 = fmaxf(m0, mx0), nm1 = fmaxf(m1, mx1);
        float cr0 = __expf(m0 - nm0), cr1 = __expf(m1 - nm1);
        m0 = nm0; m1 = nm1;
        l0 *= cr0; l1 *= cr1;
#pragma unroll
        for (int t = 0; t < 8; ++t) {
            o[t][0] *= cr0; o[t][1] *= cr0;
            o[t][2] *= cr1; o[t][3] *= cr1;
        }

        // ---- O += P V with P,V hi/lo split (3 terms)
#pragma unroll
        for (int ks = 0; ks < 4; ++ks) {
            uint32_t aPh[4], aPl[4];
#pragma unroll
            for (int half = 0; half < 2; ++half) {
                int t = 2 * ks + half;
                float p0 = __expf(c[t][0] - nm0);
                float p1 = __expf(c[t][1] - nm0);
                float p2 = __expf(c[t][2] - nm1);
                float p3 = __expf(c[t][3] - nm1);
                l0 += p0 + p1;
                l1 += p2 + p3;
                uint32_t h01 = bf2pack(p0, p1);
                uint32_t h23 = bf2pack(p2, p3);
                float hh0 = __uint_as_float(h01 << 16);
                float hh1 = __uint_as_float(h01 & 0xffff0000u);
                float hh2 = __uint_as_float(h23 << 16);
                float hh3 = __uint_as_float(h23 & 0xffff0000u);
                aPh[half ? 2 : 0] = h01;
                aPh[half ? 3 : 1] = h23;
                aPl[half ? 2 : 0] = bf2pack(p0 - hh0, p1 - hh1);
                aPl[half ? 3 : 1] = bf2pack(p2 - hh2, p3 - hh3);
            }
            int row = ks * 16 + jj;
            uint32_t rbase = (uint32_t)(row * 128);
            uint32_t msk = (uint32_t)((row & 7) << 4);
#pragma unroll
            for (int dt2 = 0; dt2 < 4; ++dt2) {
                uint32_t off = rbase + (uint32_t)(((dt2 * 16 + dd8) * 2) ^ (int)msk);
                uint32_t vh4[4], vl4[4];
                ldsm4t(vh4, stb + KV_VH + off);
                ldsm4t(vl4, stb + KV_VL + off);
                uint32_t bh0[2] = { vh4[0], vh4[1] };
                uint32_t bh1[2] = { vh4[2], vh4[3] };
                uint32_t bl0[2] = { vl4[0], vl4[1] };
                uint32_t bl1[2] = { vl4[2], vl4[3] };
                mma16816(o[2 * dt2 + 0], aPh, bh0);
                mma16816(o[2 * dt2 + 1], aPh, bh1);
                mma16816(o[2 * dt2 + 0], aPl, bh0);
                mma16816(o[2 * dt2 + 1], aPl, bh1);
                mma16816(o[2 * dt2 + 0], aPh, bl0);
                mma16816(o[2 * dt2 + 1], aPh, bl1);
            }
        }
        __syncthreads();   // all warps done with this stage before it is re-filled
    }

    // l is a per-thread partial over 16-of-64 j cols; o holds the full row sum.
    l0 += __shfl_xor_sync(0xffffffffu, l0, 1);
    l0 += __shfl_xor_sync(0xffffffffu, l0, 2);
    l1 += __shfl_xor_sync(0xffffffffu, l1, 1);
    l1 += __shfl_xor_sync(0xffffffffu, l1, 2);

    // ---- epilogue: write bf16 hi/lo of O at [b, n, h*64+d]
    const int b = bh >> 3, h = bh & 7;
    const int gr = wid * 16 + (lane >> 2);
    const float inv0 = 1.f / l0, inv1 = 1.f / l1;
    const int n0 = qtile * 128 + gr;
    const int colb = h * 64 + 2 * (lane & 3);
#pragma unroll
    for (int t = 0; t < 8; ++t) {
        const int d = t * 8;
        {
            float v0 = o[t][0] * inv0, v1 = o[t][1] * inv0;
            uint32_t ph = bf2pack(v0, v1);
            float h0 = __uint_as_float(ph << 16);
            float h1 = __uint_as_float(ph & 0xffff0000u);
            size_t idx = (((size_t)(b * NN + n0) * INNERR) + colb + d) >> 1;
            ((uint32_t*)g_oh)[idx] = ph;
            ((uint32_t*)g_ol)[idx] = bf2pack(v0 - h0, v1 - h1);
        }
        {
            float v0 = o[t][2] * inv1, v1 = o[t][3] * inv1;
            uint32_t ph = bf2pack(v0, v1);
            float h0 = __uint_as_float(ph << 16);
            float h1 = __uint_as_float(ph & 0xffff0000u);
            size_t idx = (((size_t)(b * NN + n0 + 8) * INNERR) + colb + d) >> 1;
            ((uint32_t*)g_oh)[idx] = ph;
            ((uint32_t*)g_ol)[idx] = bf2pack(v0 - h0, v1 - h1);
        }
    }
}

// ---------------------------------------------------------------------------
extern "C" void kernel_launch(void* const* d_in, const int* in_sizes, int n_in,
                              void* d_out, int out_size)
{
    const float* x  = (const float*)d_in[0];
    const float* m  = (const float*)d_in[1];
    const float* Wq = (const float*)d_in[2];
    const float* Wk = (const float*)d_in[3];
    const float* Wv = (const float*)d_in[4];
    const float* Wo = (const float*)d_in[5];
    const float* bo = (const float*)d_in[6];
    float* out = (float*)d_out;

    cudaFuncSetAttribute(attn_mma, cudaFuncAttributeMaxDynamicSharedMemorySize, AT_SMEM);
    cudaFuncSetAttribute(gemm_mma<0>, cudaFuncAttributeMaxDynamicSharedMemorySize, GM_SMEM);
    cudaFuncSetAttribute(gemm_mma<1>, cudaFuncAttributeMaxDynamicSharedMemorySize, GM_SMEM);
    cudaFuncSetAttribute(gemm_mma<2>, cudaFuncAttributeMaxDynamicSharedMemorySize, GM_SMEM);
    cudaFuncSetAttribute(gemm_mma<3>, cudaFuncAttributeMaxDynamicSharedMemorySize, GM_SMEM);

    // bf16 hi/lo splits of inputs + transposed weights
    cvtA<0><<<8192, 256>>>(x);
    cvtA<1><<<8192, 256>>>(m);
    dim3 wg(16, 16), wb(32, 32);
    cvtW<0><<<wg, wb>>>(Wq);
    cvtW<1><<<wg, wb>>>(Wk);
    cvtW<2><<<wg, wb>>>(Wv);
    cvtW<3><<<wg, wb>>>(Wo);

    // projections -> bf16 Q (scaled, hi/lo), K (hi/lo), V (hi/lo)
    dim3 gg(4, 128);
    gemm_mma<0><<<gg, 256, GM_SMEM>>>(bo, nullptr);
    gemm_mma<1><<<gg, 256, GM_SMEM>>>(bo, nullptr);
    gemm_mma<2><<<gg, 256, GM_SMEM>>>(bo, nullptr);

    attn_mma<<<dim3(16, BB * HH), 256, AT_SMEM>>>();

    // output projection (reads g_oh/g_ol)
    gemm_mma<3><<<gg, 256, GM_SMEM>>>(bo, out);
}

// round 11
// speedup vs baseline: 7.2711x; 1.4272x over previous
#include <cuda_runtime.h>
#include <cuda_bf16.h>
#include <cuda_fp16.h>
#include <cstdint>

// Problem constants
#define BB    8
#define NN    2048
#define DIMM  512
#define HH    8
#define DD    64
#define INNERR 512
#define NSCALE 0.044194173824159216f   // 512^-0.5

// ---- warp MMA helpers (sm_80+ baseline; no arch-'a' gating) ----
__device__ __forceinline__ void ldsm4(uint32_t* r, uint32_t addr) {
    asm volatile("ldmatrix.sync.aligned.m8n8.x4.shared.b16 {%0,%1,%2,%3}, [%4];"
                 : "=r"(r[0]), "=r"(r[1]), "=r"(r[2]), "=r"(r[3]) : "r"(addr));
}
__device__ __forceinline__ void ldsm4t(uint32_t* r, uint32_t addr) {
    asm volatile("ldmatrix.sync.aligned.m8n8.x4.trans.shared.b16 {%0,%1,%2,%3}, [%4];"
                 : "=r"(r[0]), "=r"(r[1]), "=r"(r[2]), "=r"(r[3]) : "r"(addr));
}
__device__ __forceinline__ void mma16816(float* c, const uint32_t* a, const uint32_t* b) {
    asm volatile("mma.sync.aligned.m16n8k16.row.col.f32.bf16.bf16.f32 "
                 "{%0,%1,%2,%3}, {%4,%5,%6,%7}, {%8,%9}, {%0,%1,%2,%3};"
                 : "+f"(c[0]), "+f"(c[1]), "+f"(c[2]), "+f"(c[3])
                 : "r"(a[0]), "r"(a[1]), "r"(a[2]), "r"(a[3]), "r"(b[0]), "r"(b[1]));
}
__device__ __forceinline__ void mma16816h(float* c, const uint32_t* a, const uint32_t* b) {
    asm volatile("mma.sync.aligned.m16n8k16.row.col.f32.f16.f16.f32 "
                 "{%0,%1,%2,%3}, {%4,%5,%6,%7}, {%8,%9}, {%0,%1,%2,%3};"
                 : "+f"(c[0]), "+f"(c[1]), "+f"(c[2]), "+f"(c[3])
                 : "r"(a[0]), "r"(a[1]), "r"(a[2]), "r"(a[3]), "r"(b[0]), "r"(b[1]));
}
__device__ __forceinline__ uint32_t smem_to_u32(const void* p) {
    uint32_t a;
    asm("{ .reg .u64 t; cvta.to.shared.u64 t, %1; cvt.u32.u64 %0, t; }"
        : "=r"(a) : "l"(p));
    return a;
}
// ---- cp.async (LDGSTS) ----
__device__ __forceinline__ void cpa16(uint32_t dst, const void* src) {
    asm volatile("cp.async.cg.shared.global [%0], [%1], 16;" :: "r"(dst), "l"(src));
}
#define CP_COMMIT() asm volatile("cp.async.commit_group;" ::: "memory")
#define CP_WAIT(N)  asm volatile("cp.async.wait_group %0;" :: "n"(N) : "memory")

#define SWZ(off) ((off) ^ (((off) >> 3) & 0x70))

__device__ __forceinline__ uint32_t bf2pack(float lo, float hi) {
    __nv_bfloat162 t = __floats2bfloat162_rn(lo, hi);   // x=lo (low 16b), y=hi
    return *reinterpret_cast<uint32_t*>(&t);
}
__device__ __forceinline__ uint32_t hf2pack(float lo, float hi) {
    __half2 t = __floats2half2_rn(lo, hi);
    return *reinterpret_cast<uint32_t*>(&t);
}

// =========================== scratch (device globals only) =================
#define ACNT ((size_t)16384 * 512)
__device__ unsigned short g_xh[ACNT], g_xl[ACNT];   // x bf16 hi/lo
__device__ unsigned short g_mh[ACNT], g_ml[ACNT];   // m bf16 hi/lo
__device__ unsigned short g_oh[ACNT], g_ol[ACNT];   // attention out hi/lo [b,n,(h d)]
#define QKV ((size_t)BB * HH * NN * DD)
__device__ unsigned short g_qf[QKV];                // Q*scale fp16 [b,h,n,d]
__device__ unsigned short g_kf[QKV];                // K fp16
__device__ unsigned short g_vf[QKV];                // V fp16
#define WCNT ((size_t)512 * 512)
__device__ unsigned short g_wqh[WCNT], g_wql[WCNT];
__device__ unsigned short g_wkh[WCNT], g_wkl[WCNT];
__device__ unsigned short g_wvh[WCNT], g_wvl[WCNT];
__device__ unsigned short g_woh[WCNT], g_wol[WCNT];

__device__ __forceinline__ void bf16split(float v, unsigned short& h, unsigned short& l) {
    __nv_bfloat16 bh = __float2bfloat16(v);
    float r = v - __bfloat162float(bh);
    __nv_bfloat16 bl = __float2bfloat16(r);
    h = __bfloat16_as_ushort(bh);
    l = __bfloat16_as_ushort(bl);
}

// ---------------------------------------------------------------------------
// cvtA<SEL>: row-major fp32 [16384,512] -> bf16 hi/lo. 0: x, 1: m.
// ---------------------------------------------------------------------------
template<int SEL>
__global__ __launch_bounds__(256)
void cvtA(const float* __restrict__ src)
{
    unsigned short* h = (SEL == 0) ? g_xh : g_mh;
    unsigned short* l = (SEL == 0) ? g_xl : g_ml;
    size_t i4 = (size_t)blockIdx.x * 256 + threadIdx.x;
    float4 v = ((const float4*)src)[i4];
    ushort4 hv, lv;
    bf16split(v.x, hv.x, lv.x);
    bf16split(v.y, hv.y, lv.y);
    bf16split(v.z, hv.z, lv.z);
    bf16split(v.w, hv.w, lv.w);
    ((ushort4*)h)[i4] = hv;
    ((ushort4*)l)[i4] = lv;
}

// ---------------------------------------------------------------------------
// cvtW<SEL>: W[512 k,512 n] fp32 -> transposed bf16 hi/lo Wt[n][k].
// ---------------------------------------------------------------------------
template<int SEL>
__global__ __launch_bounds__(1024)
void cvtW(const float* __restrict__ W)
{
    unsigned short* h = (SEL == 0) ? g_wqh : (SEL == 1) ? g_wkh : (SEL == 2) ? g_wvh : g_woh;
    unsigned short* l = (SEL == 0) ? g_wql : (SEL == 1) ? g_wkl : (SEL == 2) ? g_wvl : g_wol;
    __shared__ float tile[32][33];
    int k = blockIdx.y * 32 + threadIdx.y;
    int n = blockIdx.x * 32 + threadIdx.x;
    tile[threadIdx.y][threadIdx.x] = W[(size_t)k * 512 + n];
    __syncthreads();
    int nn = blockIdx.x * 32 + threadIdx.y;
    int kk = blockIdx.y * 32 + threadIdx.x;
    float v = tile[threadIdx.x][threadIdx.y];
    unsigned short hv, lv;
    bf16split(v, hv, lv);
    h[(size_t)nn * 512 + kk] = hv;
    l[(size_t)nn * 512 + kk] = lv;
}

// ---------------------------------------------------------------------------
// HMMA GEMM: C[16384,512] = A @ W, bf16 3-split internals. Block 128x128.
// 2-stage cp.async double buffer over k-chunks of 64 (stage = 64KB).
// DST 0: Q*scale -> fp16   1: K -> fp16   2: V -> fp16
// DST 3: out = g_oh/g_ol @ Wo + bias (fp32 out)
// ---------------------------------------------------------------------------
#define SA_H 0
#define SA_L 16384
#define SB_H 32768
#define SB_L 49152
#define GM_STAGE 65536
#define GM_SMEM  (2 * GM_STAGE)

template<int DST>
__global__ __launch_bounds__(256)
void gemm_mma(const float* __restrict__ bias, float* __restrict__ Cout)
{
    const unsigned short* Ah = (DST == 0) ? g_xh : (DST == 3) ? g_oh : g_mh;
    const unsigned short* Al = (DST == 0) ? g_xl : (DST == 3) ? g_ol : g_ml;
    const unsigned short* Bhp = (DST == 0) ? g_wqh : (DST == 1) ? g_wkh
                               : (DST == 2) ? g_wvh : g_woh;
    const unsigned short* Blp = (DST == 0) ? g_wql : (DST == 1) ? g_wkl
                               : (DST == 2) ? g_wvl : g_wol;

    extern __shared__ char smem[];
    const uint32_t sb = smem_to_u32(smem);

    const int tid  = threadIdx.x;
    const int wid  = tid >> 5;
    const int lane = tid & 31;
    const int warp_m = wid >> 2;
    const int warp_n = wid & 3;
    const int rowBase = blockIdx.y * 128;
    const int colBase = blockIdx.x * 128;

    float c[4][4][4];
#pragma unroll
    for (int i = 0; i < 4; ++i)
#pragma unroll
        for (int j = 0; j < 4; ++j)
#pragma unroll
            for (int e = 0; e < 4; ++e) c[i][j][e] = 0.f;

    uint32_t aAddr[4], maskA[4];
    {
        int r = lane & 15, hf = lane >> 4;
#pragma unroll
        for (int mt = 0; mt < 4; ++mt) {
            uint32_t rb = (uint32_t)((warp_m * 64 + mt * 16 + r) * 128 + hf * 16);
            maskA[mt] = (rb >> 3) & 0x70;
            aAddr[mt] = rb;
        }
    }
    uint32_t bAddr[2], maskB[2];
    {
        int rn = ((lane >> 4) << 3) + (lane & 7);
        int hf = (lane >> 3) & 1;
#pragma unroll
        for (int nt2 = 0; nt2 < 2; ++nt2) {
            uint32_t rb = (uint32_t)((warp_n * 32 + nt2 * 16 + rn) * 128 + hf * 16);
            maskB[nt2] = (rb >> 3) & 0x70;
            bAddr[nt2] = rb;
        }
    }

    auto load_stage = [&](int st, int kc) {
        uint32_t base = sb + st * GM_STAGE;
#pragma unroll
        for (int it = 0; it < 4; ++it) {
            int unit = it * 256 + tid;
            int row = unit >> 3, seg = unit & 7;
            uint32_t off = SWZ((uint32_t)(row * 128 + seg * 16));
            size_t ga = (size_t)(rowBase + row) * 512 + kc * 64 + seg * 8;
            size_t gb = (size_t)(colBase + row) * 512 + kc * 64 + seg * 8;
            cpa16(base + SA_H + off, Ah + ga);
            cpa16(base + SA_L + off, Al + ga);
            cpa16(base + SB_H + off, Bhp + gb);
            cpa16(base + SB_L + off, Blp + gb);
        }
    };

    load_stage(0, 0);
    CP_COMMIT();

    for (int kc = 0; kc < 8; ++kc) {
        if (kc + 1 < 8) {
            load_stage((kc + 1) & 1, kc + 1);
            CP_COMMIT();
            CP_WAIT(1);
        } else {
            CP_WAIT(0);
        }
        __syncthreads();

        const uint32_t stb = sb + (kc & 1) * GM_STAGE;
#pragma unroll
        for (int ks = 0; ks < 4; ++ks) {
            uint32_t ah[4][4], al[4][4], bh[4][2], bl[4][2];
#pragma unroll
            for (int mt = 0; mt < 4; ++mt) {
                uint32_t o = ((aAddr[mt] + ks * 32) ^ maskA[mt]);
                ldsm4(ah[mt], stb + SA_H + o);
                ldsm4(al[mt], stb + SA_L + o);
            }
#pragma unroll
            for (int nt2 = 0; nt2 < 2; ++nt2) {
                uint32_t o = ((bAddr[nt2] + ks * 32) ^ maskB[nt2]);
                uint32_t t4[4];
                ldsm4(t4, stb + SB_H + o);
                bh[2 * nt2][0] = t4[0]; bh[2 * nt2][1] = t4[1];
                bh[2 * nt2 + 1][0] = t4[2]; bh[2 * nt2 + 1][1] = t4[3];
                ldsm4(t4, stb + SB_L + o);
                bl[2 * nt2][0] = t4[0]; bl[2 * nt2][1] = t4[1];
                bl[2 * nt2 + 1][0] = t4[2]; bl[2 * nt2 + 1][1] = t4[3];
            }
#pragma unroll
            for (int mt = 0; mt < 4; ++mt)
#pragma unroll
                for (int nt = 0; nt < 4; ++nt) {
                    mma16816(c[mt][nt], ah[mt], bh[nt]);
                    mma16816(c[mt][nt], ah[mt], bl[nt]);
                    mma16816(c[mt][nt], al[mt], bh[nt]);
                }
        }
        __syncthreads();
    }

    const int r0 = (lane >> 2);
    const int c2 = 2 * (lane & 3);
#pragma unroll
    for (int mt = 0; mt < 4; ++mt) {
#pragma unroll
        for (int nt = 0; nt < 4; ++nt) {
            int row = rowBase + warp_m * 64 + mt * 16 + r0;
            int col = colBase + warp_n * 32 + nt * 8 + c2;
            if (DST < 3) {
                const float s = (DST == 0) ? NSCALE : 1.f;
                const int h = col >> 6, d0 = col & 63;
                unsigned short* Cf = (DST == 0) ? g_qf : (DST == 1) ? g_kf : g_vf;
#pragma unroll
                for (int half = 0; half < 2; ++half) {
                    const int rw = row + half * 8;
                    const int b = rw >> 11, n = rw & 2047;
                    float v0 = c[mt][nt][2 * half + 0] * s;
                    float v1 = c[mt][nt][2 * half + 1] * s;
                    size_t idx = (((size_t)(b * HH + h) * NN + n) * DD + d0) >> 1;
                    ((uint32_t*)Cf)[idx] = hf2pack(v0, v1);
                }
            } else {
                float2 bv = *(const float2*)&bias[col];
                float* p0 = Cout + (size_t)row * 512 + col;
                *(float2*)p0 = make_float2(c[mt][nt][0] + bv.x, c[mt][nt][1] + bv.y);
                float* p1 = Cout + (size_t)(row + 8) * 512 + col;
                *(float2*)p1 = make_float2(c[mt][nt][2] + bv.x, c[mt][nt][3] + bv.y);
            }
        }
    }
}

// ---------------------------------------------------------------------------
// Flash attention, single-fp16 MMA: BM=128 (8 warps x 16 rows), KV tiles 64.
// S = Q K^T (1 MMA), P,V fp16 (1 MMA). 2-stage cp.async KV pipeline.
// smem: Q 16K | stage0 16K (K 8K + V 8K) | stage1 16K  = 48 KB.
// ---------------------------------------------------------------------------
#define AT_Q 0
#define AT_ST0 16384
#define AT_STAGE 16384
#define KV_K 0
#define KV_V 8192
#define AT_SMEM (AT_ST0 + 2 * AT_STAGE)

__global__ __launch_bounds__(256)
void attn_mma()
{
    extern __shared__ char smem[];
    const uint32_t sb = smem_to_u32(smem);
    const int tid = threadIdx.x, wid = tid >> 5, lane = tid & 31;
    const int bh = blockIdx.y, qtile = blockIdx.x;

    const size_t bhoff = (size_t)bh * NN * DD;

    auto load_kv = [&](int st, int jt) {
        uint32_t base = sb + AT_ST0 + st * AT_STAGE;
        const size_t kvoff = bhoff + (size_t)jt * 64 * DD;
#pragma unroll
        for (int i = 0; i < 2; ++i) {
            int unit = i * 256 + tid;        // 512 units per plane
            int row = unit >> 3, seg = unit & 7;
            uint32_t off = (uint32_t)(row * 128 + ((seg * 16) ^ ((row & 7) << 4)));
            size_t g = kvoff + row * 64 + seg * 8;
            cpa16(base + KV_K + off, g_kf + g);
            cpa16(base + KV_V + off, g_vf + g);
        }
    };

    load_kv(0, 0);
    CP_COMMIT();

    // stage Q (128x64 fp16) into swizzled smem
    const size_t qoff = bhoff + (size_t)qtile * 128 * DD;
#pragma unroll
    for (int i = 0; i < 4; ++i) {
        int unit = i * 256 + tid;           // 1024 units
        int row = unit >> 3, seg = unit & 7;
        uint32_t off = (uint32_t)(row * 128 + ((seg * 16) ^ ((row & 7) << 4)));
        *(uint4*)(smem + AT_Q + off) = *(const uint4*)(g_qf + qoff + row * 64 + seg * 8);
    }
    __syncthreads();

    // per-warp Q A-fragments in regs
    uint32_t qh[4][4];
    {
        int r = lane & 15, hf = lane >> 4;
        int row = wid * 16 + r;
        uint32_t base = (uint32_t)(row * 128);
        uint32_t msk = (uint32_t)((row & 7) << 4);
#pragma unroll
        for (int ks = 0; ks < 4; ++ks)
            ldsm4(qh[ks], sb + AT_Q + base + (uint32_t)((hf * 16 + ks * 32) ^ (int)msk));
    }

    const int rnk = ((lane >> 4) << 3) + (lane & 7);
    const int hfk = (lane >> 3) & 1;
    const int jj  = lane & 15;
    const int dd8 = ((lane >> 4) & 1) * 8;

    float m0 = -1e30f, m1 = -1e30f, l0 = 0.f, l1 = 0.f;
    float o[8][4];
#pragma unroll
    for (int t = 0; t < 8; ++t)
#pragma unroll
        for (int e = 0; e < 4; ++e) o[t][e] = 0.f;

    for (int jt = 0; jt < NN / 64; ++jt) {
        if (jt + 1 < NN / 64) {
            load_kv((jt + 1) & 1, jt + 1);
            CP_COMMIT();
            CP_WAIT(1);
        } else {
            CP_WAIT(0);
        }
        __syncthreads();

        const uint32_t stb = sb + AT_ST0 + (jt & 1) * AT_STAGE;

        // ---- S = Q K^T (single fp16)
        float c[8][4];
#pragma unroll
        for (int t = 0; t < 8; ++t)
#pragma unroll
            for (int e = 0; e < 4; ++e) c[t][e] = 0.f;

#pragma unroll
        for (int ks = 0; ks < 4; ++ks) {
            uint32_t kf[4][4];
#pragma unroll
            for (int nt2 = 0; nt2 < 4; ++nt2) {
                int row = nt2 * 16 + rnk;
                uint32_t koff = (uint32_t)(row * 128)
                              + (uint32_t)((hfk * 16 + ks * 32) ^ ((row & 7) << 4));
                ldsm4(kf[nt2], stb + KV_K + koff);
            }
#pragma unroll
            for (int nt2 = 0; nt2 < 4; ++nt2) {
                uint32_t b0[2] = { kf[nt2][0], kf[nt2][1] };
                uint32_t b1[2] = { kf[nt2][2], kf[nt2][3] };
                mma16816h(c[2 * nt2 + 0], qh[ks], b0);
                mma16816h(c[2 * nt2 + 1], qh[ks], b1);
            }
        }

        // ---- online softmax (rows r0 = lane>>2, r0+8)
        float mx0 = -1e30f, mx1 = -1e30f;
#pragma unroll
        for (int t = 0; t < 8; ++t) {
            mx0 = fmaxf(mx0, fmaxf(c[t][0], c[t][1]));
            mx1 = fmaxf(mx1, fmaxf(c[t][2], c[t][3]));
        }
        mx0 = fmaxf(mx0, __shfl_xor_sync(0xffffffffu, mx0, 1));
        mx0 = fmaxf(mx0, __shfl_xor_sync(0xffffffffu, mx0, 2));
        mx1 = fmaxf(mx1, __shfl_xor_sync(0xffffffffu, mx1, 1));
        mx1 = fmaxf(mx1, __shfl_xor_sync(0xffffffffu, mx1, 2));

        float nm0 = fmaxf(m0, mx0), nm1 = fmaxf(m1, mx1);
        float cr0 = __expf(m0 - nm0), cr1 = __expf(m1 - nm1);
        m0 = nm0; m1 = nm1;
        l0 *= cr0; l1 *= cr1;
#pragma unroll
        for (int t = 0; t < 8; ++t) {
            o[t][0] *= cr0; o[t][1] *= cr0;
            o[t][2] *= cr1; o[t][3] *= cr1;
        }

        // ---- O += P V (single fp16)
#pragma unroll
        for (int ks = 0; ks < 4; ++ks) {
            uint32_t aP[4];
#pragma unroll
            for (int half = 0; half < 2; ++half) {
                int t = 2 * ks + half;
                float p0 = __expf(c[t][0] - nm0);
                float p1 = __expf(c[t][1] - nm0);
                float p2 = __expf(c[t][2] - nm1);
                float p3 = __expf(c[t][3] - nm1);
                l0 += p0 + p1;
                l1 += p2 + p3;
                aP[half ? 2 : 0] = hf2pack(p0, p1);
                aP[half ? 3 : 1] = hf2pack(p2, p3);
            }
            int row = ks * 16 + jj;
            uint32_t rbase = (uint32_t)(row * 128);
            uint32_t msk = (uint32_t)((row & 7) << 4);
#pragma unroll
            for (int dt2 = 0; dt2 < 4; ++dt2) {
                uint32_t off = rbase + (uint32_t)(((dt2 * 16 + dd8) * 2) ^ (int)msk);
                uint32_t v4[4];
                ldsm4t(v4, stb + KV_V + off);
                uint32_t b0[2] = { v4[0], v4[1] };
                uint32_t b1[2] = { v4[2], v4[3] };
                mma16816h(o[2 * dt2 + 0], aP, b0);
                mma16816h(o[2 * dt2 + 1], aP, b1);
            }
        }
        __syncthreads();
    }

    // l is a per-thread partial over 16-of-64 j cols; o holds the full row sum.
    l0 += __shfl_xor_sync(0xffffffffu, l0, 1);
    l0 += __shfl_xor_sync(0xffffffffu, l0, 2);
    l1 += __shfl_xor_sync(0xffffffffu, l1, 1);
    l1 += __shfl_xor_sync(0xffffffffu, l1, 2);

    // ---- epilogue: write bf16 hi/lo of O at [b, n, h*64+d]
    const int b = bh >> 3, h = bh & 7;
    const int gr = wid * 16 + (lane >> 2);
    const float inv0 = 1.f / l0, inv1 = 1.f / l1;
    const int n0 = qtile * 128 + gr;
    const int colb = h * 64 + 2 * (lane & 3);
#pragma unroll
    for (int t = 0; t < 8; ++t) {
        const int d = t * 8;
        {
            float v0 = o[t][0] * inv0, v1 = o[t][1] * inv0;
            uint32_t ph = bf2pack(v0, v1);
            float h0 = __uint_as_float(ph << 16);
            float h1 = __uint_as_float(ph & 0xffff0000u);
            size_t idx = (((size_t)(b * NN + n0) * INNERR) + colb + d) >> 1;
            ((uint32_t*)g_oh)[idx] = ph;
            ((uint32_t*)g_ol)[idx] = bf2pack(v0 - h0, v1 - h1);
        }
        {
            float v0 = o[t][2] * inv1, v1 = o[t][3] * inv1;
            uint32_t ph = bf2pack(v0, v1);
            float h0 = __uint_as_float(ph << 16);
            float h1 = __uint_as_float(ph & 0xffff0000u);
            size_t idx = (((size_t)(b * NN + n0 + 8) * INNERR) + colb + d) >> 1;
            ((uint32_t*)g_oh)[idx] = ph;
            ((uint32_t*)g_ol)[idx] = bf2pack(v0 - h0, v1 - h1);
        }
    }
}

// ---------------------------------------------------------------------------
extern "C" void kernel_launch(void* const* d_in, const int* in_sizes, int n_in,
                              void* d_out, int out_size)
{
    const float* x  = (const float*)d_in[0];
    const float* m  = (const float*)d_in[1];
    const float* Wq = (const float*)d_in[2];
    const float* Wk = (const float*)d_in[3];
    const float* Wv = (const float*)d_in[4];
    const float* Wo = (const float*)d_in[5];
    const float* bo = (const float*)d_in[6];
    float* out = (float*)d_out;

    cudaFuncSetAttribute(attn_mma, cudaFuncAttributeMaxDynamicSharedMemorySize, AT_SMEM);
    cudaFuncSetAttribute(gemm_mma<0>, cudaFuncAttributeMaxDynamicSharedMemorySize, GM_SMEM);
    cudaFuncSetAttribute(gemm_mma<1>, cudaFuncAttributeMaxDynamicSharedMemorySize, GM_SMEM);
    cudaFuncSetAttribute(gemm_mma<2>, cudaFuncAttributeMaxDynamicSharedMemorySize, GM_SMEM);
    cudaFuncSetAttribute(gemm_mma<3>, cudaFuncAttributeMaxDynamicSharedMemorySize, GM_SMEM);

    // bf16 hi/lo splits of inputs + transposed weights.
    // NOTE: launch order puts gemm_mma<0> at index 5 so ncu (-s 5 -c 1)
    // profiles a hot kernel.
    cvtA<0><<<8192, 256>>>(x);          // 0
    cvtA<1><<<8192, 256>>>(m);          // 1
    dim3 wg(16, 16), wb(32, 32);
    cvtW<0><<<wg, wb>>>(Wq);            // 2
    cvtW<1><<<wg, wb>>>(Wk);            // 3
    cvtW<2><<<wg, wb>>>(Wv);            // 4

    dim3 gg(4, 128);
    gemm_mma<0><<<gg, 256, GM_SMEM>>>(bo, nullptr);   // 5  <- profiled
    gemm_mma<1><<<gg, 256, GM_SMEM>>>(bo, nullptr);   // 6
    gemm_mma<2><<<gg, 256, GM_SMEM>>>(bo, nullptr);   // 7

    cvtW<3><<<wg, wb>>>(Wo);            // 8 (needed before gemm<3>)

    attn_mma<<<dim3(16, BB * HH), 256, AT_SMEM>>>();  // 9

    gemm_mma<3><<<gg, 256, GM_SMEM>>>(bo, out);       // 10
}

// round 12
// speedup vs baseline: 9.3466x; 1.2854x over previous
#include <cuda_runtime.h>
#include <cuda_bf16.h>
#include <cuda_fp16.h>
#include <cstdint>

// Problem constants
#define BB    8
#define NN    2048
#define DIMM  512
#define HH    8
#define DD    64
#define INNERR 512
#define NSCALE 0.044194173824159216f   // 512^-0.5

// ---- warp MMA helpers (sm_80+ baseline; no arch-'a' gating) ----
__device__ __forceinline__ void ldsm4(uint32_t* r, uint32_t addr) {
    asm volatile("ldmatrix.sync.aligned.m8n8.x4.shared.b16 {%0,%1,%2,%3}, [%4];"
                 : "=r"(r[0]), "=r"(r[1]), "=r"(r[2]), "=r"(r[3]) : "r"(addr));
}
__device__ __forceinline__ void ldsm4t(uint32_t* r, uint32_t addr) {
    asm volatile("ldmatrix.sync.aligned.m8n8.x4.trans.shared.b16 {%0,%1,%2,%3}, [%4];"
                 : "=r"(r[0]), "=r"(r[1]), "=r"(r[2]), "=r"(r[3]) : "r"(addr));
}
__device__ __forceinline__ void mma16816(float* c, const uint32_t* a, const uint32_t* b) {
    asm volatile("mma.sync.aligned.m16n8k16.row.col.f32.bf16.bf16.f32 "
                 "{%0,%1,%2,%3}, {%4,%5,%6,%7}, {%8,%9}, {%0,%1,%2,%3};"
                 : "+f"(c[0]), "+f"(c[1]), "+f"(c[2]), "+f"(c[3])
                 : "r"(a[0]), "r"(a[1]), "r"(a[2]), "r"(a[3]), "r"(b[0]), "r"(b[1]));
}
__device__ __forceinline__ void mma16816h(float* c, const uint32_t* a, const uint32_t* b) {
    asm volatile("mma.sync.aligned.m16n8k16.row.col.f32.f16.f16.f32 "
                 "{%0,%1,%2,%3}, {%4,%5,%6,%7}, {%8,%9}, {%0,%1,%2,%3};"
                 : "+f"(c[0]), "+f"(c[1]), "+f"(c[2]), "+f"(c[3])
                 : "r"(a[0]), "r"(a[1]), "r"(a[2]), "r"(a[3]), "r"(b[0]), "r"(b[1]));
}
__device__ __forceinline__ uint32_t smem_to_u32(const void* p) {
    uint32_t a;
    asm("{ .reg .u64 t; cvta.to.shared.u64 t, %1; cvt.u32.u64 %0, t; }"
        : "=r"(a) : "l"(p));
    return a;
}
// ---- cp.async (LDGSTS) ----
__device__ __forceinline__ void cpa16(uint32_t dst, const void* src) {
    asm volatile("cp.async.cg.shared.global [%0], [%1], 16;" :: "r"(dst), "l"(src));
}
#define CP_COMMIT() asm volatile("cp.async.commit_group;" ::: "memory")
#define CP_WAIT(N)  asm volatile("cp.async.wait_group %0;" :: "n"(N) : "memory")

#define SWZ(off) ((off) ^ (((off) >> 3) & 0x70))

__device__ __forceinline__ uint32_t bf2pack(float lo, float hi) {
    __nv_bfloat162 t = __floats2bfloat162_rn(lo, hi);   // x=lo (low 16b), y=hi
    return *reinterpret_cast<uint32_t*>(&t);
}
__device__ __forceinline__ uint32_t hf2pack(float lo, float hi) {
    __half2 t = __floats2half2_rn(lo, hi);
    return *reinterpret_cast<uint32_t*>(&t);
}

// =========================== scratch (device globals only) =================
#define ACNT ((size_t)16384 * 512)
__device__ unsigned short g_xf[ACNT];               // x fp16
__device__ unsigned short g_mf[ACNT];               // m fp16
__device__ unsigned short g_oh[ACNT], g_ol[ACNT];   // attention out bf16 hi/lo [b,n,(h d)]
#define QKV ((size_t)BB * HH * NN * DD)
__device__ unsigned short g_qf[QKV];                // Q*scale fp16 [b,h,n,d]
__device__ unsigned short g_kf[QKV];                // K fp16
__device__ unsigned short g_vf[QKV];                // V fp16
#define WCNT ((size_t)512 * 512)
__device__ unsigned short g_wqf[WCNT];              // Wq^T fp16
__device__ unsigned short g_wkf[WCNT];              // Wk^T fp16
__device__ unsigned short g_wvf[WCNT];              // Wv^T fp16
__device__ unsigned short g_woh[WCNT], g_wol[WCNT]; // Wo^T bf16 hi/lo

__device__ __forceinline__ void bf16split(float v, unsigned short& h, unsigned short& l) {
    __nv_bfloat16 bh = __float2bfloat16(v);
    float r = v - __bfloat162float(bh);
    __nv_bfloat16 bl = __float2bfloat16(r);
    h = __bfloat16_as_ushort(bh);
    l = __bfloat16_as_ushort(bl);
}

// ---------------------------------------------------------------------------
// cvtAf<SEL>: row-major fp32 [16384,512] -> fp16. 0: x, 1: m.
// ---------------------------------------------------------------------------
template<int SEL>
__global__ __launch_bounds__(256)
void cvtAf(const float* __restrict__ src)
{
    unsigned short* d = (SEL == 0) ? g_xf : g_mf;
    size_t i4 = (size_t)blockIdx.x * 256 + threadIdx.x;
    float4 v = ((const float4*)src)[i4];
    uint2 o;
    o.x = hf2pack(v.x, v.y);
    o.y = hf2pack(v.z, v.w);
    ((uint2*)d)[i4] = o;
}

// ---------------------------------------------------------------------------
// cvtWf<SEL>: W[512 k,512 n] fp32 -> transposed fp16 Wt[n][k]. 0/1/2 = q/k/v.
// ---------------------------------------------------------------------------
template<int SEL>
__global__ __launch_bounds__(1024)
void cvtWf(const float* __restrict__ W)
{
    unsigned short* d = (SEL == 0) ? g_wqf : (SEL == 1) ? g_wkf : g_wvf;
    __shared__ float tile[32][33];
    int k = blockIdx.y * 32 + threadIdx.y;
    int n = blockIdx.x * 32 + threadIdx.x;
    tile[threadIdx.y][threadIdx.x] = W[(size_t)k * 512 + n];
    __syncthreads();
    int nn = blockIdx.x * 32 + threadIdx.y;
    int kk = blockIdx.y * 32 + threadIdx.x;
    d[(size_t)nn * 512 + kk] =
        __half_as_ushort(__float2half_rn(tile[threadIdx.x][threadIdx.y]));
}

// ---------------------------------------------------------------------------
// cvtWo: Wo[512,512] fp32 -> transposed bf16 hi/lo (accurate final proj).
// ---------------------------------------------------------------------------
__global__ __launch_bounds__(1024)
void cvtWo(const float* __restrict__ W)
{
    __shared__ float tile[32][33];
    int k = blockIdx.y * 32 + threadIdx.y;
    int n = blockIdx.x * 32 + threadIdx.x;
    tile[threadIdx.y][threadIdx.x] = W[(size_t)k * 512 + n];
    __syncthreads();
    int nn = blockIdx.x * 32 + threadIdx.y;
    int kk = blockIdx.y * 32 + threadIdx.x;
    unsigned short hv, lv;
    bf16split(tile[threadIdx.x][threadIdx.y], hv, lv);
    g_woh[(size_t)nn * 512 + kk] = hv;
    g_wol[(size_t)nn * 512 + kk] = lv;
}

// ---------------------------------------------------------------------------
// fp16 GEMM for QKV projections: C = A @ W (single fp16 MMA, fp32 accum).
// Block 128x128, 8 warps, 2-stage cp.async (stage = A 16K + B 16K = 32KB).
// DST 0: Q*scale  1: K  2: V   (fp16 out, head-split [b,h,n,d])
// ---------------------------------------------------------------------------
#define GF_SA 0
#define GF_SB 16384
#define GF_STAGE 32768
#define GF_SMEM (2 * GF_STAGE)

template<int DST>
__global__ __launch_bounds__(256)
void gemm_f16(const float* __restrict__ xarg)
{
    const unsigned short* A = (DST == 0) ? g_xf : g_mf;
    const unsigned short* B = (DST == 0) ? g_wqf : (DST == 1) ? g_wkf : g_wvf;
    unsigned short* Cf = (DST == 0) ? g_qf : (DST == 1) ? g_kf : g_vf;
    (void)xarg;

    extern __shared__ char smem[];
    const uint32_t sb = smem_to_u32(smem);

    const int tid  = threadIdx.x;
    const int wid  = tid >> 5;
    const int lane = tid & 31;
    const int warp_m = wid >> 2;
    const int warp_n = wid & 3;
    const int rowBase = blockIdx.y * 128;
    const int colBase = blockIdx.x * 128;

    float c[4][4][4];
#pragma unroll
    for (int i = 0; i < 4; ++i)
#pragma unroll
        for (int j = 0; j < 4; ++j)
#pragma unroll
            for (int e = 0; e < 4; ++e) c[i][j][e] = 0.f;

    uint32_t aAddr[4], maskA[4];
    {
        int r = lane & 15, hf = lane >> 4;
#pragma unroll
        for (int mt = 0; mt < 4; ++mt) {
            uint32_t rb = (uint32_t)((warp_m * 64 + mt * 16 + r) * 128 + hf * 16);
            maskA[mt] = (rb >> 3) & 0x70;
            aAddr[mt] = rb;
        }
    }
    uint32_t bAddr[2], maskB[2];
    {
        int rn = ((lane >> 4) << 3) + (lane & 7);
        int hf = (lane >> 3) & 1;
#pragma unroll
        for (int nt2 = 0; nt2 < 2; ++nt2) {
            uint32_t rb = (uint32_t)((warp_n * 32 + nt2 * 16 + rn) * 128 + hf * 16);
            maskB[nt2] = (rb >> 3) & 0x70;
            bAddr[nt2] = rb;
        }
    }

    auto load_stage = [&](int st, int kc) {
        uint32_t base = sb + st * GF_STAGE;
#pragma unroll
        for (int it = 0; it < 4; ++it) {
            int unit = it * 256 + tid;
            int row = unit >> 3, seg = unit & 7;
            uint32_t off = SWZ((uint32_t)(row * 128 + seg * 16));
            cpa16(base + GF_SA + off, A + (size_t)(rowBase + row) * 512 + kc * 64 + seg * 8);
            cpa16(base + GF_SB + off, B + (size_t)(colBase + row) * 512 + kc * 64 + seg * 8);
        }
    };

    load_stage(0, 0);
    CP_COMMIT();

    for (int kc = 0; kc < 8; ++kc) {
        if (kc + 1 < 8) {
            load_stage((kc + 1) & 1, kc + 1);
            CP_COMMIT();
            CP_WAIT(1);
        } else {
            CP_WAIT(0);
        }
        __syncthreads();

        const uint32_t stb = sb + (kc & 1) * GF_STAGE;
#pragma unroll
        for (int ks = 0; ks < 4; ++ks) {
            uint32_t af[4][4], bf[4][2];
#pragma unroll
            for (int mt = 0; mt < 4; ++mt)
                ldsm4(af[mt], stb + GF_SA + ((aAddr[mt] + ks * 32) ^ maskA[mt]));
#pragma unroll
            for (int nt2 = 0; nt2 < 2; ++nt2) {
                uint32_t t4[4];
                ldsm4(t4, stb + GF_SB + ((bAddr[nt2] + ks * 32) ^ maskB[nt2]));
                bf[2 * nt2][0] = t4[0]; bf[2 * nt2][1] = t4[1];
                bf[2 * nt2 + 1][0] = t4[2]; bf[2 * nt2 + 1][1] = t4[3];
            }
#pragma unroll
            for (int mt = 0; mt < 4; ++mt)
#pragma unroll
                for (int nt = 0; nt < 4; ++nt)
                    mma16816h(c[mt][nt], af[mt], bf[nt]);
        }
        __syncthreads();
    }

    const int r0 = (lane >> 2);
    const int c2 = 2 * (lane & 3);
    const float s = (DST == 0) ? NSCALE : 1.f;
#pragma unroll
    for (int mt = 0; mt < 4; ++mt) {
#pragma unroll
        for (int nt = 0; nt < 4; ++nt) {
            int row = rowBase + warp_m * 64 + mt * 16 + r0;
            int col = colBase + warp_n * 32 + nt * 8 + c2;
            const int h = col >> 6, d0 = col & 63;
#pragma unroll
            for (int half = 0; half < 2; ++half) {
                const int rw = row + half * 8;
                const int b = rw >> 11, n = rw & 2047;
                size_t idx = (((size_t)(b * HH + h) * NN + n) * DD + d0) >> 1;
                ((uint32_t*)Cf)[idx] = hf2pack(c[mt][nt][2 * half + 0] * s,
                                               c[mt][nt][2 * half + 1] * s);
            }
        }
    }
}

// ---------------------------------------------------------------------------
// Final projection: out = O @ Wo + bias, bf16 3-split (accurate), fp32 out.
// Block 128x128, 2-stage cp.async (stage = 4 planes x 16KB = 64KB).
// ---------------------------------------------------------------------------
#define SA_H 0
#define SA_L 16384
#define SB_H 32768
#define SB_L 49152
#define GM_STAGE 65536
#define GM_SMEM  (2 * GM_STAGE)

__global__ __launch_bounds__(256)
void gemm_out(const float* __restrict__ bias, float* __restrict__ Cout)
{
    extern __shared__ char smem[];
    const uint32_t sb = smem_to_u32(smem);

    const int tid  = threadIdx.x;
    const int wid  = tid >> 5;
    const int lane = tid & 31;
    const int warp_m = wid >> 2;
    const int warp_n = wid & 3;
    const int rowBase = blockIdx.y * 128;
    const int colBase = blockIdx.x * 128;

    float c[4][4][4];
#pragma unroll
    for (int i = 0; i < 4; ++i)
#pragma unroll
        for (int j = 0; j < 4; ++j)
#pragma unroll
            for (int e = 0; e < 4; ++e) c[i][j][e] = 0.f;

    uint32_t aAddr[4], maskA[4];
    {
        int r = lane & 15, hf = lane >> 4;
#pragma unroll
        for (int mt = 0; mt < 4; ++mt) {
            uint32_t rb = (uint32_t)((warp_m * 64 + mt * 16 + r) * 128 + hf * 16);
            maskA[mt] = (rb >> 3) & 0x70;
            aAddr[mt] = rb;
        }
    }
    uint32_t bAddr[2], maskB[2];
    {
        int rn = ((lane >> 4) << 3) + (lane & 7);
        int hf = (lane >> 3) & 1;
#pragma unroll
        for (int nt2 = 0; nt2 < 2; ++nt2) {
            uint32_t rb = (uint32_t)((warp_n * 32 + nt2 * 16 + rn) * 128 + hf * 16);
            maskB[nt2] = (rb >> 3) & 0x70;
            bAddr[nt2] = rb;
        }
    }

    auto load_stage = [&](int st, int kc) {
        uint32_t base = sb + st * GM_STAGE;
#pragma unroll
        for (int it = 0; it < 4; ++it) {
            int unit = it * 256 + tid;
            int row = unit >> 3, seg = unit & 7;
            uint32_t off = SWZ((uint32_t)(row * 128 + seg * 16));
            size_t ga = (size_t)(rowBase + row) * 512 + kc * 64 + seg * 8;
            size_t gb = (size_t)(colBase + row) * 512 + kc * 64 + seg * 8;
            cpa16(base + SA_H + off, g_oh + ga);
            cpa16(base + SA_L + off, g_ol + ga);
            cpa16(base + SB_H + off, g_woh + gb);
            cpa16(base + SB_L + off, g_wol + gb);
        }
    };

    load_stage(0, 0);
    CP_COMMIT();

    for (int kc = 0; kc < 8; ++kc) {
        if (kc + 1 < 8) {
            load_stage((kc + 1) & 1, kc + 1);
            CP_COMMIT();
            CP_WAIT(1);
        } else {
            CP_WAIT(0);
        }
        __syncthreads();

        const uint32_t stb = sb + (kc & 1) * GM_STAGE;
#pragma unroll
        for (int ks = 0; ks < 4; ++ks) {
            uint32_t ah[4][4], al[4][4], bh[4][2], bl[4][2];
#pragma unroll
            for (int mt = 0; mt < 4; ++mt) {
                uint32_t o = ((aAddr[mt] + ks * 32) ^ maskA[mt]);
                ldsm4(ah[mt], stb + SA_H + o);
                ldsm4(al[mt], stb + SA_L + o);
            }
#pragma unroll
            for (int nt2 = 0; nt2 < 2; ++nt2) {
                uint32_t o = ((bAddr[nt2] + ks * 32) ^ maskB[nt2]);
                uint32_t t4[4];
                ldsm4(t4, stb + SB_H + o);
                bh[2 * nt2][0] = t4[0]; bh[2 * nt2][1] = t4[1];
                bh[2 * nt2 + 1][0] = t4[2]; bh[2 * nt2 + 1][1] = t4[3];
                ldsm4(t4, stb + SB_L + o);
                bl[2 * nt2][0] = t4[0]; bl[2 * nt2][1] = t4[1];
                bl[2 * nt2 + 1][0] = t4[2]; bl[2 * nt2 + 1][1] = t4[3];
            }
#pragma unroll
            for (int mt = 0; mt < 4; ++mt)
#pragma unroll
                for (int nt = 0; nt < 4; ++nt) {
                    mma16816(c[mt][nt], ah[mt], bh[nt]);
                    mma16816(c[mt][nt], ah[mt], bl[nt]);
                    mma16816(c[mt][nt], al[mt], bh[nt]);
                }
        }
        __syncthreads();
    }

    const int r0 = (lane >> 2);
    const int c2 = 2 * (lane & 3);
#pragma unroll
    for (int mt = 0; mt < 4; ++mt) {
#pragma unroll
        for (int nt = 0; nt < 4; ++nt) {
            int row = rowBase + warp_m * 64 + mt * 16 + r0;
            int col = colBase + warp_n * 32 + nt * 8 + c2;
            float2 bv = *(const float2*)&bias[col];
            float* p0 = Cout + (size_t)row * 512 + col;
            *(float2*)p0 = make_float2(c[mt][nt][0] + bv.x, c[mt][nt][1] + bv.y);
            float* p1 = Cout + (size_t)(row + 8) * 512 + col;
            *(float2*)p1 = make_float2(c[mt][nt][2] + bv.x, c[mt][nt][3] + bv.y);
        }
    }
}

// ---------------------------------------------------------------------------
// Flash attention, single-fp16 MMA: BM=128 (8 warps x 16 rows), KV tiles 64.
// 2-stage cp.async KV pipeline. O written as bf16 hi/lo for final 3-split proj.
// smem: Q 16K | stage0 16K (K 8K + V 8K) | stage1 16K  = 48 KB.
// ---------------------------------------------------------------------------
#define AT_Q 0
#define AT_ST0 16384
#define AT_STAGE 16384
#define KV_K 0
#define KV_V 8192
#define AT_SMEM (AT_ST0 + 2 * AT_STAGE)

__global__ __launch_bounds__(256)
void attn_mma()
{
    extern __shared__ char smem[];
    const uint32_t sb = smem_to_u32(smem);
    const int tid = threadIdx.x, wid = tid >> 5, lane = tid & 31;
    const int bh = blockIdx.y, qtile = blockIdx.x;

    const size_t bhoff = (size_t)bh * NN * DD;

    auto load_kv = [&](int st, int jt) {
        uint32_t base = sb + AT_ST0 + st * AT_STAGE;
        const size_t kvoff = bhoff + (size_t)jt * 64 * DD;
#pragma unroll
        for (int i = 0; i < 2; ++i) {
            int unit = i * 256 + tid;        // 512 units per plane
            int row = unit >> 3, seg = unit & 7;
            uint32_t off = (uint32_t)(row * 128 + ((seg * 16) ^ ((row & 7) << 4)));
            size_t g = kvoff + row * 64 + seg * 8;
            cpa16(base + KV_K + off, g_kf + g);
            cpa16(base + KV_V + off, g_vf + g);
        }
    };

    load_kv(0, 0);
    CP_COMMIT();

    // stage Q (128x64 fp16) into swizzled smem
    const size_t qoff = bhoff + (size_t)qtile * 128 * DD;
#pragma unroll
    for (int i = 0; i < 4; ++i) {
        int unit = i * 256 + tid;           // 1024 units
        int row = unit >> 3, seg = unit & 7;
        uint32_t off = (uint32_t)(row * 128 + ((seg * 16) ^ ((row & 7) << 4)));
        *(uint4*)(smem + AT_Q + off) = *(const uint4*)(g_qf + qoff + row * 64 + seg * 8);
    }
    __syncthreads();

    // per-warp Q A-fragments in regs
    uint32_t qh[4][4];
    {
        int r = lane & 15, hf = lane >> 4;
        int row = wid * 16 + r;
        uint32_t base = (uint32_t)(row * 128);
        uint32_t msk = (uint32_t)((row & 7) << 4);
#pragma unroll
        for (int ks = 0; ks < 4; ++ks)
            ldsm4(qh[ks], sb + AT_Q + base + (uint32_t)((hf * 16 + ks * 32) ^ (int)msk));
    }

    const int rnk = ((lane >> 4) << 3) + (lane & 7);
    const int hfk = (lane >> 3) & 1;
    const int jj  = lane & 15;
    const int dd8 = ((lane >> 4) & 1) * 8;

    float m0 = -1e30f, m1 = -1e30f, l0 = 0.f, l1 = 0.f;
    float o[8][4];
#pragma unroll
    for (int t = 0; t < 8; ++t)
#pragma unroll
        for (int e = 0; e < 4; ++e) o[t][e] = 0.f;

    for (int jt = 0; jt < NN / 64; ++jt) {
        if (jt + 1 < NN / 64) {
            load_kv((jt + 1) & 1, jt + 1);
            CP_COMMIT();
            CP_WAIT(1);
        } else {
            CP_WAIT(0);
        }
        __syncthreads();

        const uint32_t stb = sb + AT_ST0 + (jt & 1) * AT_STAGE;

        // ---- S = Q K^T (single fp16)
        float c[8][4];
#pragma unroll
        for (int t = 0; t < 8; ++t)
#pragma unroll
            for (int e = 0; e < 4; ++e) c[t][e] = 0.f;

#pragma unroll
        for (int ks = 0; ks < 4; ++ks) {
            uint32_t kf[4][4];
#pragma unroll
            for (int nt2 = 0; nt2 < 4; ++nt2) {
                int row = nt2 * 16 + rnk;
                uint32_t koff = (uint32_t)(row * 128)
                              + (uint32_t)((hfk * 16 + ks * 32) ^ ((row & 7) << 4));
                ldsm4(kf[nt2], stb + KV_K + koff);
            }
#pragma unroll
            for (int nt2 = 0; nt2 < 4; ++nt2) {
                uint32_t b0[2] = { kf[nt2][0], kf[nt2][1] };
                uint32_t b1[2] = { kf[nt2][2], kf[nt2][3] };
                mma16816h(c[2 * nt2 + 0], qh[ks], b0);
                mma16816h(c[2 * nt2 + 1], qh[ks], b1);
            }
        }

        // ---- online softmax (rows r0 = lane>>2, r0+8)
        float mx0 = -1e30f, mx1 = -1e30f;
#pragma unroll
        for (int t = 0; t < 8; ++t) {
            mx0 = fmaxf(mx0, fmaxf(c[t][0], c[t][1]));
            mx1 = fmaxf(mx1, fmaxf(c[t][2], c[t][3]));
        }
        mx0 = fmaxf(mx0, __shfl_xor_sync(0xffffffffu, mx0, 1));
        mx0 = fmaxf(mx0, __shfl_xor_sync(0xffffffffu, mx0, 2));
        mx1 = fmaxf(mx1, __shfl_xor_sync(0xffffffffu, mx1, 1));
        mx1 = fmaxf(mx1, __shfl_xor_sync(0xffffffffu, mx1, 2));

        float nm0 = fmaxf(m0, mx0), nm1 = fmaxf(m1, mx1);
        float cr0 = __expf(m0 - nm0), cr1 = __expf(m1 - nm1);
        m0 = nm0; m1 = nm1;
        l0 *= cr0; l1 *= cr1;
#pragma unroll
        for (int t = 0; t < 8; ++t) {
            o[t][0] *= cr0; o[t][1] *= cr0;
            o[t][2] *= cr1; o[t][3] *= cr1;
        }

        // ---- O += P V (single fp16)
#pragma unroll
        for (int ks = 0; ks < 4; ++ks) {
            uint32_t aP[4];
#pragma unroll
            for (int half = 0; half < 2; ++half) {
                int t = 2 * ks + half;
                float p0 = __expf(c[t][0] - nm0);
                float p1 = __expf(c[t][1] - nm0);
                float p2 = __expf(c[t][2] - nm1);
                float p3 = __expf(c[t][3] - nm1);
                l0 += p0 + p1;
                l1 += p2 + p3;
                aP[half ? 2 : 0] = hf2pack(p0, p1);
                aP[half ? 3 : 1] = hf2pack(p2, p3);
            }
            int row = ks * 16 + jj;
            uint32_t rbase = (uint32_t)(row * 128);
            uint32_t msk = (uint32_t)((row & 7) << 4);
#pragma unroll
            for (int dt2 = 0; dt2 < 4; ++dt2) {
                uint32_t off = rbase + (uint32_t)(((dt2 * 16 + dd8) * 2) ^ (int)msk);
                uint32_t v4[4];
                ldsm4t(v4, stb + KV_V + off);
                uint32_t b0[2] = { v4[0], v4[1] };
                uint32_t b1[2] = { v4[2], v4[3] };
                mma16816h(o[2 * dt2 + 0], aP, b0);
                mma16816h(o[2 * dt2 + 1], aP, b1);
            }
        }
        __syncthreads();
    }

    // l is a per-thread partial over 16-of-64 j cols; o holds the full row sum.
    l0 += __shfl_xor_sync(0xffffffffu, l0, 1);
    l0 += __shfl_xor_sync(0xffffffffu, l0, 2);
    l1 += __shfl_xor_sync(0xffffffffu, l1, 1);
    l1 += __shfl_xor_sync(0xffffffffu, l1, 2);

    // ---- epilogue: write bf16 hi/lo of O at [b, n, h*64+d]
    const int b = bh >> 3, h = bh & 7;
    const int gr = wid * 16 + (lane >> 2);
    const float inv0 = 1.f / l0, inv1 = 1.f / l1;
    const int n0 = qtile * 128 + gr;
    const int colb = h * 64 + 2 * (lane & 3);
#pragma unroll
    for (int t = 0; t < 8; ++t) {
        const int d = t * 8;
        {
            float v0 = o[t][0] * inv0, v1 = o[t][1] * inv0;
            uint32_t ph = bf2pack(v0, v1);
            float h0 = __uint_as_float(ph << 16);
            float h1 = __uint_as_float(ph & 0xffff0000u);
            size_t idx = (((size_t)(b * NN + n0) * INNERR) + colb + d) >> 1;
            ((uint32_t*)g_oh)[idx] = ph;
            ((uint32_t*)g_ol)[idx] = bf2pack(v0 - h0, v1 - h1);
        }
        {
            float v0 = o[t][2] * inv1, v1 = o[t][3] * inv1;
            uint32_t ph = bf2pack(v0, v1);
            float h0 = __uint_as_float(ph << 16);
            float h1 = __uint_as_float(ph & 0xffff0000u);
            size_t idx = (((size_t)(b * NN + n0 + 8) * INNERR) + colb + d) >> 1;
            ((uint32_t*)g_oh)[idx] = ph;
            ((uint32_t*)g_ol)[idx] = bf2pack(v0 - h0, v1 - h1);
        }
    }
}

// ---------------------------------------------------------------------------
extern "C" void kernel_launch(void* const* d_in, const int* in_sizes, int n_in,
                              void* d_out, int out_size)
{
    const float* x  = (const float*)d_in[0];
    const float* m  = (const float*)d_in[1];
    const float* Wq = (const float*)d_in[2];
    const float* Wk = (const float*)d_in[3];
    const float* Wv = (const float*)d_in[4];
    const float* Wo = (const float*)d_in[5];
    const float* bo = (const float*)d_in[6];
    float* out = (float*)d_out;

    cudaFuncSetAttribute(attn_mma, cudaFuncAttributeMaxDynamicSharedMemorySize, AT_SMEM);
    cudaFuncSetAttribute(gemm_f16<0>, cudaFuncAttributeMaxDynamicSharedMemorySize, GF_SMEM);
    cudaFuncSetAttribute(gemm_f16<1>, cudaFuncAttributeMaxDynamicSharedMemorySize, GF_SMEM);
    cudaFuncSetAttribute(gemm_f16<2>, cudaFuncAttributeMaxDynamicSharedMemorySize, GF_SMEM);
    cudaFuncSetAttribute(gemm_out, cudaFuncAttributeMaxDynamicSharedMemorySize, GM_SMEM);

    dim3 wg(16, 16), wb(32, 32);
    cvtAf<0><<<8192, 256>>>(x);          // 0
    cvtAf<1><<<8192, 256>>>(m);          // 1
    cvtWf<0><<<wg, wb>>>(Wq);            // 2
    cvtWf<1><<<wg, wb>>>(Wk);            // 3
    cvtWf<2><<<wg, wb>>>(Wv);            // 4

    dim3 gg(4, 128);
    gemm_f16<0><<<gg, 256, GF_SMEM>>>(nullptr);   // 5  <- ncu -s 5
    gemm_f16<1><<<gg, 256, GF_SMEM>>>(nullptr);   // 6
    gemm_f16<2><<<gg, 256, GF_SMEM>>>(nullptr);   // 7

    cvtWo<<<wg, wb>>>(Wo);               // 8

    attn_mma<<<dim3(16, BB * HH), 256, AT_SMEM>>>();  // 9

    gemm_out<<<gg, 256, GM_SMEM>>>(bo, out);          // 10
}

// round 13
// speedup vs baseline: 9.8696x; 1.0560x over previous
#include <cuda_runtime.h>
#include <cuda_bf16.h>
#include <cuda_fp16.h>
#include <cstdint>

// Problem constants
#define BB    8
#define NN    2048
#define DIMM  512
#define HH    8
#define DD    64
#define INNERR 512
#define NSCALE 0.044194173824159216f   // 512^-0.5

// ---- warp MMA helpers (sm_80+ baseline; no arch-'a' gating) ----
__device__ __forceinline__ void ldsm4(uint32_t* r, uint32_t addr) {
    asm volatile("ldmatrix.sync.aligned.m8n8.x4.shared.b16 {%0,%1,%2,%3}, [%4];"
                 : "=r"(r[0]), "=r"(r[1]), "=r"(r[2]), "=r"(r[3]) : "r"(addr));
}
__device__ __forceinline__ void ldsm4t(uint32_t* r, uint32_t addr) {
    asm volatile("ldmatrix.sync.aligned.m8n8.x4.trans.shared.b16 {%0,%1,%2,%3}, [%4];"
                 : "=r"(r[0]), "=r"(r[1]), "=r"(r[2]), "=r"(r[3]) : "r"(addr));
}
__device__ __forceinline__ void mma16816h(float* c, const uint32_t* a, const uint32_t* b) {
    asm volatile("mma.sync.aligned.m16n8k16.row.col.f32.f16.f16.f32 "
                 "{%0,%1,%2,%3}, {%4,%5,%6,%7}, {%8,%9}, {%0,%1,%2,%3};"
                 : "+f"(c[0]), "+f"(c[1]), "+f"(c[2]), "+f"(c[3])
                 : "r"(a[0]), "r"(a[1]), "r"(a[2]), "r"(a[3]), "r"(b[0]), "r"(b[1]));
}
__device__ __forceinline__ uint32_t smem_to_u32(const void* p) {
    uint32_t a;
    asm("{ .reg .u64 t; cvta.to.shared.u64 t, %1; cvt.u32.u64 %0, t; }"
        : "=r"(a) : "l"(p));
    return a;
}
// ---- cp.async (LDGSTS) ----
__device__ __forceinline__ void cpa16(uint32_t dst, const void* src) {
    asm volatile("cp.async.cg.shared.global [%0], [%1], 16;" :: "r"(dst), "l"(src));
}
#define CP_COMMIT() asm volatile("cp.async.commit_group;" ::: "memory")
#define CP_WAIT(N)  asm volatile("cp.async.wait_group %0;" :: "n"(N) : "memory")

#define SWZ(off) ((off) ^ (((off) >> 3) & 0x70))

__device__ __forceinline__ uint32_t hf2pack(float lo, float hi) {
    __half2 t = __floats2half2_rn(lo, hi);
    return *reinterpret_cast<uint32_t*>(&t);
}

// =========================== scratch (device globals only) =================
#define ACNT ((size_t)16384 * 512)
__device__ unsigned short g_xf[ACNT];               // x fp16
__device__ unsigned short g_mf[ACNT];               // m fp16
__device__ unsigned short g_of[ACNT];               // attention out fp16 [b,n,(h d)]
#define QKV ((size_t)BB * HH * NN * DD)
__device__ unsigned short g_qf[QKV];                // Q*scale fp16 [b,h,n,d]
__device__ unsigned short g_kf[QKV];                // K fp16
__device__ unsigned short g_vf[QKV];                // V fp16
#define WCNT ((size_t)512 * 512)
__device__ unsigned short g_wqf[WCNT];              // Wq^T fp16
__device__ unsigned short g_wkf[WCNT];              // Wk^T fp16
__device__ unsigned short g_wvf[WCNT];              // Wv^T fp16
__device__ unsigned short g_woh[WCNT], g_wol[WCNT]; // Wo^T fp16 hi/lo

// ---------------------------------------------------------------------------
// cvtAf<SEL>: row-major fp32 [16384,512] -> fp16. 0: x, 1: m.
// ---------------------------------------------------------------------------
template<int SEL>
__global__ __launch_bounds__(256)
void cvtAf(const float* __restrict__ src)
{
    unsigned short* d = (SEL == 0) ? g_xf : g_mf;
    size_t i4 = (size_t)blockIdx.x * 256 + threadIdx.x;
    float4 v = ((const float4*)src)[i4];
    uint2 o;
    o.x = hf2pack(v.x, v.y);
    o.y = hf2pack(v.z, v.w);
    ((uint2*)d)[i4] = o;
}

// ---------------------------------------------------------------------------
// cvtWf<SEL>: W[512 k,512 n] fp32 -> transposed fp16 Wt[n][k]. 0/1/2 = q/k/v.
// ---------------------------------------------------------------------------
template<int SEL>
__global__ __launch_bounds__(1024)
void cvtWf(const float* __restrict__ W)
{
    unsigned short* d = (SEL == 0) ? g_wqf : (SEL == 1) ? g_wkf : g_wvf;
    __shared__ float tile[32][33];
    int k = blockIdx.y * 32 + threadIdx.y;
    int n = blockIdx.x * 32 + threadIdx.x;
    tile[threadIdx.y][threadIdx.x] = W[(size_t)k * 512 + n];
    __syncthreads();
    int nn = blockIdx.x * 32 + threadIdx.y;
    int kk = blockIdx.y * 32 + threadIdx.x;
    d[(size_t)nn * 512 + kk] =
        __half_as_ushort(__float2half_rn(tile[threadIdx.x][threadIdx.y]));
}

// ---------------------------------------------------------------------------
// cvtWo: Wo[512,512] fp32 -> transposed fp16 hi/lo (hi = f16(w), lo = f16(w-hi)).
// ---------------------------------------------------------------------------
__global__ __launch_bounds__(1024)
void cvtWo(const float* __restrict__ W)
{
    __shared__ float tile[32][33];
    int k = blockIdx.y * 32 + threadIdx.y;
    int n = blockIdx.x * 32 + threadIdx.x;
    tile[threadIdx.y][threadIdx.x] = W[(size_t)k * 512 + n];
    __syncthreads();
    int nn = blockIdx.x * 32 + threadIdx.y;
    int kk = blockIdx.y * 32 + threadIdx.x;
    float v = tile[threadIdx.x][threadIdx.y];
    __half hh = __float2half_rn(v);
    float r = v - __half2float(hh);
    g_woh[(size_t)nn * 512 + kk] = __half_as_ushort(hh);
    g_wol[(size_t)nn * 512 + kk] = __half_as_ushort(__float2half_rn(r));
}

// ---------------------------------------------------------------------------
// fp16 GEMM for QKV projections: C = A @ W (single fp16 MMA, fp32 accum).
// Block 128x128, 8 warps, 2-stage cp.async (stage = A 16K + B 16K = 32KB).
// DST 0: Q*scale  1: K  2: V   (fp16 out, head-split [b,h,n,d])
// ---------------------------------------------------------------------------
#define GF_SA 0
#define GF_SB 16384
#define GF_STAGE 32768
#define GF_SMEM (2 * GF_STAGE)

template<int DST>
__global__ __launch_bounds__(256)
void gemm_f16()
{
    const unsigned short* A = (DST == 0) ? g_xf : g_mf;
    const unsigned short* B = (DST == 0) ? g_wqf : (DST == 1) ? g_wkf : g_wvf;
    unsigned short* Cf = (DST == 0) ? g_qf : (DST == 1) ? g_kf : g_vf;

    extern __shared__ char smem[];
    const uint32_t sb = smem_to_u32(smem);

    const int tid  = threadIdx.x;
    const int wid  = tid >> 5;
    const int lane = tid & 31;
    const int warp_m = wid >> 2;
    const int warp_n = wid & 3;
    const int rowBase = blockIdx.y * 128;
    const int colBase = blockIdx.x * 128;

    float c[4][4][4];
#pragma unroll
    for (int i = 0; i < 4; ++i)
#pragma unroll
        for (int j = 0; j < 4; ++j)
#pragma unroll
            for (int e = 0; e < 4; ++e) c[i][j][e] = 0.f;

    uint32_t aAddr[4], maskA[4];
    {
        int r = lane & 15, hf = lane >> 4;
#pragma unroll
        for (int mt = 0; mt < 4; ++mt) {
            uint32_t rb = (uint32_t)((warp_m * 64 + mt * 16 + r) * 128 + hf * 16);
            maskA[mt] = (rb >> 3) & 0x70;
            aAddr[mt] = rb;
        }
    }
    uint32_t bAddr[2], maskB[2];
    {
        int rn = ((lane >> 4) << 3) + (lane & 7);
        int hf = (lane >> 3) & 1;
#pragma unroll
        for (int nt2 = 0; nt2 < 2; ++nt2) {
            uint32_t rb = (uint32_t)((warp_n * 32 + nt2 * 16 + rn) * 128 + hf * 16);
            maskB[nt2] = (rb >> 3) & 0x70;
            bAddr[nt2] = rb;
        }
    }

    auto load_stage = [&](int st, int kc) {
        uint32_t base = sb + st * GF_STAGE;
#pragma unroll
        for (int it = 0; it < 4; ++it) {
            int unit = it * 256 + tid;
            int row = unit >> 3, seg = unit & 7;
            uint32_t off = SWZ((uint32_t)(row * 128 + seg * 16));
            cpa16(base + GF_SA + off, A + (size_t)(rowBase + row) * 512 + kc * 64 + seg * 8);
            cpa16(base + GF_SB + off, B + (size_t)(colBase + row) * 512 + kc * 64 + seg * 8);
        }
    };

    load_stage(0, 0);
    CP_COMMIT();

    for (int kc = 0; kc < 8; ++kc) {
        if (kc + 1 < 8) {
            load_stage((kc + 1) & 1, kc + 1);
            CP_COMMIT();
            CP_WAIT(1);
        } else {
            CP_WAIT(0);
        }
        __syncthreads();

        const uint32_t stb = sb + (kc & 1) * GF_STAGE;
#pragma unroll
        for (int ks = 0; ks < 4; ++ks) {
            uint32_t af[4][4], bf[4][2];
#pragma unroll
            for (int mt = 0; mt < 4; ++mt)
                ldsm4(af[mt], stb + GF_SA + ((aAddr[mt] + ks * 32) ^ maskA[mt]));
#pragma unroll
            for (int nt2 = 0; nt2 < 2; ++nt2) {
                uint32_t t4[4];
                ldsm4(t4, stb + GF_SB + ((bAddr[nt2] + ks * 32) ^ maskB[nt2]));
                bf[2 * nt2][0] = t4[0]; bf[2 * nt2][1] = t4[1];
                bf[2 * nt2 + 1][0] = t4[2]; bf[2 * nt2 + 1][1] = t4[3];
            }
#pragma unroll
            for (int mt = 0; mt < 4; ++mt)
#pragma unroll
                for (int nt = 0; nt < 4; ++nt)
                    mma16816h(c[mt][nt], af[mt], bf[nt]);
        }
        __syncthreads();
    }

    const int r0 = (lane >> 2);
    const int c2 = 2 * (lane & 3);
    const float s = (DST == 0) ? NSCALE : 1.f;
#pragma unroll
    for (int mt = 0; mt < 4; ++mt) {
#pragma unroll
        for (int nt = 0; nt < 4; ++nt) {
            int row = rowBase + warp_m * 64 + mt * 16 + r0;
            int col = colBase + warp_n * 32 + nt * 8 + c2;
            const int h = col >> 6, d0 = col & 63;
#pragma unroll
            for (int half = 0; half < 2; ++half) {
                const int rw = row + half * 8;
                const int b = rw >> 11, n = rw & 2047;
                size_t idx = (((size_t)(b * HH + h) * NN + n) * DD + d0) >> 1;
                ((uint32_t*)Cf)[idx] = hf2pack(c[mt][nt][2 * half + 0] * s,
                                               c[mt][nt][2 * half + 1] * s);
            }
        }
    }
}

// ---------------------------------------------------------------------------
// Final projection: out = O @ (Wo_h + Wo_l) + bias, fp16 2-term, fp32 out.
// Block 128x128, 2-stage cp.async (stage = 3 planes x 16KB = 48KB).
// ---------------------------------------------------------------------------
#define GO_SA  0
#define GO_BH  16384
#define GO_BL  32768
#define GO_STAGE 49152
#define GO_SMEM  (2 * GO_STAGE)

__global__ __launch_bounds__(256)
void gemm_out(const float* __restrict__ bias, float* __restrict__ Cout)
{
    extern __shared__ char smem[];
    const uint32_t sb = smem_to_u32(smem);

    const int tid  = threadIdx.x;
    const int wid  = tid >> 5;
    const int lane = tid & 31;
    const int warp_m = wid >> 2;
    const int warp_n = wid & 3;
    const int rowBase = blockIdx.y * 128;
    const int colBase = blockIdx.x * 128;

    float c[4][4][4];
#pragma unroll
    for (int i = 0; i < 4; ++i)
#pragma unroll
        for (int j = 0; j < 4; ++j)
#pragma unroll
            for (int e = 0; e < 4; ++e) c[i][j][e] = 0.f;

    uint32_t aAddr[4], maskA[4];
    {
        int r = lane & 15, hf = lane >> 4;
#pragma unroll
        for (int mt = 0; mt < 4; ++mt) {
            uint32_t rb = (uint32_t)((warp_m * 64 + mt * 16 + r) * 128 + hf * 16);
            maskA[mt] = (rb >> 3) & 0x70;
            aAddr[mt] = rb;
        }
    }
    uint32_t bAddr[2], maskB[2];
    {
        int rn = ((lane >> 4) << 3) + (lane & 7);
        int hf = (lane >> 3) & 1;
#pragma unroll
        for (int nt2 = 0; nt2 < 2; ++nt2) {
            uint32_t rb = (uint32_t)((warp_n * 32 + nt2 * 16 + rn) * 128 + hf * 16);
            maskB[nt2] = (rb >> 3) & 0x70;
            bAddr[nt2] = rb;
        }
    }

    auto load_stage = [&](int st, int kc) {
        uint32_t base = sb + st * GO_STAGE;
#pragma unroll
        for (int it = 0; it < 4; ++it) {
            int unit = it * 256 + tid;
            int row = unit >> 3, seg = unit & 7;
            uint32_t off = SWZ((uint32_t)(row * 128 + seg * 16));
            size_t ga = (size_t)(rowBase + row) * 512 + kc * 64 + seg * 8;
            size_t gb = (size_t)(colBase + row) * 512 + kc * 64 + seg * 8;
            cpa16(base + GO_SA + off, g_of + ga);
            cpa16(base + GO_BH + off, g_woh + gb);
            cpa16(base + GO_BL + off, g_wol + gb);
        }
    };

    load_stage(0, 0);
    CP_COMMIT();

    for (int kc = 0; kc < 8; ++kc) {
        if (kc + 1 < 8) {
            load_stage((kc + 1) & 1, kc + 1);
            CP_COMMIT();
            CP_WAIT(1);
        } else {
            CP_WAIT(0);
        }
        __syncthreads();

        const uint32_t stb = sb + (kc & 1) * GO_STAGE;
#pragma unroll
        for (int ks = 0; ks < 4; ++ks) {
            uint32_t af[4][4], bh[4][2], bl[4][2];
#pragma unroll
            for (int mt = 0; mt < 4; ++mt)
                ldsm4(af[mt], stb + GO_SA + ((aAddr[mt] + ks * 32) ^ maskA[mt]));
#pragma unroll
            for (int nt2 = 0; nt2 < 2; ++nt2) {
                uint32_t o = ((bAddr[nt2] + ks * 32) ^ maskB[nt2]);
                uint32_t t4[4];
                ldsm4(t4, stb + GO_BH + o);
                bh[2 * nt2][0] = t4[0]; bh[2 * nt2][1] = t4[1];
                bh[2 * nt2 + 1][0] = t4[2]; bh[2 * nt2 + 1][1] = t4[3];
                ldsm4(t4, stb + GO_BL + o);
                bl[2 * nt2][0] = t4[0]; bl[2 * nt2][1] = t4[1];
                bl[2 * nt2 + 1][0] = t4[2]; bl[2 * nt2 + 1][1] = t4[3];
            }
#pragma unroll
            for (int mt = 0; mt < 4; ++mt)
#pragma unroll
                for (int nt = 0; nt < 4; ++nt) {
                    mma16816h(c[mt][nt], af[mt], bh[nt]);
                    mma16816h(c[mt][nt], af[mt], bl[nt]);
                }
        }
        __syncthreads();
    }

    const int r0 = (lane >> 2);
    const int c2 = 2 * (lane & 3);
#pragma unroll
    for (int mt = 0; mt < 4; ++mt) {
#pragma unroll
        for (int nt = 0; nt < 4; ++nt) {
            int row = rowBase + warp_m * 64 + mt * 16 + r0;
            int col = colBase + warp_n * 32 + nt * 8 + c2;
            float2 bv = *(const float2*)&bias[col];
            float* p0 = Cout + (size_t)row * 512 + col;
            *(float2*)p0 = make_float2(c[mt][nt][0] + bv.x, c[mt][nt][1] + bv.y);
            float* p1 = Cout + (size_t)(row + 8) * 512 + col;
            *(float2*)p1 = make_float2(c[mt][nt][2] + bv.x, c[mt][nt][3] + bv.y);
        }
    }
}

// ---------------------------------------------------------------------------
// Flash attention, single-fp16 MMA: BM=128 (8 warps x 16 rows), KV tiles 64.
// 2-stage cp.async KV pipeline. O written as single fp16.
// smem: Q 16K | stage0 16K (K 8K + V 8K) | stage1 16K  = 48 KB.
// ---------------------------------------------------------------------------
#define AT_Q 0
#define AT_ST0 16384
#define AT_STAGE 16384
#define KV_K 0
#define KV_V 8192
#define AT_SMEM (AT_ST0 + 2 * AT_STAGE)

__global__ __launch_bounds__(256)
void attn_mma()
{
    extern __shared__ char smem[];
    const uint32_t sb = smem_to_u32(smem);
    const int tid = threadIdx.x, wid = tid >> 5, lane = tid & 31;
    const int bh = blockIdx.y, qtile = blockIdx.x;

    const size_t bhoff = (size_t)bh * NN * DD;

    auto load_kv = [&](int st, int jt) {
        uint32_t base = sb + AT_ST0 + st * AT_STAGE;
        const size_t kvoff = bhoff + (size_t)jt * 64 * DD;
#pragma unroll
        for (int i = 0; i < 2; ++i) {
            int unit = i * 256 + tid;        // 512 units per plane
            int row = unit >> 3, seg = unit & 7;
            uint32_t off = (uint32_t)(row * 128 + ((seg * 16) ^ ((row & 7) << 4)));
            size_t g = kvoff + row * 64 + seg * 8;
            cpa16(base + KV_K + off, g_kf + g);
            cpa16(base + KV_V + off, g_vf + g);
        }
    };

    load_kv(0, 0);
    CP_COMMIT();

    // stage Q (128x64 fp16) into swizzled smem
    const size_t qoff = bhoff + (size_t)qtile * 128 * DD;
#pragma unroll
    for (int i = 0; i < 4; ++i) {
        int unit = i * 256 + tid;           // 1024 units
        int row = unit >> 3, seg = unit & 7;
        uint32_t off = (uint32_t)(row * 128 + ((seg * 16) ^ ((row & 7) << 4)));
        *(uint4*)(smem + AT_Q + off) = *(const uint4*)(g_qf + qoff + row * 64 + seg * 8);
    }
    __syncthreads();

    // per-warp Q A-fragments in regs
    uint32_t qh[4][4];
    {
        int r = lane & 15, hf = lane >> 4;
        int row = wid * 16 + r;
        uint32_t base = (uint32_t)(row * 128);
        uint32_t msk = (uint32_t)((row & 7) << 4);
#pragma unroll
        for (int ks = 0; ks < 4; ++ks)
            ldsm4(qh[ks], sb + AT_Q + base + (uint32_t)((hf * 16 + ks * 32) ^ (int)msk));
    }

    const int rnk = ((lane >> 4) << 3) + (lane & 7);
    const int hfk = (lane >> 3) & 1;
    const int jj  = lane & 15;
    const int dd8 = ((lane >> 4) & 1) * 8;

    float m0 = -1e30f, m1 = -1e30f, l0 = 0.f, l1 = 0.f;
    float o[8][4];
#pragma unroll
    for (int t = 0; t < 8; ++t)
#pragma unroll
        for (int e = 0; e < 4; ++e) o[t][e] = 0.f;

    for (int jt = 0; jt < NN / 64; ++jt) {
        if (jt + 1 < NN / 64) {
            load_kv((jt + 1) & 1, jt + 1);
            CP_COMMIT();
            CP_WAIT(1);
        } else {
            CP_WAIT(0);
        }
        __syncthreads();

        const uint32_t stb = sb + AT_ST0 + (jt & 1) * AT_STAGE;

        // ---- S = Q K^T (single fp16)
        float c[8][4];
#pragma unroll
        for (int t = 0; t < 8; ++t)
#pragma unroll
            for (int e = 0; e < 4; ++e) c[t][e] = 0.f;

#pragma unroll
        for (int ks = 0; ks < 4; ++ks) {
            uint32_t kf[4][4];
#pragma unroll
            for (int nt2 = 0; nt2 < 4; ++nt2) {
                int row = nt2 * 16 + rnk;
                uint32_t koff = (uint32_t)(row * 128)
                              + (uint32_t)((hfk * 16 + ks * 32) ^ ((row & 7) << 4));
                ldsm4(kf[nt2], stb + KV_K + koff);
            }
#pragma unroll
            for (int nt2 = 0; nt2 < 4; ++nt2) {
                uint32_t b0[2] = { kf[nt2][0], kf[nt2][1] };
                uint32_t b1[2] = { kf[nt2][2], kf[nt2][3] };
                mma16816h(c[2 * nt2 + 0], qh[ks], b0);
                mma16816h(c[2 * nt2 + 1], qh[ks], b1);
            }
        }

        // ---- online softmax (rows r0 = lane>>2, r0+8)
        float mx0 = -1e30f, mx1 = -1e30f;
#pragma unroll
        for (int t = 0; t < 8; ++t) {
            mx0 = fmaxf(mx0, fmaxf(c[t][0], c[t][1]));
            mx1 = fmaxf(mx1, fmaxf(c[t][2], c[t][3]));
        }
        mx0 = fmaxf(mx0, __shfl_xor_sync(0xffffffffu, mx0, 1));
        mx0 = fmaxf(mx0, __shfl_xor_sync(0xffffffffu, mx0, 2));
        mx1 = fmaxf(mx1, __shfl_xor_sync(0xffffffffu, mx1, 1));
        mx1 = fmaxf(mx1, __shfl_xor_sync(0xffffffffu, mx1, 2));

        float nm0 = fmaxf(m0, mx0), nm1 = fmaxf(m1, mx1);
        float cr0 = __expf(m0 - nm0), cr1 = __expf(m1 - nm1);
        m0 = nm0; m1 = nm1;
        l0 *= cr0; l1 *= cr1;
#pragma unroll
        for (int t = 0; t < 8; ++t) {
            o[t][0] *= cr0; o[t][1] *= cr0;
            o[t][2] *= cr1; o[t][3] *= cr1;
        }

        // ---- O += P V (single fp16)
#pragma unroll
        for (int ks = 0; ks < 4; ++ks) {
            uint32_t aP[4];
#pragma unroll
            for (int half = 0; half < 2; ++half) {
                int t = 2 * ks + half;
                float p0 = __expf(c[t][0] - nm0);
                float p1 = __expf(c[t][1] - nm0);
                float p2 = __expf(c[t][2] - nm1);
                float p3 = __expf(c[t][3] - nm1);
                l0 += p0 + p1;
                l1 += p2 + p3;
                aP[half ? 2 : 0] = hf2pack(p0, p1);
                aP[half ? 3 : 1] = hf2pack(p2, p3);
            }
            int row = ks * 16 + jj;
            uint32_t rbase = (uint32_t)(row * 128);
            uint32_t msk = (uint32_t)((row & 7) << 4);
#pragma unroll
            for (int dt2 = 0; dt2 < 4; ++dt2) {
                uint32_t off = rbase + (uint32_t)(((dt2 * 16 + dd8) * 2) ^ (int)msk);
                uint32_t v4[4];
                ldsm4t(v4, stb + KV_V + off);
                uint32_t b0[2] = { v4[0], v4[1] };
                uint32_t b1[2] = { v4[2], v4[3] };
                mma16816h(o[2 * dt2 + 0], aP, b0);
                mma16816h(o[2 * dt2 + 1], aP, b1);
            }
        }
        __syncthreads();
    }

    // l is a per-thread partial over 16-of-64 j cols; o holds the full row sum.
    l0 += __shfl_xor_sync(0xffffffffu, l0, 1);
    l0 += __shfl_xor_sync(0xffffffffu, l0, 2);
    l1 += __shfl_xor_sync(0xffffffffu, l1, 1);
    l1 += __shfl_xor_sync(0xffffffffu, l1, 2);

    // ---- epilogue: write fp16 O at [b, n, h*64+d]
    const int b = bh >> 3, h = bh & 7;
    const int gr = wid * 16 + (lane >> 2);
    const float inv0 = 1.f / l0, inv1 = 1.f / l1;
    const int n0 = qtile * 128 + gr;
    const int colb = h * 64 + 2 * (lane & 3);
#pragma unroll
    for (int t = 0; t < 8; ++t) {
        const int d = t * 8;
        {
            size_t idx = (((size_t)(b * NN + n0) * INNERR) + colb + d) >> 1;
            ((uint32_t*)g_of)[idx] = hf2pack(o[t][0] * inv0, o[t][1] * inv0);
        }
        {
            size_t idx = (((size_t)(b * NN + n0 + 8) * INNERR) + colb + d) >> 1;
            ((uint32_t*)g_of)[idx] = hf2pack(o[t][2] * inv1, o[t][3] * inv1);
        }
    }
}

// ---------------------------------------------------------------------------
extern "C" void kernel_launch(void* const* d_in, const int* in_sizes, int n_in,
                              void* d_out, int out_size)
{
    const float* x  = (const float*)d_in[0];
    const float* m  = (const float*)d_in[1];
    const float* Wq = (const float*)d_in[2];
    const float* Wk = (const float*)d_in[3];
    const float* Wv = (const float*)d_in[4];
    const float* Wo = (const float*)d_in[5];
    const float* bo = (const float*)d_in[6];
    float* out = (float*)d_out;

    cudaFuncSetAttribute(attn_mma, cudaFuncAttributeMaxDynamicSharedMemorySize, AT_SMEM);
    cudaFuncSetAttribute(gemm_f16<0>, cudaFuncAttributeMaxDynamicSharedMemorySize, GF_SMEM);
    cudaFuncSetAttribute(gemm_f16<1>, cudaFuncAttributeMaxDynamicSharedMemorySize, GF_SMEM);
    cudaFuncSetAttribute(gemm_f16<2>, cudaFuncAttributeMaxDynamicSharedMemorySize, GF_SMEM);
    cudaFuncSetAttribute(gemm_out, cudaFuncAttributeMaxDynamicSharedMemorySize, GO_SMEM);

    dim3 wg(16, 16), wb(32, 32);
    cvtAf<0><<<8192, 256>>>(x);          // 0
    cvtAf<1><<<8192, 256>>>(m);          // 1
    cvtWf<0><<<wg, wb>>>(Wq);            // 2
    cvtWf<1><<<wg, wb>>>(Wk);            // 3
    cvtWf<2><<<wg, wb>>>(Wv);            // 4

    dim3 gg(4, 128);
    gemm_f16<0><<<gg, 256, GF_SMEM>>>();   // 5  <- ncu -s 5
    gemm_f16<1><<<gg, 256, GF_SMEM>>>();   // 6
    gemm_f16<2><<<gg, 256, GF_SMEM>>>();   // 7

    cvtWo<<<wg, wb>>>(Wo);               // 8

    attn_mma<<<dim3(16, BB * HH), 256, AT_SMEM>>>();  // 9

    gemm_out<<<gg, 256, GO_SMEM>>>(bo, out);          // 10
}

// round 14
// speedup vs baseline: 10.2034x; 1.0338x over previous
#include <cuda_runtime.h>
#include <cuda_bf16.h>
#include <cuda_fp16.h>
#include <cstdint>

// Problem constants
#define BB    8
#define NN    2048
#define DIMM  512
#define HH    8
#define DD    64
#define INNERR 512
#define NSCALE 0.044194173824159216f   // 512^-0.5
#define LOG2E  1.4426950408889634f
#define QSCALE (NSCALE * LOG2E)        // folded so S is in log2 domain

// ---- warp MMA helpers (sm_80+ baseline; no arch-'a' gating) ----
__device__ __forceinline__ void ldsm4(uint32_t* r, uint32_t addr) {
    asm volatile("ldmatrix.sync.aligned.m8n8.x4.shared.b16 {%0,%1,%2,%3}, [%4];"
                 : "=r"(r[0]), "=r"(r[1]), "=r"(r[2]), "=r"(r[3]) : "r"(addr));
}
__device__ __forceinline__ void ldsm4t(uint32_t* r, uint32_t addr) {
    asm volatile("ldmatrix.sync.aligned.m8n8.x4.trans.shared.b16 {%0,%1,%2,%3}, [%4];"
                 : "=r"(r[0]), "=r"(r[1]), "=r"(r[2]), "=r"(r[3]) : "r"(addr));
}
__device__ __forceinline__ void mma16816h(float* c, const uint32_t* a, const uint32_t* b) {
    asm volatile("mma.sync.aligned.m16n8k16.row.col.f32.f16.f16.f32 "
                 "{%0,%1,%2,%3}, {%4,%5,%6,%7}, {%8,%9}, {%0,%1,%2,%3};"
                 : "+f"(c[0]), "+f"(c[1]), "+f"(c[2]), "+f"(c[3])
                 : "r"(a[0]), "r"(a[1]), "r"(a[2]), "r"(a[3]), "r"(b[0]), "r"(b[1]));
}
__device__ __forceinline__ uint32_t smem_to_u32(const void* p) {
    uint32_t a;
    asm("{ .reg .u64 t; cvta.to.shared.u64 t, %1; cvt.u32.u64 %0, t; }"
        : "=r"(a) : "l"(p));
    return a;
}
// ---- cp.async (LDGSTS) ----
__device__ __forceinline__ void cpa16(uint32_t dst, const void* src) {
    asm volatile("cp.async.cg.shared.global [%0], [%1], 16;" :: "r"(dst), "l"(src));
}
#define CP_COMMIT() asm volatile("cp.async.commit_group;" ::: "memory")
#define CP_WAIT(N)  asm volatile("cp.async.wait_group %0;" :: "n"(N) : "memory")

#define SWZ(off) ((off) ^ (((off) >> 3) & 0x70))

__device__ __forceinline__ uint32_t hf2pack(float lo, float hi) {
    __half2 t = __floats2half2_rn(lo, hi);
    return *reinterpret_cast<uint32_t*>(&t);
}

// =========================== scratch (device globals only) =================
#define ACNT ((size_t)16384 * 512)
__device__ unsigned short g_xf[ACNT];               // x fp16
__device__ unsigned short g_mf[ACNT];               // m fp16
__device__ unsigned short g_of[ACNT];               // attention out fp16 [b,n,(h d)]
#define QKV ((size_t)BB * HH * NN * DD)
__device__ unsigned short g_qf[QKV];                // Q*qscale fp16 [b,h,n,d]
__device__ unsigned short g_kf[QKV];                // K fp16
__device__ unsigned short g_vf[QKV];                // V fp16
#define WCNT ((size_t)512 * 512)
__device__ unsigned short g_wqf[WCNT];              // Wq^T fp16
__device__ unsigned short g_wkf[WCNT];              // Wk^T fp16
__device__ unsigned short g_wvf[WCNT];              // Wv^T fp16
__device__ unsigned short g_woh[WCNT], g_wol[WCNT]; // Wo^T fp16 hi/lo

// ---------------------------------------------------------------------------
// cvtA: fp32 [16384,512] -> fp16. blockIdx.y selects x / m.
// ---------------------------------------------------------------------------
__global__ __launch_bounds__(256)
void cvtA(const float* __restrict__ x, const float* __restrict__ m)
{
    const float* src = blockIdx.y ? m : x;
    unsigned short* d = blockIdx.y ? g_mf : g_xf;
    size_t i4 = (size_t)blockIdx.x * 256 + threadIdx.x;
    float4 v = ((const float4*)src)[i4];
    uint2 o;
    o.x = hf2pack(v.x, v.y);
    o.y = hf2pack(v.z, v.w);
    ((uint2*)d)[i4] = o;
}

// ---------------------------------------------------------------------------
// cvtW: all 4 weights, blockIdx.z selects. z<3 -> fp16 transposed plane;
// z==3 -> Wo fp16 hi/lo transposed planes.
// ---------------------------------------------------------------------------
__global__ __launch_bounds__(1024)
void cvtW(const float* __restrict__ Wq, const float* __restrict__ Wk,
          const float* __restrict__ Wv, const float* __restrict__ Wo)
{
    const int z = blockIdx.z;
    const float* W = (z == 0) ? Wq : (z == 1) ? Wk : (z == 2) ? Wv : Wo;
    __shared__ float tile[32][33];
    int k = blockIdx.y * 32 + threadIdx.y;
    int n = blockIdx.x * 32 + threadIdx.x;
    tile[threadIdx.y][threadIdx.x] = W[(size_t)k * 512 + n];
    __syncthreads();
    int nn = blockIdx.x * 32 + threadIdx.y;
    int kk = blockIdx.y * 32 + threadIdx.x;
    float v = tile[threadIdx.x][threadIdx.y];
    size_t idx = (size_t)nn * 512 + kk;
    if (z < 3) {
        unsigned short* d = (z == 0) ? g_wqf : (z == 1) ? g_wkf : g_wvf;
        d[idx] = __half_as_ushort(__float2half_rn(v));
    } else {
        __half hh = __float2half_rn(v);
        float r = v - __half2float(hh);
        g_woh[idx] = __half_as_ushort(hh);
        g_wol[idx] = __half_as_ushort(__float2half_rn(r));
    }
}

// ---------------------------------------------------------------------------
// Fused QKV projection GEMM: grid (12, 128).
// col-blocks 0-3: Q = x @ Wq * QSCALE; 4-7: K = m @ Wk; 8-11: V = m @ Wv.
// Block 128x128, 8 warps, 2-stage cp.async (stage = 32KB). fp16 out, head-split.
// ---------------------------------------------------------------------------
#define GF_SA 0
#define GF_SB 16384
#define GF_STAGE 32768
#define GF_SMEM (2 * GF_STAGE)

__global__ __launch_bounds__(256)
void gemm_qkv()
{
    const int sel = blockIdx.x >> 2;        // 0=Q 1=K 2=V
    const int cb  = blockIdx.x & 3;         // col block within 512
    const unsigned short* A = (sel == 0) ? g_xf : g_mf;
    const unsigned short* B = (sel == 0) ? g_wqf : (sel == 1) ? g_wkf : g_wvf;
    unsigned short* Cf = (sel == 0) ? g_qf : (sel == 1) ? g_kf : g_vf;

    extern __shared__ char smem[];
    const uint32_t sb = smem_to_u32(smem);

    const int tid  = threadIdx.x;
    const int wid  = tid >> 5;
    const int lane = tid & 31;
    const int warp_m = wid >> 2;
    const int warp_n = wid & 3;
    const int rowBase = blockIdx.y * 128;
    const int colBase = cb * 128;

    float c[4][4][4];
#pragma unroll
    for (int i = 0; i < 4; ++i)
#pragma unroll
        for (int j = 0; j < 4; ++j)
#pragma unroll
            for (int e = 0; e < 4; ++e) c[i][j][e] = 0.f;

    uint32_t aAddr[4], maskA[4];
    {
        int r = lane & 15, hf = lane >> 4;
#pragma unroll
        for (int mt = 0; mt < 4; ++mt) {
            uint32_t rb = (uint32_t)((warp_m * 64 + mt * 16 + r) * 128 + hf * 16);
            maskA[mt] = (rb >> 3) & 0x70;
            aAddr[mt] = rb;
        }
    }
    uint32_t bAddr[2], maskB[2];
    {
        int rn = ((lane >> 4) << 3) + (lane & 7);
        int hf = (lane >> 3) & 1;
#pragma unroll
        for (int nt2 = 0; nt2 < 2; ++nt2) {
            uint32_t rb = (uint32_t)((warp_n * 32 + nt2 * 16 + rn) * 128 + hf * 16);
            maskB[nt2] = (rb >> 3) & 0x70;
            bAddr[nt2] = rb;
        }
    }

    auto load_stage = [&](int st, int kc) {
        uint32_t base = sb + st * GF_STAGE;
#pragma unroll
        for (int it = 0; it < 4; ++it) {
            int unit = it * 256 + tid;
            int row = unit >> 3, seg = unit & 7;
            uint32_t off = SWZ((uint32_t)(row * 128 + seg * 16));
            cpa16(base + GF_SA + off, A + (size_t)(rowBase + row) * 512 + kc * 64 + seg * 8);
            cpa16(base + GF_SB + off, B + (size_t)(colBase + row) * 512 + kc * 64 + seg * 8);
        }
    };

    load_stage(0, 0);
    CP_COMMIT();

    for (int kc = 0; kc < 8; ++kc) {
        if (kc + 1 < 8) {
            load_stage((kc + 1) & 1, kc + 1);
            CP_COMMIT();
            CP_WAIT(1);
        } else {
            CP_WAIT(0);
        }
        __syncthreads();

        const uint32_t stb = sb + (kc & 1) * GF_STAGE;
#pragma unroll
        for (int ks = 0; ks < 4; ++ks) {
            uint32_t af[4][4], bf[4][2];
#pragma unroll
            for (int mt = 0; mt < 4; ++mt)
                ldsm4(af[mt], stb + GF_SA + ((aAddr[mt] + ks * 32) ^ maskA[mt]));
#pragma unroll
            for (int nt2 = 0; nt2 < 2; ++nt2) {
                uint32_t t4[4];
                ldsm4(t4, stb + GF_SB + ((bAddr[nt2] + ks * 32) ^ maskB[nt2]));
                bf[2 * nt2][0] = t4[0]; bf[2 * nt2][1] = t4[1];
                bf[2 * nt2 + 1][0] = t4[2]; bf[2 * nt2 + 1][1] = t4[3];
            }
#pragma unroll
            for (int mt = 0; mt < 4; ++mt)
#pragma unroll
                for (int nt = 0; nt < 4; ++nt)
                    mma16816h(c[mt][nt], af[mt], bf[nt]);
        }
        __syncthreads();
    }

    const int r0 = (lane >> 2);
    const int c2 = 2 * (lane & 3);
    const float s = (sel == 0) ? QSCALE : 1.f;
#pragma unroll
    for (int mt = 0; mt < 4; ++mt) {
#pragma unroll
        for (int nt = 0; nt < 4; ++nt) {
            int row = rowBase + warp_m * 64 + mt * 16 + r0;
            int col = colBase + warp_n * 32 + nt * 8 + c2;
            const int h = col >> 6, d0 = col & 63;
#pragma unroll
            for (int half = 0; half < 2; ++half) {
                const int rw = row + half * 8;
                const int b = rw >> 11, n = rw & 2047;
                size_t idx = (((size_t)(b * HH + h) * NN + n) * DD + d0) >> 1;
                ((uint32_t*)Cf)[idx] = hf2pack(c[mt][nt][2 * half + 0] * s,
                                               c[mt][nt][2 * half + 1] * s);
            }
        }
    }
}

// ---------------------------------------------------------------------------
// Final projection: out = O @ (Wo_h + Wo_l) + bias, fp16 2-term, fp32 out.
// Block 128x128, 2-stage cp.async (stage = 3 planes x 16KB = 48KB).
// ---------------------------------------------------------------------------
#define GO_SA  0
#define GO_BH  16384
#define GO_BL  32768
#define GO_STAGE 49152
#define GO_SMEM  (2 * GO_STAGE)

__global__ __launch_bounds__(256)
void gemm_out(const float* __restrict__ bias, float* __restrict__ Cout)
{
    extern __shared__ char smem[];
    const uint32_t sb = smem_to_u32(smem);

    const int tid  = threadIdx.x;
    const int wid  = tid >> 5;
    const int lane = tid & 31;
    const int warp_m = wid >> 2;
    const int warp_n = wid & 3;
    const int rowBase = blockIdx.y * 128;
    const int colBase = blockIdx.x * 128;

    float c[4][4][4];
#pragma unroll
    for (int i = 0; i < 4; ++i)
#pragma unroll
        for (int j = 0; j < 4; ++j)
#pragma unroll
            for (int e = 0; e < 4; ++e) c[i][j][e] = 0.f;

    uint32_t aAddr[4], maskA[4];
    {
        int r = lane & 15, hf = lane >> 4;
#pragma unroll
        for (int mt = 0; mt < 4; ++mt) {
            uint32_t rb = (uint32_t)((warp_m * 64 + mt * 16 + r) * 128 + hf * 16);
            maskA[mt] = (rb >> 3) & 0x70;
            aAddr[mt] = rb;
        }
    }
    uint32_t bAddr[2], maskB[2];
    {
        int rn = ((lane >> 4) << 3) + (lane & 7);
        int hf = (lane >> 3) & 1;
#pragma unroll
        for (int nt2 = 0; nt2 < 2; ++nt2) {
            uint32_t rb = (uint32_t)((warp_n * 32 + nt2 * 16 + rn) * 128 + hf * 16);
            maskB[nt2] = (rb >> 3) & 0x70;
            bAddr[nt2] = rb;
        }
    }

    auto load_stage = [&](int st, int kc) {
        uint32_t base = sb + st * GO_STAGE;
#pragma unroll
        for (int it = 0; it < 4; ++it) {
            int unit = it * 256 + tid;
            int row = unit >> 3, seg = unit & 7;
            uint32_t off = SWZ((uint32_t)(row * 128 + seg * 16));
            size_t ga = (size_t)(rowBase + row) * 512 + kc * 64 + seg * 8;
            size_t gb = (size_t)(colBase + row) * 512 + kc * 64 + seg * 8;
            cpa16(base + GO_SA + off, g_of + ga);
            cpa16(base + GO_BH + off, g_woh + gb);
            cpa16(base + GO_BL + off, g_wol + gb);
        }
    };

    load_stage(0, 0);
    CP_COMMIT();

    for (int kc = 0; kc < 8; ++kc) {
        if (kc + 1 < 8) {
            load_stage((kc + 1) & 1, kc + 1);
            CP_COMMIT();
            CP_WAIT(1);
        } else {
            CP_WAIT(0);
        }
        __syncthreads();

        const uint32_t stb = sb + (kc & 1) * GO_STAGE;
#pragma unroll
        for (int ks = 0; ks < 4; ++ks) {
            uint32_t af[4][4], bh[4][2], bl[4][2];
#pragma unroll
            for (int mt = 0; mt < 4; ++mt)
                ldsm4(af[mt], stb + GO_SA + ((aAddr[mt] + ks * 32) ^ maskA[mt]));
#pragma unroll
            for (int nt2 = 0; nt2 < 2; ++nt2) {
                uint32_t o = ((bAddr[nt2] + ks * 32) ^ maskB[nt2]);
                uint32_t t4[4];
                ldsm4(t4, stb + GO_BH + o);
                bh[2 * nt2][0] = t4[0]; bh[2 * nt2][1] = t4[1];
                bh[2 * nt2 + 1][0] = t4[2]; bh[2 * nt2 + 1][1] = t4[3];
                ldsm4(t4, stb + GO_BL + o);
                bl[2 * nt2][0] = t4[0]; bl[2 * nt2][1] = t4[1];
                bl[2 * nt2 + 1][0] = t4[2]; bl[2 * nt2 + 1][1] = t4[3];
            }
#pragma unroll
            for (int mt = 0; mt < 4; ++mt)
#pragma unroll
                for (int nt = 0; nt < 4; ++nt) {
                    mma16816h(c[mt][nt], af[mt], bh[nt]);
                    mma16816h(c[mt][nt], af[mt], bl[nt]);
                }
        }
        __syncthreads();
    }

    const int r0 = (lane >> 2);
    const int c2 = 2 * (lane & 3);
#pragma unroll
    for (int mt = 0; mt < 4; ++mt) {
#pragma unroll
        for (int nt = 0; nt < 4; ++nt) {
            int row = rowBase + warp_m * 64 + mt * 16 + r0;
            int col = colBase + warp_n * 32 + nt * 8 + c2;
            float2 bv = *(const float2*)&bias[col];
            float* p0 = Cout + (size_t)row * 512 + col;
            *(float2*)p0 = make_float2(c[mt][nt][0] + bv.x, c[mt][nt][1] + bv.y);
            float* p1 = Cout + (size_t)(row + 8) * 512 + col;
            *(float2*)p1 = make_float2(c[mt][nt][2] + bv.x, c[mt][nt][3] + bv.y);
        }
    }
}

// ---------------------------------------------------------------------------
// Flash attention, single-fp16 MMA, log2-domain softmax (Q has QSCALE baked,
// so S is in log2 units; p = exp2f(s - m)). BM=128 (8 warps), KV tiles 64.
// 2-stage cp.async KV pipeline. O written as fp16.
// smem: Q 16K | stage0 16K | stage1 16K = 48 KB.
// ---------------------------------------------------------------------------
#define AT_Q 0
#define AT_ST0 16384
#define AT_STAGE 16384
#define KV_K 0
#define KV_V 8192
#define AT_SMEM (AT_ST0 + 2 * AT_STAGE)

__global__ __launch_bounds__(256)
void attn_mma()
{
    extern __shared__ char smem[];
    const uint32_t sb = smem_to_u32(smem);
    const int tid = threadIdx.x, wid = tid >> 5, lane = tid & 31;
    const int bh = blockIdx.y, qtile = blockIdx.x;

    const size_t bhoff = (size_t)bh * NN * DD;

    auto load_kv = [&](int st, int jt) {
        uint32_t base = sb + AT_ST0 + st * AT_STAGE;
        const size_t kvoff = bhoff + (size_t)jt * 64 * DD;
#pragma unroll
        for (int i = 0; i < 2; ++i) {
            int unit = i * 256 + tid;
            int row = unit >> 3, seg = unit & 7;
            uint32_t off = (uint32_t)(row * 128 + ((seg * 16) ^ ((row & 7) << 4)));
            size_t g = kvoff + row * 64 + seg * 8;
            cpa16(base + KV_K + off, g_kf + g);
            cpa16(base + KV_V + off, g_vf + g);
        }
    };

    load_kv(0, 0);
    CP_COMMIT();

    const size_t qoff = bhoff + (size_t)qtile * 128 * DD;
#pragma unroll
    for (int i = 0; i < 4; ++i) {
        int unit = i * 256 + tid;
        int row = unit >> 3, seg = unit & 7;
        uint32_t off = (uint32_t)(row * 128 + ((seg * 16) ^ ((row & 7) << 4)));
        *(uint4*)(smem + AT_Q + off) = *(const uint4*)(g_qf + qoff + row * 64 + seg * 8);
    }
    __syncthreads();

    uint32_t qh[4][4];
    {
        int r = lane & 15, hf = lane >> 4;
        int row = wid * 16 + r;
        uint32_t base = (uint32_t)(row * 128);
        uint32_t msk = (uint32_t)((row & 7) << 4);
#pragma unroll
        for (int ks = 0; ks < 4; ++ks)
            ldsm4(qh[ks], sb + AT_Q + base + (uint32_t)((hf * 16 + ks * 32) ^ (int)msk));
    }

    const int rnk = ((lane >> 4) << 3) + (lane & 7);
    const int hfk = (lane >> 3) & 1;
    const int jj  = lane & 15;
    const int dd8 = ((lane >> 4) & 1) * 8;

    float m0 = -1e30f, m1 = -1e30f, l0 = 0.f, l1 = 0.f;
    float o[8][4];
#pragma unroll
    for (int t = 0; t < 8; ++t)
#pragma unroll
        for (int e = 0; e < 4; ++e) o[t][e] = 0.f;

    for (int jt = 0; jt < NN / 64; ++jt) {
        if (jt + 1 < NN / 64) {
            load_kv((jt + 1) & 1, jt + 1);
            CP_COMMIT();
            CP_WAIT(1);
        } else {
            CP_WAIT(0);
        }
        __syncthreads();

        const uint32_t stb = sb + AT_ST0 + (jt & 1) * AT_STAGE;

        // ---- S = Q K^T (log2-domain scores)
        float c[8][4];
#pragma unroll
        for (int t = 0; t < 8; ++t)
#pragma unroll
            for (int e = 0; e < 4; ++e) c[t][e] = 0.f;

#pragma unroll
        for (int ks = 0; ks < 4; ++ks) {
            uint32_t kf[4][4];
#pragma unroll
            for (int nt2 = 0; nt2 < 4; ++nt2) {
                int row = nt2 * 16 + rnk;
                uint32_t koff = (uint32_t)(row * 128)
                              + (uint32_t)((hfk * 16 + ks * 32) ^ ((row & 7) << 4));
                ldsm4(kf[nt2], stb + KV_K + koff);
            }
#pragma unroll
            for (int nt2 = 0; nt2 < 4; ++nt2) {
                uint32_t b0[2] = { kf[nt2][0], kf[nt2][1] };
                uint32_t b1[2] = { kf[nt2][2], kf[nt2][3] };
                mma16816h(c[2 * nt2 + 0], qh[ks], b0);
                mma16816h(c[2 * nt2 + 1], qh[ks], b1);
            }
        }

        // ---- online softmax (base-2)
        float mx0 = -1e30f, mx1 = -1e30f;
#pragma unroll
        for (int t = 0; t < 8; ++t) {
            mx0 = fmaxf(mx0, fmaxf(c[t][0], c[t][1]));
            mx1 = fmaxf(mx1, fmaxf(c[t][2], c[t][3]));
        }
        mx0 = fmaxf(mx0, __shfl_xor_sync(0xffffffffu, mx0, 1));
        mx0 = fmaxf(mx0, __shfl_xor_sync(0xffffffffu, mx0, 2));
        mx1 = fmaxf(mx1, __shfl_xor_sync(0xffffffffu, mx1, 1));
        mx1 = fmaxf(mx1, __shfl_xor_sync(0xffffffffu, mx1, 2));

        float nm0 = fmaxf(m0, mx0), nm1 = fmaxf(m1, mx1);
        float cr0 = exp2f(m0 - nm0), cr1 = exp2f(m1 - nm1);
        m0 = nm0; m1 = nm1;
        l0 *= cr0; l1 *= cr1;
#pragma unroll
        for (int t = 0; t < 8; ++t) {
            o[t][0] *= cr0; o[t][1] *= cr0;
            o[t][2] *= cr1; o[t][3] *= cr1;
        }

        // ---- O += P V (single fp16)
#pragma unroll
        for (int ks = 0; ks < 4; ++ks) {
            uint32_t aP[4];
#pragma unroll
            for (int half = 0; half < 2; ++half) {
                int t = 2 * ks + half;
                float p0 = exp2f(c[t][0] - nm0);
                float p1 = exp2f(c[t][1] - nm0);
                float p2 = exp2f(c[t][2] - nm1);
                float p3 = exp2f(c[t][3] - nm1);
                l0 += p0 + p1;
                l1 += p2 + p3;
                aP[half ? 2 : 0] = hf2pack(p0, p1);
                aP[half ? 3 : 1] = hf2pack(p2, p3);
            }
            int row = ks * 16 + jj;
            uint32_t rbase = (uint32_t)(row * 128);
            uint32_t msk = (uint32_t)((row & 7) << 4);
#pragma unroll
            for (int dt2 = 0; dt2 < 4; ++dt2) {
                uint32_t off = rbase + (uint32_t)(((dt2 * 16 + dd8) * 2) ^ (int)msk);
                uint32_t v4[4];
                ldsm4t(v4, stb + KV_V + off);
                uint32_t b0[2] = { v4[0], v4[1] };
                uint32_t b1[2] = { v4[2], v4[3] };
                mma16816h(o[2 * dt2 + 0], aP, b0);
                mma16816h(o[2 * dt2 + 1], aP, b1);
            }
        }
        __syncthreads();
    }

    // quad-reduce l (o already holds the full row sum via MMA k-reduction)
    l0 += __shfl_xor_sync(0xffffffffu, l0, 1);
    l0 += __shfl_xor_sync(0xffffffffu, l0, 2);
    l1 += __shfl_xor_sync(0xffffffffu, l1, 1);
    l1 += __shfl_xor_sync(0xffffffffu, l1, 2);

    // ---- epilogue: write fp16 O at [b, n, h*64+d]
    const int b = bh >> 3, h = bh & 7;
    const int gr = wid * 16 + (lane >> 2);
    const float inv0 = 1.f / l0, inv1 = 1.f / l1;
    const int n0 = qtile * 128 + gr;
    const int colb = h * 64 + 2 * (lane & 3);
#pragma unroll
    for (int t = 0; t < 8; ++t) {
        const int d = t * 8;
        {
            size_t idx = (((size_t)(b * NN + n0) * INNERR) + colb + d) >> 1;
            ((uint32_t*)g_of)[idx] = hf2pack(o[t][0] * inv0, o[t][1] * inv0);
        }
        {
            size_t idx = (((size_t)(b * NN + n0 + 8) * INNERR) + colb + d) >> 1;
            ((uint32_t*)g_of)[idx] = hf2pack(o[t][2] * inv1, o[t][3] * inv1);
        }
    }
}

// ---------------------------------------------------------------------------
extern "C" void kernel_launch(void* const* d_in, const int* in_sizes, int n_in,
                              void* d_out, int out_size)
{
    const float* x  = (const float*)d_in[0];
    const float* m  = (const float*)d_in[1];
    const float* Wq = (const float*)d_in[2];
    const float* Wk = (const float*)d_in[3];
    const float* Wv = (const float*)d_in[4];
    const float* Wo = (const float*)d_in[5];
    const float* bo = (const float*)d_in[6];
    float* out = (float*)d_out;

    cudaFuncSetAttribute(attn_mma, cudaFuncAttributeMaxDynamicSharedMemorySize, AT_SMEM);
    cudaFuncSetAttribute(gemm_qkv, cudaFuncAttributeMaxDynamicSharedMemorySize, GF_SMEM);
    cudaFuncSetAttribute(gemm_out, cudaFuncAttributeMaxDynamicSharedMemorySize, GO_SMEM);

    cvtA<<<dim3(8192, 2), 256>>>(x, m);                       // 0
    cvtW<<<dim3(16, 16, 4), dim3(32, 32)>>>(Wq, Wk, Wv, Wo);  // 1
    gemm_qkv<<<dim3(12, 128), 256, GF_SMEM>>>();              // 2
    attn_mma<<<dim3(16, BB * HH), 256, AT_SMEM>>>();          // 3 <- likely profiled
    gemm_out<<<dim3(4, 128), 256, GO_SMEM>>>(bo, out);        // 4
}

// round 15
// speedup vs baseline: 11.1919x; 1.0969x over previous
#include <cuda_runtime.h>
#include <cuda_bf16.h>
#include <cuda_fp16.h>
#include <cstdint>

// Problem constants
#define BB    8
#define NN    2048
#define DIMM  512
#define HH    8
#define DD    64
#define INNERR 512
#define NSCALE 0.044194173824159216f   // 512^-0.5
#define LOG2E  1.4426950408889634f
#define QSCALE (NSCALE * LOG2E)        // folded so S is in log2 domain

// ---- warp MMA helpers (sm_80+ baseline; no arch-'a' gating) ----
__device__ __forceinline__ void ldsm4(uint32_t* r, uint32_t addr) {
    asm volatile("ldmatrix.sync.aligned.m8n8.x4.shared.b16 {%0,%1,%2,%3}, [%4];"
                 : "=r"(r[0]), "=r"(r[1]), "=r"(r[2]), "=r"(r[3]) : "r"(addr));
}
__device__ __forceinline__ void ldsm4t(uint32_t* r, uint32_t addr) {
    asm volatile("ldmatrix.sync.aligned.m8n8.x4.trans.shared.b16 {%0,%1,%2,%3}, [%4];"
                 : "=r"(r[0]), "=r"(r[1]), "=r"(r[2]), "=r"(r[3]) : "r"(addr));
}
__device__ __forceinline__ void mma16816h(float* c, const uint32_t* a, const uint32_t* b) {
    asm volatile("mma.sync.aligned.m16n8k16.row.col.f32.f16.f16.f32 "
                 "{%0,%1,%2,%3}, {%4,%5,%6,%7}, {%8,%9}, {%0,%1,%2,%3};"
                 : "+f"(c[0]), "+f"(c[1]), "+f"(c[2]), "+f"(c[3])
                 : "r"(a[0]), "r"(a[1]), "r"(a[2]), "r"(a[3]), "r"(b[0]), "r"(b[1]));
}
__device__ __forceinline__ uint32_t smem_to_u32(const void* p) {
    uint32_t a;
    asm("{ .reg .u64 t; cvta.to.shared.u64 t, %1; cvt.u32.u64 %0, t; }"
        : "=r"(a) : "l"(p));
    return a;
}
// ---- cp.async (LDGSTS) ----
__device__ __forceinline__ void cpa16(uint32_t dst, const void* src) {
    asm volatile("cp.async.cg.shared.global [%0], [%1], 16;" :: "r"(dst), "l"(src));
}
#define CP_COMMIT() asm volatile("cp.async.commit_group;" ::: "memory")
#define CP_WAIT(N)  asm volatile("cp.async.wait_group %0;" :: "n"(N) : "memory")

#define SWZ(off) ((off) ^ (((off) >> 3) & 0x70))

__device__ __forceinline__ uint32_t hf2pack(float lo, float hi) {
    __half2 t = __floats2half2_rn(lo, hi);
    return *reinterpret_cast<uint32_t*>(&t);
}

// =========================== scratch (device globals only) =================
#define ACNT ((size_t)16384 * 512)
__device__ unsigned short g_xf[ACNT];               // x fp16
__device__ unsigned short g_mf[ACNT];               // m fp16
__device__ unsigned short g_of[ACNT];               // attention out fp16 [b,n,(h d)]
#define QKV ((size_t)BB * HH * NN * DD)
__device__ unsigned short g_qf[QKV];                // Q*qscale fp16 [b,h,n,d]
__device__ unsigned short g_kf[QKV];                // K fp16
__device__ unsigned short g_vf[QKV];                // V fp16
#define WCNT ((size_t)512 * 512)
__device__ unsigned short g_wqf[WCNT];              // Wq^T fp16
__device__ unsigned short g_wkf[WCNT];              // Wk^T fp16
__device__ unsigned short g_wvf[WCNT];              // Wv^T fp16
__device__ unsigned short g_woh[WCNT], g_wol[WCNT]; // Wo^T fp16 hi/lo

// ---------------------------------------------------------------------------
// cvtA: fp32 [16384,512] -> fp16. blockIdx.y selects x / m.
// ---------------------------------------------------------------------------
__global__ __launch_bounds__(256)
void cvtA(const float* __restrict__ x, const float* __restrict__ m)
{
    const float* src = blockIdx.y ? m : x;
    unsigned short* d = blockIdx.y ? g_mf : g_xf;
    size_t i4 = (size_t)blockIdx.x * 256 + threadIdx.x;
    float4 v = ((const float4*)src)[i4];
    uint2 o;
    o.x = hf2pack(v.x, v.y);
    o.y = hf2pack(v.z, v.w);
    ((uint2*)d)[i4] = o;
}

// ---------------------------------------------------------------------------
// cvtW: all 4 weights, blockIdx.z selects. z<3 -> fp16 transposed plane;
// z==3 -> Wo fp16 hi/lo transposed planes.
// ---------------------------------------------------------------------------
__global__ __launch_bounds__(1024)
void cvtW(const float* __restrict__ Wq, const float* __restrict__ Wk,
          const float* __restrict__ Wv, const float* __restrict__ Wo)
{
    const int z = blockIdx.z;
    const float* W = (z == 0) ? Wq : (z == 1) ? Wk : (z == 2) ? Wv : Wo;
    __shared__ float tile[32][33];
    int k = blockIdx.y * 32 + threadIdx.y;
    int n = blockIdx.x * 32 + threadIdx.x;
    tile[threadIdx.y][threadIdx.x] = W[(size_t)k * 512 + n];
    __syncthreads();
    int nn = blockIdx.x * 32 + threadIdx.y;
    int kk = blockIdx.y * 32 + threadIdx.x;
    float v = tile[threadIdx.x][threadIdx.y];
    size_t idx = (size_t)nn * 512 + kk;
    if (z < 3) {
        unsigned short* d = (z == 0) ? g_wqf : (z == 1) ? g_wkf : g_wvf;
        d[idx] = __half_as_ushort(__float2half_rn(v));
    } else {
        __half hh = __float2half_rn(v);
        float r = v - __half2float(hh);
        g_woh[idx] = __half_as_ushort(hh);
        g_wol[idx] = __half_as_ushort(__float2half_rn(r));
    }
}

// ---------------------------------------------------------------------------
// Fused QKV projection GEMM: grid (12, 128).
// col-blocks 0-3: Q = x @ Wq * QSCALE; 4-7: K = m @ Wk; 8-11: V = m @ Wv.
// Block 128x128, 8 warps, 2-stage cp.async (stage = 32KB). fp16 out, head-split.
// ---------------------------------------------------------------------------
#define GF_SA 0
#define GF_SB 16384
#define GF_STAGE 32768
#define GF_SMEM (2 * GF_STAGE)

__global__ __launch_bounds__(256)
void gemm_qkv()
{
    const int sel = blockIdx.x >> 2;        // 0=Q 1=K 2=V
    const int cb  = blockIdx.x & 3;         // col block within 512
    const unsigned short* A = (sel == 0) ? g_xf : g_mf;
    const unsigned short* B = (sel == 0) ? g_wqf : (sel == 1) ? g_wkf : g_wvf;
    unsigned short* Cf = (sel == 0) ? g_qf : (sel == 1) ? g_kf : g_vf;

    extern __shared__ char smem[];
    const uint32_t sb = smem_to_u32(smem);

    const int tid  = threadIdx.x;
    const int wid  = tid >> 5;
    const int lane = tid & 31;
    const int warp_m = wid >> 2;
    const int warp_n = wid & 3;
    const int rowBase = blockIdx.y * 128;
    const int colBase = cb * 128;

    float c[4][4][4];
#pragma unroll
    for (int i = 0; i < 4; ++i)
#pragma unroll
        for (int j = 0; j < 4; ++j)
#pragma unroll
            for (int e = 0; e < 4; ++e) c[i][j][e] = 0.f;

    uint32_t aAddr[4], maskA[4];
    {
        int r = lane & 15, hf = lane >> 4;
#pragma unroll
        for (int mt = 0; mt < 4; ++mt) {
            uint32_t rb = (uint32_t)((warp_m * 64 + mt * 16 + r) * 128 + hf * 16);
            maskA[mt] = (rb >> 3) & 0x70;
            aAddr[mt] = rb;
        }
    }
    uint32_t bAddr[2], maskB[2];
    {
        int rn = ((lane >> 4) << 3) + (lane & 7);
        int hf = (lane >> 3) & 1;
#pragma unroll
        for (int nt2 = 0; nt2 < 2; ++nt2) {
            uint32_t rb = (uint32_t)((warp_n * 32 + nt2 * 16 + rn) * 128 + hf * 16);
            maskB[nt2] = (rb >> 3) & 0x70;
            bAddr[nt2] = rb;
        }
    }

    auto load_stage = [&](int st, int kc) {
        uint32_t base = sb + st * GF_STAGE;
#pragma unroll
        for (int it = 0; it < 4; ++it) {
            int unit = it * 256 + tid;
            int row = unit >> 3, seg = unit & 7;
            uint32_t off = SWZ((uint32_t)(row * 128 + seg * 16));
            cpa16(base + GF_SA + off, A + (size_t)(rowBase + row) * 512 + kc * 64 + seg * 8);
            cpa16(base + GF_SB + off, B + (size_t)(colBase + row) * 512 + kc * 64 + seg * 8);
        }
    };

    load_stage(0, 0);
    CP_COMMIT();

    for (int kc = 0; kc < 8; ++kc) {
        if (kc + 1 < 8) {
            load_stage((kc + 1) & 1, kc + 1);
            CP_COMMIT();
            CP_WAIT(1);
        } else {
            CP_WAIT(0);
        }
        __syncthreads();

        const uint32_t stb = sb + (kc & 1) * GF_STAGE;
#pragma unroll
        for (int ks = 0; ks < 4; ++ks) {
            uint32_t af[4][4], bf[4][2];
#pragma unroll
            for (int mt = 0; mt < 4; ++mt)
                ldsm4(af[mt], stb + GF_SA + ((aAddr[mt] + ks * 32) ^ maskA[mt]));
#pragma unroll
            for (int nt2 = 0; nt2 < 2; ++nt2) {
                uint32_t t4[4];
                ldsm4(t4, stb + GF_SB + ((bAddr[nt2] + ks * 32) ^ maskB[nt2]));
                bf[2 * nt2][0] = t4[0]; bf[2 * nt2][1] = t4[1];
                bf[2 * nt2 + 1][0] = t4[2]; bf[2 * nt2 + 1][1] = t4[3];
            }
#pragma unroll
            for (int mt = 0; mt < 4; ++mt)
#pragma unroll
                for (int nt = 0; nt < 4; ++nt)
                    mma16816h(c[mt][nt], af[mt], bf[nt]);
        }
        __syncthreads();
    }

    const int r0 = (lane >> 2);
    const int c2 = 2 * (lane & 3);
    const float s = (sel == 0) ? QSCALE : 1.f;
#pragma unroll
    for (int mt = 0; mt < 4; ++mt) {
#pragma unroll
        for (int nt = 0; nt < 4; ++nt) {
            int row = rowBase + warp_m * 64 + mt * 16 + r0;
            int col = colBase + warp_n * 32 + nt * 8 + c2;
            const int h = col >> 6, d0 = col & 63;
#pragma unroll
            for (int half = 0; half < 2; ++half) {
                const int rw = row + half * 8;
                const int b = rw >> 11, n = rw & 2047;
                size_t idx = (((size_t)(b * HH + h) * NN + n) * DD + d0) >> 1;
                ((uint32_t*)Cf)[idx] = hf2pack(c[mt][nt][2 * half + 0] * s,
                                               c[mt][nt][2 * half + 1] * s);
            }
        }
    }
}

// ---------------------------------------------------------------------------
// Final projection: out = O @ (Wo_h + Wo_l) + bias, fp16 2-term, fp32 out.
// Block 128x128, 2-stage cp.async (stage = 3 planes x 16KB = 48KB).
// ---------------------------------------------------------------------------
#define GO_SA  0
#define GO_BH  16384
#define GO_BL  32768
#define GO_STAGE 49152
#define GO_SMEM  (2 * GO_STAGE)

__global__ __launch_bounds__(256)
void gemm_out(const float* __restrict__ bias, float* __restrict__ Cout)
{
    extern __shared__ char smem[];
    const uint32_t sb = smem_to_u32(smem);

    const int tid  = threadIdx.x;
    const int wid  = tid >> 5;
    const int lane = tid & 31;
    const int warp_m = wid >> 2;
    const int warp_n = wid & 3;
    const int rowBase = blockIdx.y * 128;
    const int colBase = blockIdx.x * 128;

    float c[4][4][4];
#pragma unroll
    for (int i = 0; i < 4; ++i)
#pragma unroll
        for (int j = 0; j < 4; ++j)
#pragma unroll
            for (int e = 0; e < 4; ++e) c[i][j][e] = 0.f;

    uint32_t aAddr[4], maskA[4];
    {
        int r = lane & 15, hf = lane >> 4;
#pragma unroll
        for (int mt = 0; mt < 4; ++mt) {
            uint32_t rb = (uint32_t)((warp_m * 64 + mt * 16 + r) * 128 + hf * 16);
            maskA[mt] = (rb >> 3) & 0x70;
            aAddr[mt] = rb;
        }
    }
    uint32_t bAddr[2], maskB[2];
    {
        int rn = ((lane >> 4) << 3) + (lane & 7);
        int hf = (lane >> 3) & 1;
#pragma unroll
        for (int nt2 = 0; nt2 < 2; ++nt2) {
            uint32_t rb = (uint32_t)((warp_n * 32 + nt2 * 16 + rn) * 128 + hf * 16);
            maskB[nt2] = (rb >> 3) & 0x70;
            bAddr[nt2] = rb;
        }
    }

    auto load_stage = [&](int st, int kc) {
        uint32_t base = sb + st * GO_STAGE;
#pragma unroll
        for (int it = 0; it < 4; ++it) {
            int unit = it * 256 + tid;
            int row = unit >> 3, seg = unit & 7;
            uint32_t off = SWZ((uint32_t)(row * 128 + seg * 16));
            size_t ga = (size_t)(rowBase + row) * 512 + kc * 64 + seg * 8;
            size_t gb = (size_t)(colBase + row) * 512 + kc * 64 + seg * 8;
            cpa16(base + GO_SA + off, g_of + ga);
            cpa16(base + GO_BH + off, g_woh + gb);
            cpa16(base + GO_BL + off, g_wol + gb);
        }
    };

    load_stage(0, 0);
    CP_COMMIT();

    for (int kc = 0; kc < 8; ++kc) {
        if (kc + 1 < 8) {
            load_stage((kc + 1) & 1, kc + 1);
            CP_COMMIT();
            CP_WAIT(1);
        } else {
            CP_WAIT(0);
        }
        __syncthreads();

        const uint32_t stb = sb + (kc & 1) * GO_STAGE;
#pragma unroll
        for (int ks = 0; ks < 4; ++ks) {
            uint32_t af[4][4], bh[4][2], bl[4][2];
#pragma unroll
            for (int mt = 0; mt < 4; ++mt)
                ldsm4(af[mt], stb + GO_SA + ((aAddr[mt] + ks * 32) ^ maskA[mt]));
#pragma unroll
            for (int nt2 = 0; nt2 < 2; ++nt2) {
                uint32_t o = ((bAddr[nt2] + ks * 32) ^ maskB[nt2]);
                uint32_t t4[4];
                ldsm4(t4, stb + GO_BH + o);
                bh[2 * nt2][0] = t4[0]; bh[2 * nt2][1] = t4[1];
                bh[2 * nt2 + 1][0] = t4[2]; bh[2 * nt2 + 1][1] = t4[3];
                ldsm4(t4, stb + GO_BL + o);
                bl[2 * nt2][0] = t4[0]; bl[2 * nt2][1] = t4[1];
                bl[2 * nt2 + 1][0] = t4[2]; bl[2 * nt2 + 1][1] = t4[3];
            }
#pragma unroll
            for (int mt = 0; mt < 4; ++mt)
#pragma unroll
                for (int nt = 0; nt < 4; ++nt) {
                    mma16816h(c[mt][nt], af[mt], bh[nt]);
                    mma16816h(c[mt][nt], af[mt], bl[nt]);
                }
        }
        __syncthreads();
    }

    const int r0 = (lane >> 2);
    const int c2 = 2 * (lane & 3);
#pragma unroll
    for (int mt = 0; mt < 4; ++mt) {
#pragma unroll
        for (int nt = 0; nt < 4; ++nt) {
            int row = rowBase + warp_m * 64 + mt * 16 + r0;
            int col = colBase + warp_n * 32 + nt * 8 + c2;
            float2 bv = *(const float2*)&bias[col];
            float* p0 = Cout + (size_t)row * 512 + col;
            *(float2*)p0 = make_float2(c[mt][nt][0] + bv.x, c[mt][nt][1] + bv.y);
            float* p1 = Cout + (size_t)(row + 8) * 512 + col;
            *(float2*)p1 = make_float2(c[mt][nt][2] + bv.x, c[mt][nt][3] + bv.y);
        }
    }
}

// ---------------------------------------------------------------------------
// Flash attention, single-fp16 MMA, log2 softmax. 4 warps x 32 q-rows
// (2 row-groups of 16 per warp) -> each K/V fragment feeds 2x the MMAs,
// halving CTA ldsm traffic (L1 was the top pipe at 57%).
// BM=128, KV tiles 64, 128 threads, 2-stage cp.async.
// smem: Q 16K | stage0 16K | stage1 16K = 48 KB.
// ---------------------------------------------------------------------------
#define AT_Q 0
#define AT_ST0 16384
#define AT_STAGE 16384
#define KV_K 0
#define KV_V 8192
#define AT_SMEM (AT_ST0 + 2 * AT_STAGE)

__global__ __launch_bounds__(128)
void attn_mma()
{
    extern __shared__ char smem[];
    const uint32_t sb = smem_to_u32(smem);
    const int tid = threadIdx.x, wid = tid >> 5, lane = tid & 31;
    const int bh = blockIdx.y, qtile = blockIdx.x;

    const size_t bhoff = (size_t)bh * NN * DD;

    auto load_kv = [&](int st, int jt) {
        uint32_t base = sb + AT_ST0 + st * AT_STAGE;
        const size_t kvoff = bhoff + (size_t)jt * 64 * DD;
#pragma unroll
        for (int i = 0; i < 4; ++i) {
            int unit = i * 128 + tid;        // 512 units per plane
            int row = unit >> 3, seg = unit & 7;
            uint32_t off = (uint32_t)(row * 128 + ((seg * 16) ^ ((row & 7) << 4)));
            size_t g = kvoff + row * 64 + seg * 8;
            cpa16(base + KV_K + off, g_kf + g);
            cpa16(base + KV_V + off, g_vf + g);
        }
    };

    load_kv(0, 0);
    CP_COMMIT();

    const size_t qoff = bhoff + (size_t)qtile * 128 * DD;
#pragma unroll
    for (int i = 0; i < 8; ++i) {
        int unit = i * 128 + tid;           // 1024 units
        int row = unit >> 3, seg = unit & 7;
        uint32_t off = (uint32_t)(row * 128 + ((seg * 16) ^ ((row & 7) << 4)));
        *(uint4*)(smem + AT_Q + off) = *(const uint4*)(g_qf + qoff + row * 64 + seg * 8);
    }
    __syncthreads();

    // per-warp Q A-fragments: 2 row-groups of 16 rows
    uint32_t qh[2][4][4];
    {
        int r = lane & 15, hf = lane >> 4;
#pragma unroll
        for (int rg = 0; rg < 2; ++rg) {
            int row = wid * 32 + rg * 16 + r;
            uint32_t base = (uint32_t)(row * 128);
            uint32_t msk = (uint32_t)((row & 7) << 4);
#pragma unroll
            for (int ks = 0; ks < 4; ++ks)
                ldsm4(qh[rg][ks], sb + AT_Q + base + (uint32_t)((hf * 16 + ks * 32) ^ (int)msk));
        }
    }

    const int rnk = ((lane >> 4) << 3) + (lane & 7);
    const int hfk = (lane >> 3) & 1;
    const int jj  = lane & 15;
    const int dd8 = ((lane >> 4) & 1) * 8;

    float m[2][2], l[2][2];
#pragma unroll
    for (int rg = 0; rg < 2; ++rg) {
        m[rg][0] = -1e30f; m[rg][1] = -1e30f;
        l[rg][0] = 0.f;    l[rg][1] = 0.f;
    }
    float o[2][8][4];
#pragma unroll
    for (int rg = 0; rg < 2; ++rg)
#pragma unroll
        for (int t = 0; t < 8; ++t)
#pragma unroll
            for (int e = 0; e < 4; ++e) o[rg][t][e] = 0.f;

    for (int jt = 0; jt < NN / 64; ++jt) {
        if (jt + 1 < NN / 64) {
            load_kv((jt + 1) & 1, jt + 1);
            CP_COMMIT();
            CP_WAIT(1);
        } else {
            CP_WAIT(0);
        }
        __syncthreads();

        const uint32_t stb = sb + AT_ST0 + (jt & 1) * AT_STAGE;

        // ---- S = Q K^T (both row-groups share each K fragment)
        float c[2][8][4];
#pragma unroll
        for (int rg = 0; rg < 2; ++rg)
#pragma unroll
            for (int t = 0; t < 8; ++t)
#pragma unroll
                for (int e = 0; e < 4; ++e) c[rg][t][e] = 0.f;

#pragma unroll
        for (int ks = 0; ks < 4; ++ks) {
            uint32_t kf[4][4];
#pragma unroll
            for (int nt2 = 0; nt2 < 4; ++nt2) {
                int row = nt2 * 16 + rnk;
                uint32_t koff = (uint32_t)(row * 128)
                              + (uint32_t)((hfk * 16 + ks * 32) ^ ((row & 7) << 4));
                ldsm4(kf[nt2], stb + KV_K + koff);
            }
#pragma unroll
            for (int nt2 = 0; nt2 < 4; ++nt2) {
                uint32_t b0[2] = { kf[nt2][0], kf[nt2][1] };
                uint32_t b1[2] = { kf[nt2][2], kf[nt2][3] };
#pragma unroll
                for (int rg = 0; rg < 2; ++rg) {
                    mma16816h(c[rg][2 * nt2 + 0], qh[rg][ks], b0);
                    mma16816h(c[rg][2 * nt2 + 1], qh[rg][ks], b1);
                }
            }
        }

        // ---- online softmax (base-2) per row-group
#pragma unroll
        for (int rg = 0; rg < 2; ++rg) {
            float mx0 = -1e30f, mx1 = -1e30f;
#pragma unroll
            for (int t = 0; t < 8; ++t) {
                mx0 = fmaxf(mx0, fmaxf(c[rg][t][0], c[rg][t][1]));
                mx1 = fmaxf(mx1, fmaxf(c[rg][t][2], c[rg][t][3]));
            }
            mx0 = fmaxf(mx0, __shfl_xor_sync(0xffffffffu, mx0, 1));
            mx0 = fmaxf(mx0, __shfl_xor_sync(0xffffffffu, mx0, 2));
            mx1 = fmaxf(mx1, __shfl_xor_sync(0xffffffffu, mx1, 1));
            mx1 = fmaxf(mx1, __shfl_xor_sync(0xffffffffu, mx1, 2));

            float nm0 = fmaxf(m[rg][0], mx0), nm1 = fmaxf(m[rg][1], mx1);
            float cr0 = exp2f(m[rg][0] - nm0), cr1 = exp2f(m[rg][1] - nm1);
            m[rg][0] = nm0; m[rg][1] = nm1;
            l[rg][0] *= cr0; l[rg][1] *= cr1;
#pragma unroll
            for (int t = 0; t < 8; ++t) {
                o[rg][t][0] *= cr0; o[rg][t][1] *= cr0;
                o[rg][t][2] *= cr1; o[rg][t][3] *= cr1;
            }
        }

        // ---- O += P V (both row-groups share each V fragment)
#pragma unroll
        for (int ks = 0; ks < 4; ++ks) {
            uint32_t aP[2][4];
#pragma unroll
            for (int rg = 0; rg < 2; ++rg) {
#pragma unroll
                for (int half = 0; half < 2; ++half) {
                    int t = 2 * ks + half;
                    float p0 = exp2f(c[rg][t][0] - m[rg][0]);
                    float p1 = exp2f(c[rg][t][1] - m[rg][0]);
                    float p2 = exp2f(c[rg][t][2] - m[rg][1]);
                    float p3 = exp2f(c[rg][t][3] - m[rg][1]);
                    l[rg][0] += p0 + p1;
                    l[rg][1] += p2 + p3;
                    aP[rg][half ? 2 : 0] = hf2pack(p0, p1);
                    aP[rg][half ? 3 : 1] = hf2pack(p2, p3);
                }
            }
            int row = ks * 16 + jj;
            uint32_t rbase = (uint32_t)(row * 128);
            uint32_t msk = (uint32_t)((row & 7) << 4);
#pragma unroll
            for (int dt2 = 0; dt2 < 4; ++dt2) {
                uint32_t off = rbase + (uint32_t)(((dt2 * 16 + dd8) * 2) ^ (int)msk);
                uint32_t v4[4];
                ldsm4t(v4, stb + KV_V + off);
                uint32_t b0[2] = { v4[0], v4[1] };
                uint32_t b1[2] = { v4[2], v4[3] };
#pragma unroll
                for (int rg = 0; rg < 2; ++rg) {
                    mma16816h(o[rg][2 * dt2 + 0], aP[rg], b0);
                    mma16816h(o[rg][2 * dt2 + 1], aP[rg], b1);
                }
            }
        }
        __syncthreads();
    }

    // quad-reduce l (o already holds the full row sum via MMA k-reduction)
#pragma unroll
    for (int rg = 0; rg < 2; ++rg) {
        l[rg][0] += __shfl_xor_sync(0xffffffffu, l[rg][0], 1);
        l[rg][0] += __shfl_xor_sync(0xffffffffu, l[rg][0], 2);
        l[rg][1] += __shfl_xor_sync(0xffffffffu, l[rg][1], 1);
        l[rg][1] += __shfl_xor_sync(0xffffffffu, l[rg][1], 2);
    }

    // ---- epilogue: write fp16 O at [b, n, h*64+d]
    const int b = bh >> 3, h = bh & 7;
    const int colb = h * 64 + 2 * (lane & 3);
#pragma unroll
    for (int rg = 0; rg < 2; ++rg) {
        const int gr = wid * 32 + rg * 16 + (lane >> 2);
        const int n0 = qtile * 128 + gr;
        const float inv0 = 1.f / l[rg][0], inv1 = 1.f / l[rg][1];
#pragma unroll
        for (int t = 0; t < 8; ++t) {
            const int d = t * 8;
            {
                size_t idx = (((size_t)(b * NN + n0) * INNERR) + colb + d) >> 1;
                ((uint32_t*)g_of)[idx] = hf2pack(o[rg][t][0] * inv0, o[rg][t][1] * inv0);
            }
            {
                size_t idx = (((size_t)(b * NN + n0 + 8) * INNERR) + colb + d) >> 1;
                ((uint32_t*)g_of)[idx] = hf2pack(o[rg][t][2] * inv1, o[rg][t][3] * inv1);
            }
        }
    }
}

// ---------------------------------------------------------------------------
extern "C" void kernel_launch(void* const* d_in, const int* in_sizes, int n_in,
                              void* d_out, int out_size)
{
    const float* x  = (const float*)d_in[0];
    const float* m  = (const float*)d_in[1];
    const float* Wq = (const float*)d_in[2];
    const float* Wk = (const float*)d_in[3];
    const float* Wv = (const float*)d_in[4];
    const float* Wo = (const float*)d_in[5];
    const float* bo = (const float*)d_in[6];
    float* out = (float*)d_out;

    cudaFuncSetAttribute(attn_mma, cudaFuncAttributeMaxDynamicSharedMemorySize, AT_SMEM);
    cudaFuncSetAttribute(gemm_qkv, cudaFuncAttributeMaxDynamicSharedMemorySize, GF_SMEM);
    cudaFuncSetAttribute(gemm_out, cudaFuncAttributeMaxDynamicSharedMemorySize, GO_SMEM);

    cvtA<<<dim3(8192, 2), 256>>>(x, m);                       // 0
    cvtW<<<dim3(16, 16, 4), dim3(32, 32)>>>(Wq, Wk, Wv, Wo);  // 1
    gemm_qkv<<<dim3(12, 128), 256, GF_SMEM>>>();              // 2
    attn_mma<<<dim3(16, BB * HH), 128, AT_SMEM>>>();          // 3 <- profiled
    gemm_out<<<dim3(4, 128), 256, GO_SMEM>>>(bo, out);        // 4
}